// round 6
// baseline (speedup 1.0000x reference)
#include <cuda_runtime.h>
#include <cuda_bf16.h>
#include <cuda_fp16.h>

#define NN 50000
#define EE 800000
#define HC 256

// ---------------- scratch (device globals; no allocation allowed) ----------------
__device__ __align__(16) __half g_xsh[NN * HC];  // xs of current layer, fp16
__device__ float g_hpre[NN * HC];   // aggregated pre-BN output (fp32)
__device__ float g_as[NN * 4];
__device__ float g_ad[NN * 4];
__device__ float g_ae1c[EE * 4];    // a_e layer1, CSR order
__device__ float g_ae2c[EE * 4];    // a_e layer2, CSR order
__device__ int   g_deg[NN];
__device__ int   g_offs[NN + 1];
__device__ int   g_cursor[NN];
__device__ int   g_bsum[256];
__device__ int   g_bbase[257];
__device__ int   g_csrc[EE];
__device__ float g_ve1[64];         // [16,4]
__device__ float g_ve2[64];
__device__ float g_stats[1024];     // layer1: [0,512), layer2: [512,1024)
__device__ float g_bnsc[256];       // layer1 BN scale (fused into GEMM2 A-load)
__device__ float g_bnsh[256];       // layer1 BN shift
// W pre-transposed [n][k], bf16 hi/lo planes, per layer
__device__ __align__(16) unsigned short g_WtH[2][256 * 256];
__device__ __align__(16) unsigned short g_WtL[2][256 * 256];

__device__ __forceinline__ float lrelu(float x) { return fmaxf(x, 0.2f * x); }

__device__ __forceinline__ void split_pk(float x0, float x1, unsigned& h, unsigned& l) {
    __nv_bfloat16 h0 = __float2bfloat16_rn(x0), h1 = __float2bfloat16_rn(x1);
    float r0 = x0 - __bfloat162float(h0), r1 = x1 - __bfloat162float(h1);
    __nv_bfloat16 l0 = __float2bfloat16_rn(r0), l1 = __float2bfloat16_rn(r1);
    h = (unsigned)__bfloat16_as_ushort(h0) | ((unsigned)__bfloat16_as_ushort(h1) << 16);
    l = (unsigned)__bfloat16_as_ushort(l0) | ((unsigned)__bfloat16_as_ushort(l1) << 16);
}

#define MMA_BF16(C, A0, A1, A2, A3, B0, B1)                                      \
    asm volatile("mma.sync.aligned.m16n8k16.row.col.f32.bf16.bf16.f32 "          \
                 "{%0,%1,%2,%3}, {%4,%5,%6,%7}, {%8,%9}, {%0,%1,%2,%3};\n"       \
                 : "+f"((C)[0]), "+f"((C)[1]), "+f"((C)[2]), "+f"((C)[3])        \
                 : "r"(A0), "r"(A1), "r"(A2), "r"(A3), "r"(B0), "r"(B1))

// ---------------- setup kernels ----------------
__global__ void k_zero() {
    int i = blockIdx.x * blockDim.x + threadIdx.x;
    if (i < NN) g_deg[i] = 0;
    if (i < 1024) g_stats[i] = 0.f;
}

// Ve[j][h] = sum_c We[j, h*64+c] * atte[h, c]
__global__ void k_ve(const float* __restrict__ We1, const float* __restrict__ at1,
                     const float* __restrict__ We2, const float* __restrict__ at2) {
    int t = threadIdx.x;            // 128 threads
    int which = t >> 6;
    int u = t & 63;
    int j = u >> 2, h = u & 3;
    const float* We = which ? We2 : We1;
    const float* at = which ? at2 : at1;
    float s = 0.f;
    #pragma unroll 8
    for (int c = 0; c < 64; c++) s += We[j * HC + h * 64 + c] * at[h * 64 + c];
    if (which) g_ve2[u] = s; else g_ve1[u] = s;
}

// W[K,256] fp32 -> Wt[n][k] bf16 hi/lo planes
__global__ void k_prepW(const float* __restrict__ W, int K, int layer) {
    int n = blockIdx.x;
    int k = threadIdx.x;
    if (k >= K) return;
    float x = W[(size_t)k * 256 + n];
    __nv_bfloat16 h = __float2bfloat16_rn(x);
    float lo = x - __bfloat162float(h);
    __nv_bfloat16 l = __float2bfloat16_rn(lo);
    g_WtH[layer][n * K + k] = __bfloat16_as_ushort(h);
    g_WtL[layer][n * K + k] = __bfloat16_as_ushort(l);
}

// degree histogram only (dst reads, 3.2 MB)
__global__ void k_deg(const int* __restrict__ dst) {
    int e = blockIdx.x * blockDim.x + threadIdx.x;
    if (e < EE) atomicAdd(&g_deg[dst[e]], 1);
}

// ------------- 3-kernel exclusive scan of deg -> offs, cursor -------------
__global__ void k_scan1() {
    __shared__ int sh[256];
    int b = blockIdx.x, t = threadIdx.x;
    int i = b * 256 + t;
    sh[t] = (i < NN) ? g_deg[i] : 0;
    __syncthreads();
    for (int o = 128; o; o >>= 1) { if (t < o) sh[t] += sh[t + o]; __syncthreads(); }
    if (t == 0) g_bsum[b] = sh[0];
}

__global__ void k_scan2(int nb) {
    __shared__ int sh[256];
    int t = threadIdx.x;
    sh[t] = (t < nb) ? g_bsum[t] : 0;
    __syncthreads();
    for (int o = 1; o < 256; o <<= 1) {
        int v = (t >= o) ? sh[t - o] : 0;
        __syncthreads();
        sh[t] += v;
        __syncthreads();
    }
    g_bbase[t + 1] = sh[t];
    if (t == 0) { g_bbase[0] = 0; g_offs[NN] = EE; }
}

__global__ void k_scan3() {
    __shared__ int sh[256];
    int b = blockIdx.x, t = threadIdx.x;
    int i = b * 256 + t;
    int d = (i < NN) ? g_deg[i] : 0;
    sh[t] = d;
    __syncthreads();
    for (int o = 1; o < 256; o <<= 1) {
        int v = (t >= o) ? sh[t - o] : 0;
        __syncthreads();
        sh[t] += v;
        __syncthreads();
    }
    if (i < NN) {
        int off = g_bbase[b] + sh[t] - d;
        g_offs[i] = off;
        g_cursor[i] = off;
    }
}

// per-edge a_e for both layers, scattered DIRECTLY to CSR position
__global__ void k_edge(const float* __restrict__ eattr, const int* __restrict__ src,
                       const int* __restrict__ dst) {
    int e = blockIdx.x * blockDim.x + threadIdx.x;
    if (e >= EE) return;
    const float4* p = (const float4*)(eattr + (size_t)e * 16);
    float4 a = p[0], b = p[1], c = p[2], d = p[3];
    float v[16] = {a.x,a.y,a.z,a.w, b.x,b.y,b.z,b.w, c.x,c.y,c.z,c.w, d.x,d.y,d.z,d.w};
    float o1[4] = {0,0,0,0}, o2[4] = {0,0,0,0};
    #pragma unroll
    for (int j = 0; j < 16; j++) {
        #pragma unroll
        for (int h = 0; h < 4; h++) {
            o1[h] += v[j] * g_ve1[j * 4 + h];
            o2[h] += v[j] * g_ve2[j * 4 + h];
        }
    }
    int pos = atomicAdd(&g_cursor[dst[e]], 1);
    g_csrc[pos] = src[e];
    *(float4*)(g_ae1c + (size_t)pos * 4) = make_float4(o1[0], o1[1], o1[2], o1[3]);
    *(float4*)(g_ae2c + (size_t)pos * 4) = make_float4(o2[0], o2[1], o2[2], o2[3]);
}

// ---------------- tensor-core GEMM: C[M,256] = A[M,K] @ W, bf16 3-term split ----
// BM=128 BN=128 BK=16, 8 warps (2m x 4n), warp tile 64x32, mma m16n8k16.
// Fused: optional BN-ReLU on A-load (layer2), attdot epilogue, fp16 C store.
__global__ void __launch_bounds__(256, 2)
k_gemm(const float* __restrict__ Aext, int M, int K, int layer, int bnflag,
       const float* __restrict__ atts, const float* __restrict__ attd) {
    const float* A = Aext ? Aext : g_hpre;
    __shared__ unsigned sAh[128 * 12], sAl[128 * 12];
    __shared__ unsigned sBh[128 * 12], sBl[128 * 12];
    __shared__ float2 sred[4][128];
    int tid = threadIdx.x;
    int lane = tid & 31, wid = tid >> 5;
    int wm = (wid >> 2) * 64, wn = (wid & 3) * 32;
    int rowBlk = blockIdx.y * 128, colBlk = blockIdx.x * 128;

    int ar = tid >> 1;
    int ak = (tid & 1) * 8;
    bool aval = (rowBlk + ar) < M;
    const float* Ap = A + (size_t)(rowBlk + ar) * K + ak;
    int bn_ = tid & 127;
    int bsel = tid >> 7;
    const unsigned short* Bp =
        (bsel ? g_WtL[layer] : g_WtH[layer]) + (size_t)(colBlk + bn_) * K;

    float c[4][4][4];
    #pragma unroll
    for (int mt = 0; mt < 4; mt++)
        #pragma unroll
        for (int nt = 0; nt < 4; nt++)
            #pragma unroll
            for (int q = 0; q < 4; q++) c[mt][nt][q] = 0.f;

    int nch = K >> 4;
    float av[8];
    uint4 bq0, bq1;
    {
        float4 u = aval ? *(const float4*)(Ap) : make_float4(0, 0, 0, 0);
        float4 v = aval ? *(const float4*)(Ap + 4) : make_float4(0, 0, 0, 0);
        av[0]=u.x; av[1]=u.y; av[2]=u.z; av[3]=u.w;
        av[4]=v.x; av[5]=v.y; av[6]=v.z; av[7]=v.w;
        bq0 = ((const uint4*)(Bp))[0];
        bq1 = ((const uint4*)(Bp))[1];
    }

    for (int ch = 0; ch < nch; ch++) {
        if (bnflag && aval) {
            int kk = ch * 16 + ak;
            #pragma unroll
            for (int j = 0; j < 8; j++)
                av[j] = fmaxf(fmaf(g_bnsc[kk + j], av[j], g_bnsh[kk + j]), 0.f);
        }
        {
            unsigned h0, h1, h2, h3, l0, l1, l2, l3;
            split_pk(av[0], av[1], h0, l0);
            split_pk(av[2], av[3], h1, l1);
            split_pk(av[4], av[5], h2, l2);
            split_pk(av[6], av[7], h3, l3);
            int base = ar * 12 + (ak >> 1);
            *(uint4*)(sAh + base) = make_uint4(h0, h1, h2, h3);
            *(uint4*)(sAl + base) = make_uint4(l0, l1, l2, l3);
            unsigned* sB = bsel ? sBl : sBh;
            int bb = bn_ * 12;
            *(uint4*)(sB + bb) = bq0;
            *(uint4*)(sB + bb + 4) = bq1;
        }
        __syncthreads();
        if (ch + 1 < nch) {
            const float* Ap2 = Ap + (ch + 1) * 16;
            float4 u = aval ? *(const float4*)(Ap2) : make_float4(0, 0, 0, 0);
            float4 v = aval ? *(const float4*)(Ap2 + 4) : make_float4(0, 0, 0, 0);
            av[0]=u.x; av[1]=u.y; av[2]=u.z; av[3]=u.w;
            av[4]=v.x; av[5]=v.y; av[6]=v.z; av[7]=v.w;
            const uint4* Bc = (const uint4*)(Bp + (ch + 1) * 16);
            bq0 = Bc[0];
            bq1 = Bc[1];
        }
        unsigned bh0[4], bh1[4], bl0[4], bl1[4];
        #pragma unroll
        for (int nt = 0; nt < 4; nt++) {
            int nb = (wn + nt * 8 + (lane >> 2)) * 12 + (lane & 3);
            bh0[nt] = sBh[nb]; bh1[nt] = sBh[nb + 4];
            bl0[nt] = sBl[nb]; bl1[nt] = sBl[nb + 4];
        }
        #pragma unroll
        for (int mt = 0; mt < 4; mt++) {
            int ab = (wm + mt * 16 + (lane >> 2)) * 12 + (lane & 3);
            unsigned ah0 = sAh[ab], ah1 = sAh[ab + 96];
            unsigned ah2 = sAh[ab + 4], ah3 = sAh[ab + 100];
            unsigned al0 = sAl[ab], al1 = sAl[ab + 96];
            unsigned al2 = sAl[ab + 4], al3 = sAl[ab + 100];
            #pragma unroll
            for (int nt = 0; nt < 4; nt++) {
                MMA_BF16(c[mt][nt], ah0, ah1, ah2, ah3, bh0[nt], bh1[nt]);
                MMA_BF16(c[mt][nt], ah0, ah1, ah2, ah3, bl0[nt], bl1[nt]);
                MMA_BF16(c[mt][nt], al0, al1, al2, al3, bh0[nt], bh1[nt]);
            }
        }
        __syncthreads();
    }

    // epilogue: write C as fp16 (only consumer is the agg gather)
    #pragma unroll
    for (int mt = 0; mt < 4; mt++) {
        int r0 = rowBlk + wm + mt * 16 + (lane >> 2);
        #pragma unroll
        for (int nt = 0; nt < 4; nt++) {
            int col = colBlk + wn + nt * 8 + (lane & 3) * 2;
            if (r0 < M)
                *(__half2*)(g_xsh + (size_t)r0 * 256 + col) =
                    __floats2half2_rn(c[mt][nt][0], c[mt][nt][1]);
            if (r0 + 8 < M)
                *(__half2*)(g_xsh + (size_t)(r0 + 8) * 256 + col) =
                    __floats2half2_rn(c[mt][nt][2], c[mt][nt][3]);
        }
    }
    // fused attdot: partial dots per n-warp -> smem -> reduce -> g_as/g_ad (fp32 frags)
    float sv[4][2], dv[4][2];
    #pragma unroll
    for (int nt = 0; nt < 4; nt++)
        #pragma unroll
        for (int q = 0; q < 2; q++) {
            int col = colBlk + wn + nt * 8 + (lane & 3) * 2 + q;
            sv[nt][q] = atts[col];
            dv[nt][q] = attd[col];
        }
    #pragma unroll
    for (int mt = 0; mt < 4; mt++) {
        #pragma unroll
        for (int half = 0; half < 2; half++) {
            float ss = 0.f, dd = 0.f;
            #pragma unroll
            for (int nt = 0; nt < 4; nt++) {
                #pragma unroll
                for (int q = 0; q < 2; q++) {
                    ss = fmaf(c[mt][nt][half * 2 + q], sv[nt][q], ss);
                    dd = fmaf(c[mt][nt][half * 2 + q], dv[nt][q], dd);
                }
            }
            ss += __shfl_xor_sync(0xffffffffu, ss, 1);
            ss += __shfl_xor_sync(0xffffffffu, ss, 2);
            dd += __shfl_xor_sync(0xffffffffu, dd, 1);
            dd += __shfl_xor_sync(0xffffffffu, dd, 2);
            if ((lane & 3) == 0)
                sred[wid & 3][wm + mt * 16 + half * 8 + (lane >> 2)] =
                    make_float2(ss, dd);
        }
    }
    __syncthreads();
    {
        int row = tid >> 1, hl = tid & 1;
        int r = rowBlk + row;
        if (r < M) {
            float2 aa = sred[2 * hl][row], bb = sred[2 * hl + 1][row];
            int hidx = (colBlk >> 6) + hl;
            g_as[r * 4 + hidx] = aa.x + bb.x;
            g_ad[r * 4 + hidx] = aa.y + bb.y;
        }
    }
}

// ---------------- GAT aggregation: single pass, warp per dst node.
// fp16 row gather, fp32 accum. Fused BN stats: block-reduce sum/sumsq -> REDG.
// Grid is exactly NN/8 blocks x 8 warps: no partial blocks, all threads live. ----
__global__ void __launch_bounds__(256) k_agg(int layer, const float* __restrict__ bias,
                                             int statsOff) {
    __shared__ float4 sp[8][32];
    __shared__ int    si[8][32];
    __shared__ float  s_sum[256], s_sq[256];
    int tid = threadIdx.x;
    s_sum[tid] = 0.f;
    s_sq[tid] = 0.f;
    int w = (blockIdx.x * blockDim.x + tid) >> 5;
    int lane = tid & 31;
    int wrp = tid >> 5;
    const float4* aeC = (const float4*)(layer ? g_ae2c : g_ae1c);
    int beg = g_offs[w], end = g_offs[w + 1];
    float4 adv = *(const float4*)(g_ad + (size_t)w * 4);
    int h = lane >> 3;
    int f0 = lane * 8;
    float acc[8] = {0, 0, 0, 0, 0, 0, 0, 0};
    float den0 = 0, den1 = 0, den2 = 0, den3 = 0;
    float sa0 = 0, sa1 = 0, sa2 = 0, sa3 = 0;

    for (int base = beg; base < end; base += 32) {
        int i = base + lane;
        float p0 = 0, p1 = 0, p2 = 0, p3 = 0;
        int s = 0;
        if (i < end) {
            s = g_csrc[i];
            float4 ae = aeC[i];
            float4 as = *(const float4*)(g_as + (size_t)s * 4);
            sa0 += ae.x; sa1 += ae.y; sa2 += ae.z; sa3 += ae.w;
            p0 = __expf(lrelu(as.x + adv.x + ae.x));
            p1 = __expf(lrelu(as.y + adv.y + ae.y));
            p2 = __expf(lrelu(as.z + adv.z + ae.z));
            p3 = __expf(lrelu(as.w + adv.w + ae.w));
            den0 += p0; den1 += p1; den2 += p2; den3 += p3;
        }
        sp[wrp][lane] = make_float4(p0, p1, p2, p3);
        si[wrp][lane] = s;
        __syncwarp();
        int cnt = min(32, end - base);
        #pragma unroll 4
        for (int jj = 0; jj < cnt; jj++) {
            int ss = si[wrp][jj];
            float q = ((const float*)&sp[wrp][jj])[h];
            uint4 xv = *(const uint4*)(g_xsh + (size_t)ss * HC + f0);
            float2 x0 = __half22float2(*(__half2*)&xv.x);
            float2 x1 = __half22float2(*(__half2*)&xv.y);
            float2 x2 = __half22float2(*(__half2*)&xv.z);
            float2 x3 = __half22float2(*(__half2*)&xv.w);
            acc[0] = fmaf(q, x0.x, acc[0]); acc[1] = fmaf(q, x0.y, acc[1]);
            acc[2] = fmaf(q, x1.x, acc[2]); acc[3] = fmaf(q, x1.y, acc[3]);
            acc[4] = fmaf(q, x2.x, acc[4]); acc[5] = fmaf(q, x2.y, acc[5]);
            acc[6] = fmaf(q, x3.x, acc[6]); acc[7] = fmaf(q, x3.y, acc[7]);
        }
        __syncwarp();
    }
    #pragma unroll
    for (int o = 16; o; o >>= 1) {
        den0 += __shfl_xor_sync(0xffffffffu, den0, o);
        den1 += __shfl_xor_sync(0xffffffffu, den1, o);
        den2 += __shfl_xor_sync(0xffffffffu, den2, o);
        den3 += __shfl_xor_sync(0xffffffffu, den3, o);
        sa0 += __shfl_xor_sync(0xffffffffu, sa0, o);
        sa1 += __shfl_xor_sync(0xffffffffu, sa1, o);
        sa2 += __shfl_xor_sync(0xffffffffu, sa2, o);
        sa3 += __shfl_xor_sync(0xffffffffu, sa3, o);
    }
    int deg = end - beg;
    float invd = 1.0f / fmaxf((float)deg, 1.0f);
    float4 asn = *(const float4*)(g_as + (size_t)w * 4);
    float ps0 = __expf(lrelu(asn.x + adv.x + sa0 * invd));
    float ps1 = __expf(lrelu(asn.y + adv.y + sa1 * invd));
    float ps2 = __expf(lrelu(asn.z + adv.z + sa2 * invd));
    float ps3 = __expf(lrelu(asn.w + adv.w + sa3 * invd));
    den0 += ps0 + 1e-16f; den1 += ps1 + 1e-16f;
    den2 += ps2 + 1e-16f; den3 += ps3 + 1e-16f;
    {
        uint4 xv = *(const uint4*)(g_xsh + (size_t)w * HC + f0);
        float2 x0 = __half22float2(*(__half2*)&xv.x);
        float2 x1 = __half22float2(*(__half2*)&xv.y);
        float2 x2 = __half22float2(*(__half2*)&xv.z);
        float2 x3 = __half22float2(*(__half2*)&xv.w);
        float psh = (h == 0) ? ps0 : (h == 1) ? ps1 : (h == 2) ? ps2 : ps3;
        acc[0] = fmaf(psh, x0.x, acc[0]); acc[1] = fmaf(psh, x0.y, acc[1]);
        acc[2] = fmaf(psh, x1.x, acc[2]); acc[3] = fmaf(psh, x1.y, acc[3]);
        acc[4] = fmaf(psh, x2.x, acc[4]); acc[5] = fmaf(psh, x2.y, acc[5]);
        acc[6] = fmaf(psh, x3.x, acc[6]); acc[7] = fmaf(psh, x3.y, acc[7]);
    }
    float denh = (h == 0) ? den0 : (h == 1) ? den1 : (h == 2) ? den2 : den3;
    float r = 1.0f / denh;
    float4 b0 = *(const float4*)(bias + f0);
    float4 b1 = *(const float4*)(bias + f0 + 4);
    float v[8];
    v[0] = fmaf(acc[0], r, b0.x); v[1] = fmaf(acc[1], r, b0.y);
    v[2] = fmaf(acc[2], r, b0.z); v[3] = fmaf(acc[3], r, b0.w);
    v[4] = fmaf(acc[4], r, b1.x); v[5] = fmaf(acc[5], r, b1.y);
    v[6] = fmaf(acc[6], r, b1.z); v[7] = fmaf(acc[7], r, b1.w);
    float* op = g_hpre + (size_t)w * HC + f0;
    *(float4*)(op)     = make_float4(v[0], v[1], v[2], v[3]);
    *(float4*)(op + 4) = make_float4(v[4], v[5], v[6], v[7]);
    // fused BN stats: block-local reduce, then one REDG pair per feature
    __syncthreads();
    #pragma unroll
    for (int j = 0; j < 8; j++) {
        atomicAdd(&s_sum[f0 + j], v[j]);
        atomicAdd(&s_sq[f0 + j], v[j] * v[j]);
    }
    __syncthreads();
    atomicAdd(&g_stats[statsOff + tid], s_sum[tid]);
    atomicAdd(&g_stats[statsOff + 256 + tid], s_sq[tid]);
}

// layer1 BN -> per-column scale/shift (consumed by GEMM2 A-load)
__global__ void k_bnprep(const float* __restrict__ g, const float* __restrict__ be) {
    int c = threadIdx.x;
    const float invN = 1.0f / NN;
    float mu = g_stats[c] * invN;
    float var = g_stats[256 + c] * invN - mu * mu;
    float sc = g[c] * rsqrtf(var + 1e-5f);
    g_bnsc[c] = sc;
    g_bnsh[c] = be[c] - sc * mu;
}

// ---------------- final: out[n] = relu(BN(hpre2)) . wout + bout ----------------
__global__ void k_final(const float* __restrict__ g, const float* __restrict__ be,
                        const float* __restrict__ wout, const float* __restrict__ bout,
                        float* __restrict__ out) {
    int w = (blockIdx.x * blockDim.x + threadIdx.x) >> 5;
    if (w >= NN) return;
    int lane = threadIdx.x & 31;
    const float invN = 1.0f / NN;
    float s = 0.f;
    #pragma unroll
    for (int j = 0; j < 8; j++) {
        int f = lane + 32 * j;
        float mu = g_stats[512 + f] * invN;
        float var = g_stats[768 + f] * invN - mu * mu;
        float sc = g[f] * rsqrtf(var + 1e-5f);
        float v = fmaxf(sc * (g_hpre[(size_t)w * HC + f] - mu) + be[f], 0.f);
        s = fmaf(v, wout[f], s);
    }
    #pragma unroll
    for (int o = 16; o; o >>= 1) s += __shfl_xor_sync(0xffffffffu, s, o);
    if (lane == 0) out[w] = s + bout[0];
}

// ---------------- launch ----------------
extern "C" void kernel_launch(void* const* d_in, const int* in_sizes, int n_in,
                              void* d_out, int out_size) {
    const float* x     = (const float*)d_in[0];
    const int*   esrc  = (const int*)d_in[1];
    const int*   edst  = (const int*)d_in[2];
    const float* eattr = (const float*)d_in[3];
    const float* W1    = (const float*)d_in[4];
    const float* atts1 = (const float*)d_in[5];
    const float* attd1 = (const float*)d_in[6];
    const float* We1   = (const float*)d_in[7];
    const float* atte1 = (const float*)d_in[8];
    const float* b1    = (const float*)d_in[9];
    const float* g1    = (const float*)d_in[10];
    const float* be1   = (const float*)d_in[11];
    const float* W2    = (const float*)d_in[12];
    const float* atts2 = (const float*)d_in[13];
    const float* attd2 = (const float*)d_in[14];
    const float* We2   = (const float*)d_in[15];
    const float* atte2 = (const float*)d_in[16];
    const float* b2    = (const float*)d_in[17];
    const float* g2    = (const float*)d_in[18];
    const float* be2   = (const float*)d_in[19];
    const float* Wout  = (const float*)d_in[20];
    const float* bout  = (const float*)d_in[21];
    float* out = (float*)d_out;

    const int EB = (EE + 255) / 256;
    const int NB = (NN + 255) / 256;
    const int WB = NN / 8;                 // warp-per-node kernels (256 thr)
    dim3 gg(2, (NN + 127) / 128);

    // setup
    k_zero<<<NB, 256>>>();
    k_ve<<<1, 128>>>(We1, atte1, We2, atte2);
    k_prepW<<<256, 64>>>(W1, 64, 0);
    k_prepW<<<256, 256>>>(W2, 256, 1);
    k_deg<<<EB, 256>>>(edst);
    k_scan1<<<NB, 256>>>();
    k_scan2<<<1, 256>>>(NB);
    k_scan3<<<NB, 256>>>();
    k_edge<<<EB, 256>>>(eattr, esrc, edst);   // direct CSR scatter

    // layer 1 (attdot fused into GEMM epilogue; BN stats fused into agg)
    k_gemm<<<gg, 256>>>(x, NN, 64, 0, 0, atts1, attd1);
    k_agg<<<WB, 256>>>(0, b1, 0);
    k_bnprep<<<1, 256>>>(g1, be1);

    // layer 2 (BN-ReLU of layer1 fused into GEMM A-load)
    k_gemm<<<gg, 256>>>(nullptr, NN, 256, 1, 1, atts2, attd2);
    k_agg<<<WB, 256>>>(1, b2, 512);

    // output head
    k_final<<<WB, 256>>>(g2, be2, Wout, bout, out);
}

// round 7
// speedup vs baseline: 1.3124x; 1.3124x over previous
#include <cuda_runtime.h>
#include <cuda_bf16.h>
#include <cuda_fp16.h>

#define NN 50000
#define EE 800000
#define HC 256

// ---------------- scratch (device globals; no allocation allowed) ----------------
__device__ __align__(16) __half g_xsh[NN * HC];  // xs of current layer, fp16
__device__ float g_hpre[NN * HC];   // aggregated pre-BN output (fp32)
__device__ float g_as[NN * 4];
__device__ float g_ad[NN * 4];
__device__ float g_ae1c[EE * 4];    // a_e layer1, CSR order
__device__ float g_ae2c[EE * 4];    // a_e layer2, CSR order
__device__ int   g_deg[NN];
__device__ int   g_offs[NN + 1];
__device__ int   g_cursor[NN];
__device__ int   g_bsum[256];
__device__ int   g_bbase[257];
__device__ int   g_csrc[EE];
__device__ float g_ve1[64];         // [16,4]
__device__ float g_ve2[64];
__device__ float g_stats[1024];     // layer1: [0,512), layer2: [512,1024)
__device__ float g_bnsc[256];       // layer1 BN scale (fused into GEMM2 A-load)
__device__ float g_bnsh[256];       // layer1 BN shift
// W pre-transposed [n][k], bf16 hi/lo planes, per layer
__device__ __align__(16) unsigned short g_WtH[2][256 * 256];
__device__ __align__(16) unsigned short g_WtL[2][256 * 256];

__device__ __forceinline__ float lrelu(float x) { return fmaxf(x, 0.2f * x); }

__device__ __forceinline__ void split_pk(float x0, float x1, unsigned& h, unsigned& l) {
    __nv_bfloat16 h0 = __float2bfloat16_rn(x0), h1 = __float2bfloat16_rn(x1);
    float r0 = x0 - __bfloat162float(h0), r1 = x1 - __bfloat162float(h1);
    __nv_bfloat16 l0 = __float2bfloat16_rn(r0), l1 = __float2bfloat16_rn(r1);
    h = (unsigned)__bfloat16_as_ushort(h0) | ((unsigned)__bfloat16_as_ushort(h1) << 16);
    l = (unsigned)__bfloat16_as_ushort(l0) | ((unsigned)__bfloat16_as_ushort(l1) << 16);
}

#define MMA_BF16(C, A0, A1, A2, A3, B0, B1)                                      \
    asm volatile("mma.sync.aligned.m16n8k16.row.col.f32.bf16.bf16.f32 "          \
                 "{%0,%1,%2,%3}, {%4,%5,%6,%7}, {%8,%9}, {%0,%1,%2,%3};\n"       \
                 : "+f"((C)[0]), "+f"((C)[1]), "+f"((C)[2]), "+f"((C)[3])        \
                 : "r"(A0), "r"(A1), "r"(A2), "r"(A3), "r"(B0), "r"(B1))

// ---------------- setup kernels ----------------
__global__ void k_zero() {
    int i = blockIdx.x * blockDim.x + threadIdx.x;
    if (i < NN) g_deg[i] = 0;
    if (i < 1024) g_stats[i] = 0.f;
}

// Ve[j][h] = sum_c We[j, h*64+c] * atte[h, c]
__global__ void k_ve(const float* __restrict__ We1, const float* __restrict__ at1,
                     const float* __restrict__ We2, const float* __restrict__ at2) {
    int t = threadIdx.x;            // 128 threads
    int which = t >> 6;
    int u = t & 63;
    int j = u >> 2, h = u & 3;
    const float* We = which ? We2 : We1;
    const float* at = which ? at2 : at1;
    float s = 0.f;
    #pragma unroll 8
    for (int c = 0; c < 64; c++) s += We[j * HC + h * 64 + c] * at[h * 64 + c];
    if (which) g_ve2[u] = s; else g_ve1[u] = s;
}

// W[K,256] fp32 -> Wt[n][k] bf16 hi/lo planes
__global__ void k_prepW(const float* __restrict__ W, int K, int layer) {
    int n = blockIdx.x;
    int k = threadIdx.x;
    if (k >= K) return;
    float x = W[(size_t)k * 256 + n];
    __nv_bfloat16 h = __float2bfloat16_rn(x);
    float lo = x - __bfloat162float(h);
    __nv_bfloat16 l = __float2bfloat16_rn(lo);
    g_WtH[layer][n * K + k] = __bfloat16_as_ushort(h);
    g_WtL[layer][n * K + k] = __bfloat16_as_ushort(l);
}

// degree histogram only (dst reads, 3.2 MB)
__global__ void k_deg(const int* __restrict__ dst) {
    int e = blockIdx.x * blockDim.x + threadIdx.x;
    if (e < EE) atomicAdd(&g_deg[dst[e]], 1);
}

// ------------- 3-kernel exclusive scan of deg -> offs, cursor -------------
__global__ void k_scan1() {
    __shared__ int sh[256];
    int b = blockIdx.x, t = threadIdx.x;
    int i = b * 256 + t;
    sh[t] = (i < NN) ? g_deg[i] : 0;
    __syncthreads();
    for (int o = 128; o; o >>= 1) { if (t < o) sh[t] += sh[t + o]; __syncthreads(); }
    if (t == 0) g_bsum[b] = sh[0];
}

__global__ void k_scan2(int nb) {
    __shared__ int sh[256];
    int t = threadIdx.x;
    sh[t] = (t < nb) ? g_bsum[t] : 0;
    __syncthreads();
    for (int o = 1; o < 256; o <<= 1) {
        int v = (t >= o) ? sh[t - o] : 0;
        __syncthreads();
        sh[t] += v;
        __syncthreads();
    }
    g_bbase[t + 1] = sh[t];
    if (t == 0) { g_bbase[0] = 0; g_offs[NN] = EE; }
}

__global__ void k_scan3() {
    __shared__ int sh[256];
    int b = blockIdx.x, t = threadIdx.x;
    int i = b * 256 + t;
    int d = (i < NN) ? g_deg[i] : 0;
    sh[t] = d;
    __syncthreads();
    for (int o = 1; o < 256; o <<= 1) {
        int v = (t >= o) ? sh[t - o] : 0;
        __syncthreads();
        sh[t] += v;
        __syncthreads();
    }
    if (i < NN) {
        int off = g_bbase[b] + sh[t] - d;
        g_offs[i] = off;
        g_cursor[i] = off;
    }
}

// per-edge a_e for both layers, scattered DIRECTLY to CSR position
__global__ void k_edge(const float* __restrict__ eattr, const int* __restrict__ src,
                       const int* __restrict__ dst) {
    int e = blockIdx.x * blockDim.x + threadIdx.x;
    if (e >= EE) return;
    const float4* p = (const float4*)(eattr + (size_t)e * 16);
    float4 a = p[0], b = p[1], c = p[2], d = p[3];
    float v[16] = {a.x,a.y,a.z,a.w, b.x,b.y,b.z,b.w, c.x,c.y,c.z,c.w, d.x,d.y,d.z,d.w};
    float o1[4] = {0,0,0,0}, o2[4] = {0,0,0,0};
    #pragma unroll
    for (int j = 0; j < 16; j++) {
        #pragma unroll
        for (int h = 0; h < 4; h++) {
            o1[h] += v[j] * g_ve1[j * 4 + h];
            o2[h] += v[j] * g_ve2[j * 4 + h];
        }
    }
    int pos = atomicAdd(&g_cursor[dst[e]], 1);
    g_csrc[pos] = src[e];
    *(float4*)(g_ae1c + (size_t)pos * 4) = make_float4(o1[0], o1[1], o1[2], o1[3]);
    *(float4*)(g_ae2c + (size_t)pos * 4) = make_float4(o2[0], o2[1], o2[2], o2[3]);
}

// ---------------- tensor-core GEMM: C[M,256] = A[M,K] @ W, bf16 3-term split ----
// BM=128 BN=128 BK=16, 8 warps (2m x 4n), warp tile 64x32, mma m16n8k16.
// Fused: optional BN-ReLU on A-load (layer2), attdot epilogue, fp16 C store.
__global__ void __launch_bounds__(256, 2)
k_gemm(const float* __restrict__ Aext, int M, int K, int layer, int bnflag,
       const float* __restrict__ atts, const float* __restrict__ attd) {
    const float* A = Aext ? Aext : g_hpre;
    __shared__ unsigned sAh[128 * 12], sAl[128 * 12];
    __shared__ unsigned sBh[128 * 12], sBl[128 * 12];
    __shared__ float2 sred[4][128];
    int tid = threadIdx.x;
    int lane = tid & 31, wid = tid >> 5;
    int wm = (wid >> 2) * 64, wn = (wid & 3) * 32;
    int rowBlk = blockIdx.y * 128, colBlk = blockIdx.x * 128;

    int ar = tid >> 1;
    int ak = (tid & 1) * 8;
    bool aval = (rowBlk + ar) < M;
    const float* Ap = A + (size_t)(rowBlk + ar) * K + ak;
    int bn_ = tid & 127;
    int bsel = tid >> 7;
    const unsigned short* Bp =
        (bsel ? g_WtL[layer] : g_WtH[layer]) + (size_t)(colBlk + bn_) * K;

    float c[4][4][4];
    #pragma unroll
    for (int mt = 0; mt < 4; mt++)
        #pragma unroll
        for (int nt = 0; nt < 4; nt++)
            #pragma unroll
            for (int q = 0; q < 4; q++) c[mt][nt][q] = 0.f;

    int nch = K >> 4;
    float av[8];
    uint4 bq0, bq1;
    {
        float4 u = aval ? *(const float4*)(Ap) : make_float4(0, 0, 0, 0);
        float4 v = aval ? *(const float4*)(Ap + 4) : make_float4(0, 0, 0, 0);
        av[0]=u.x; av[1]=u.y; av[2]=u.z; av[3]=u.w;
        av[4]=v.x; av[5]=v.y; av[6]=v.z; av[7]=v.w;
        bq0 = ((const uint4*)(Bp))[0];
        bq1 = ((const uint4*)(Bp))[1];
    }

    for (int ch = 0; ch < nch; ch++) {
        if (bnflag && aval) {
            int kk = ch * 16 + ak;
            #pragma unroll
            for (int j = 0; j < 8; j++)
                av[j] = fmaxf(fmaf(g_bnsc[kk + j], av[j], g_bnsh[kk + j]), 0.f);
        }
        {
            unsigned h0, h1, h2, h3, l0, l1, l2, l3;
            split_pk(av[0], av[1], h0, l0);
            split_pk(av[2], av[3], h1, l1);
            split_pk(av[4], av[5], h2, l2);
            split_pk(av[6], av[7], h3, l3);
            int base = ar * 12 + (ak >> 1);
            *(uint4*)(sAh + base) = make_uint4(h0, h1, h2, h3);
            *(uint4*)(sAl + base) = make_uint4(l0, l1, l2, l3);
            unsigned* sB = bsel ? sBl : sBh;
            int bb = bn_ * 12;
            *(uint4*)(sB + bb) = bq0;
            *(uint4*)(sB + bb + 4) = bq1;
        }
        __syncthreads();
        if (ch + 1 < nch) {
            const float* Ap2 = Ap + (ch + 1) * 16;
            float4 u = aval ? *(const float4*)(Ap2) : make_float4(0, 0, 0, 0);
            float4 v = aval ? *(const float4*)(Ap2 + 4) : make_float4(0, 0, 0, 0);
            av[0]=u.x; av[1]=u.y; av[2]=u.z; av[3]=u.w;
            av[4]=v.x; av[5]=v.y; av[6]=v.z; av[7]=v.w;
            const uint4* Bc = (const uint4*)(Bp + (ch + 1) * 16);
            bq0 = Bc[0];
            bq1 = Bc[1];
        }
        unsigned bh0[4], bh1[4], bl0[4], bl1[4];
        #pragma unroll
        for (int nt = 0; nt < 4; nt++) {
            int nb = (wn + nt * 8 + (lane >> 2)) * 12 + (lane & 3);
            bh0[nt] = sBh[nb]; bh1[nt] = sBh[nb + 4];
            bl0[nt] = sBl[nb]; bl1[nt] = sBl[nb + 4];
        }
        #pragma unroll
        for (int mt = 0; mt < 4; mt++) {
            int ab = (wm + mt * 16 + (lane >> 2)) * 12 + (lane & 3);
            unsigned ah0 = sAh[ab], ah1 = sAh[ab + 96];
            unsigned ah2 = sAh[ab + 4], ah3 = sAh[ab + 100];
            unsigned al0 = sAl[ab], al1 = sAl[ab + 96];
            unsigned al2 = sAl[ab + 4], al3 = sAl[ab + 100];
            #pragma unroll
            for (int nt = 0; nt < 4; nt++) {
                MMA_BF16(c[mt][nt], ah0, ah1, ah2, ah3, bh0[nt], bh1[nt]);
                MMA_BF16(c[mt][nt], ah0, ah1, ah2, ah3, bl0[nt], bl1[nt]);
                MMA_BF16(c[mt][nt], al0, al1, al2, al3, bh0[nt], bh1[nt]);
            }
        }
        __syncthreads();
    }

    // epilogue: write C as fp16 (only consumer is the agg gather)
    #pragma unroll
    for (int mt = 0; mt < 4; mt++) {
        int r0 = rowBlk + wm + mt * 16 + (lane >> 2);
        #pragma unroll
        for (int nt = 0; nt < 4; nt++) {
            int col = colBlk + wn + nt * 8 + (lane & 3) * 2;
            if (r0 < M)
                *(__half2*)(g_xsh + (size_t)r0 * 256 + col) =
                    __floats2half2_rn(c[mt][nt][0], c[mt][nt][1]);
            if (r0 + 8 < M)
                *(__half2*)(g_xsh + (size_t)(r0 + 8) * 256 + col) =
                    __floats2half2_rn(c[mt][nt][2], c[mt][nt][3]);
        }
    }
    // fused attdot: partial dots per n-warp -> smem -> reduce -> g_as/g_ad (fp32 frags)
    float sv[4][2], dv[4][2];
    #pragma unroll
    for (int nt = 0; nt < 4; nt++)
        #pragma unroll
        for (int q = 0; q < 2; q++) {
            int col = colBlk + wn + nt * 8 + (lane & 3) * 2 + q;
            sv[nt][q] = atts[col];
            dv[nt][q] = attd[col];
        }
    #pragma unroll
    for (int mt = 0; mt < 4; mt++) {
        #pragma unroll
        for (int half = 0; half < 2; half++) {
            float ss = 0.f, dd = 0.f;
            #pragma unroll
            for (int nt = 0; nt < 4; nt++) {
                #pragma unroll
                for (int q = 0; q < 2; q++) {
                    ss = fmaf(c[mt][nt][half * 2 + q], sv[nt][q], ss);
                    dd = fmaf(c[mt][nt][half * 2 + q], dv[nt][q], dd);
                }
            }
            ss += __shfl_xor_sync(0xffffffffu, ss, 1);
            ss += __shfl_xor_sync(0xffffffffu, ss, 2);
            dd += __shfl_xor_sync(0xffffffffu, dd, 1);
            dd += __shfl_xor_sync(0xffffffffu, dd, 2);
            if ((lane & 3) == 0)
                sred[wid & 3][wm + mt * 16 + half * 8 + (lane >> 2)] =
                    make_float2(ss, dd);
        }
    }
    __syncthreads();
    {
        int row = tid >> 1, hl = tid & 1;
        int r = rowBlk + row;
        if (r < M) {
            float2 aa = sred[2 * hl][row], bb = sred[2 * hl + 1][row];
            int hidx = (colBlk >> 6) + hl;
            g_as[r * 4 + hidx] = aa.x + bb.x;
            g_ad[r * 4 + hidx] = aa.y + bb.y;
        }
    }
}

// ---------------- GAT aggregation: single pass, warp per dst node.
// fp16 row gather: one LDG.128 per edge per lane; fp32 accumulation. --------
__global__ void __launch_bounds__(256) k_agg(int layer, const float* __restrict__ bias) {
    __shared__ float4 sp[8][32];
    __shared__ int    si[8][32];
    int w = (blockIdx.x * blockDim.x + threadIdx.x) >> 5;
    if (w >= NN) return;
    int lane = threadIdx.x & 31;
    int wrp = threadIdx.x >> 5;
    const float4* aeC = (const float4*)(layer ? g_ae2c : g_ae1c);
    int beg = g_offs[w], end = g_offs[w + 1];
    float4 adv = *(const float4*)(g_ad + (size_t)w * 4);
    int h = lane >> 3;
    int f0 = lane * 8;
    float acc[8] = {0, 0, 0, 0, 0, 0, 0, 0};
    float den0 = 0, den1 = 0, den2 = 0, den3 = 0;
    float sa0 = 0, sa1 = 0, sa2 = 0, sa3 = 0;

    for (int base = beg; base < end; base += 32) {
        int i = base + lane;
        float p0 = 0, p1 = 0, p2 = 0, p3 = 0;
        int s = 0;
        if (i < end) {
            s = g_csrc[i];
            float4 ae = aeC[i];
            float4 as = *(const float4*)(g_as + (size_t)s * 4);
            sa0 += ae.x; sa1 += ae.y; sa2 += ae.z; sa3 += ae.w;
            p0 = __expf(lrelu(as.x + adv.x + ae.x));
            p1 = __expf(lrelu(as.y + adv.y + ae.y));
            p2 = __expf(lrelu(as.z + adv.z + ae.z));
            p3 = __expf(lrelu(as.w + adv.w + ae.w));
            den0 += p0; den1 += p1; den2 += p2; den3 += p3;
        }
        sp[wrp][lane] = make_float4(p0, p1, p2, p3);
        si[wrp][lane] = s;
        __syncwarp();
        int cnt = min(32, end - base);
        #pragma unroll 4
        for (int jj = 0; jj < cnt; jj++) {
            int ss = si[wrp][jj];
            float q = ((const float*)&sp[wrp][jj])[h];
            uint4 xv = *(const uint4*)(g_xsh + (size_t)ss * HC + f0);
            float2 x0 = __half22float2(*(__half2*)&xv.x);
            float2 x1 = __half22float2(*(__half2*)&xv.y);
            float2 x2 = __half22float2(*(__half2*)&xv.z);
            float2 x3 = __half22float2(*(__half2*)&xv.w);
            acc[0] = fmaf(q, x0.x, acc[0]); acc[1] = fmaf(q, x0.y, acc[1]);
            acc[2] = fmaf(q, x1.x, acc[2]); acc[3] = fmaf(q, x1.y, acc[3]);
            acc[4] = fmaf(q, x2.x, acc[4]); acc[5] = fmaf(q, x2.y, acc[5]);
            acc[6] = fmaf(q, x3.x, acc[6]); acc[7] = fmaf(q, x3.y, acc[7]);
        }
        __syncwarp();
    }
    #pragma unroll
    for (int o = 16; o; o >>= 1) {
        den0 += __shfl_xor_sync(0xffffffffu, den0, o);
        den1 += __shfl_xor_sync(0xffffffffu, den1, o);
        den2 += __shfl_xor_sync(0xffffffffu, den2, o);
        den3 += __shfl_xor_sync(0xffffffffu, den3, o);
        sa0 += __shfl_xor_sync(0xffffffffu, sa0, o);
        sa1 += __shfl_xor_sync(0xffffffffu, sa1, o);
        sa2 += __shfl_xor_sync(0xffffffffu, sa2, o);
        sa3 += __shfl_xor_sync(0xffffffffu, sa3, o);
    }
    int deg = end - beg;
    float invd = 1.0f / fmaxf((float)deg, 1.0f);
    float4 asn = *(const float4*)(g_as + (size_t)w * 4);
    float ps0 = __expf(lrelu(asn.x + adv.x + sa0 * invd));
    float ps1 = __expf(lrelu(asn.y + adv.y + sa1 * invd));
    float ps2 = __expf(lrelu(asn.z + adv.z + sa2 * invd));
    float ps3 = __expf(lrelu(asn.w + adv.w + sa3 * invd));
    den0 += ps0 + 1e-16f; den1 += ps1 + 1e-16f;
    den2 += ps2 + 1e-16f; den3 += ps3 + 1e-16f;
    {
        uint4 xv = *(const uint4*)(g_xsh + (size_t)w * HC + f0);
        float2 x0 = __half22float2(*(__half2*)&xv.x);
        float2 x1 = __half22float2(*(__half2*)&xv.y);
        float2 x2 = __half22float2(*(__half2*)&xv.z);
        float2 x3 = __half22float2(*(__half2*)&xv.w);
        float psh = (h == 0) ? ps0 : (h == 1) ? ps1 : (h == 2) ? ps2 : ps3;
        acc[0] = fmaf(psh, x0.x, acc[0]); acc[1] = fmaf(psh, x0.y, acc[1]);
        acc[2] = fmaf(psh, x1.x, acc[2]); acc[3] = fmaf(psh, x1.y, acc[3]);
        acc[4] = fmaf(psh, x2.x, acc[4]); acc[5] = fmaf(psh, x2.y, acc[5]);
        acc[6] = fmaf(psh, x3.x, acc[6]); acc[7] = fmaf(psh, x3.y, acc[7]);
    }
    float denh = (h == 0) ? den0 : (h == 1) ? den1 : (h == 2) ? den2 : den3;
    float r = 1.0f / denh;
    float4 b0 = *(const float4*)(bias + f0);
    float4 b1 = *(const float4*)(bias + f0 + 4);
    float* op = g_hpre + (size_t)w * HC + f0;
    *(float4*)(op)     = make_float4(fmaf(acc[0], r, b0.x), fmaf(acc[1], r, b0.y),
                                     fmaf(acc[2], r, b0.z), fmaf(acc[3], r, b0.w));
    *(float4*)(op + 4) = make_float4(fmaf(acc[4], r, b1.x), fmaf(acc[5], r, b1.y),
                                     fmaf(acc[6], r, b1.z), fmaf(acc[7], r, b1.w));
}

// ---------------- BN batch stats (sum, sumsq per column) ----------------
__global__ void k_stats(int off) {
    int c = threadIdx.x;    // 256
    int rows = (NN + gridDim.x - 1) / gridDim.x;
    int r0 = blockIdx.x * rows, r1 = min(r0 + rows, NN);
    float s = 0.f, s2 = 0.f;
    for (int r = r0; r < r1; r++) {
        float v = g_hpre[(size_t)r * HC + c];
        s += v;
        s2 = fmaf(v, v, s2);
    }
    atomicAdd(&g_stats[off + c], s);
    atomicAdd(&g_stats[off + 256 + c], s2);
}

// layer1 BN -> per-column scale/shift (consumed by GEMM2 A-load)
__global__ void k_bnprep(const float* __restrict__ g, const float* __restrict__ be) {
    int c = threadIdx.x;
    const float invN = 1.0f / NN;
    float mu = g_stats[c] * invN;
    float var = g_stats[256 + c] * invN - mu * mu;
    float sc = g[c] * rsqrtf(var + 1e-5f);
    g_bnsc[c] = sc;
    g_bnsh[c] = be[c] - sc * mu;
}

// ---------------- final: out[n] = relu(BN(hpre2)) . wout + bout ----------------
__global__ void k_final(const float* __restrict__ g, const float* __restrict__ be,
                        const float* __restrict__ wout, const float* __restrict__ bout,
                        float* __restrict__ out) {
    int w = (blockIdx.x * blockDim.x + threadIdx.x) >> 5;
    if (w >= NN) return;
    int lane = threadIdx.x & 31;
    const float invN = 1.0f / NN;
    float s = 0.f;
    #pragma unroll
    for (int j = 0; j < 8; j++) {
        int f = lane + 32 * j;
        float mu = g_stats[512 + f] * invN;
        float var = g_stats[768 + f] * invN - mu * mu;
        float sc = g[f] * rsqrtf(var + 1e-5f);
        float v = fmaxf(sc * (g_hpre[(size_t)w * HC + f] - mu) + be[f], 0.f);
        s = fmaf(v, wout[f], s);
    }
    #pragma unroll
    for (int o = 16; o; o >>= 1) s += __shfl_xor_sync(0xffffffffu, s, o);
    if (lane == 0) out[w] = s + bout[0];
}

// ---------------- launch ----------------
extern "C" void kernel_launch(void* const* d_in, const int* in_sizes, int n_in,
                              void* d_out, int out_size) {
    const float* x     = (const float*)d_in[0];
    const int*   esrc  = (const int*)d_in[1];
    const int*   edst  = (const int*)d_in[2];
    const float* eattr = (const float*)d_in[3];
    const float* W1    = (const float*)d_in[4];
    const float* atts1 = (const float*)d_in[5];
    const float* attd1 = (const float*)d_in[6];
    const float* We1   = (const float*)d_in[7];
    const float* atte1 = (const float*)d_in[8];
    const float* b1    = (const float*)d_in[9];
    const float* g1    = (const float*)d_in[10];
    const float* be1   = (const float*)d_in[11];
    const float* W2    = (const float*)d_in[12];
    const float* atts2 = (const float*)d_in[13];
    const float* attd2 = (const float*)d_in[14];
    const float* We2   = (const float*)d_in[15];
    const float* atte2 = (const float*)d_in[16];
    const float* b2    = (const float*)d_in[17];
    const float* g2    = (const float*)d_in[18];
    const float* be2   = (const float*)d_in[19];
    const float* Wout  = (const float*)d_in[20];
    const float* bout  = (const float*)d_in[21];
    float* out = (float*)d_out;

    const int EB = (EE + 255) / 256;
    const int NB = (NN + 255) / 256;
    const int WB = NN / 8;                 // warp-per-node kernels (256 thr)
    dim3 gg(2, (NN + 127) / 128);

    // setup
    k_zero<<<NB, 256>>>();
    k_ve<<<1, 128>>>(We1, atte1, We2, atte2);
    k_prepW<<<256, 64>>>(W1, 64, 0);
    k_prepW<<<256, 256>>>(W2, 256, 1);
    k_deg<<<EB, 256>>>(edst);
    k_scan1<<<NB, 256>>>();
    k_scan2<<<1, 256>>>(NB);
    k_scan3<<<NB, 256>>>();
    k_edge<<<EB, 256>>>(eattr, esrc, edst);   // direct CSR scatter

    // layer 1 (attdot fused into GEMM epilogue)
    k_gemm<<<gg, 256>>>(x, NN, 64, 0, 0, atts1, attd1);
    k_agg<<<WB, 256>>>(0, b1);
    k_stats<<<256, 256>>>(0);
    k_bnprep<<<1, 256>>>(g1, be1);

    // layer 2 (BN-ReLU of layer1 fused into GEMM A-load)
    k_gemm<<<gg, 256>>>(nullptr, NN, 256, 1, 1, atts2, attd2);
    k_agg<<<WB, 256>>>(1, b2);
    k_stats<<<256, 256>>>(512);

    // output head
    k_final<<<WB, 256>>>(g2, be2, Wout, bout, out);
}

// round 8
// speedup vs baseline: 1.3338x; 1.0163x over previous
#include <cuda_runtime.h>
#include <cuda_bf16.h>
#include <cuda_fp16.h>

#define NN 50000
#define EE 800000
#define HC 256

// ---------------- scratch (device globals; no allocation allowed) ----------------
__device__ __align__(16) __half g_xsh[NN * HC];  // xs of current layer, fp16
__device__ float g_hpre[NN * HC];   // aggregated pre-BN output (fp32)
__device__ float g_as[NN * 4];
__device__ float g_ad[NN * 4];
__device__ float g_ae1c[EE * 4];    // a_e layer1, CSR order
__device__ float g_ae2c[EE * 4];    // a_e layer2, CSR order
__device__ int   g_deg[NN];
__device__ int   g_offs[NN + 1];
__device__ int   g_cursor[NN];
__device__ int   g_bsum[256];
__device__ int   g_bbase[257];
__device__ int   g_csrc[EE];
__device__ float g_ve1[64];         // [16,4]
__device__ float g_ve2[64];
__device__ float g_stats[1024];     // layer1: [0,512), layer2: [512,1024)
__device__ float g_bnsc[256];       // layer1 BN scale (fused into GEMM2 A-load)
__device__ float g_bnsh[256];       // layer1 BN shift
// W pre-transposed [n][k], bf16 hi/lo planes, per layer
__device__ __align__(16) unsigned short g_WtH[2][256 * 256];
__device__ __align__(16) unsigned short g_WtL[2][256 * 256];

__device__ __forceinline__ float lrelu(float x) { return fmaxf(x, 0.2f * x); }

__device__ __forceinline__ void split_pk(float x0, float x1, unsigned& h, unsigned& l) {
    __nv_bfloat16 h0 = __float2bfloat16_rn(x0), h1 = __float2bfloat16_rn(x1);
    float r0 = x0 - __bfloat162float(h0), r1 = x1 - __bfloat162float(h1);
    __nv_bfloat16 l0 = __float2bfloat16_rn(r0), l1 = __float2bfloat16_rn(r1);
    h = (unsigned)__bfloat16_as_ushort(h0) | ((unsigned)__bfloat16_as_ushort(h1) << 16);
    l = (unsigned)__bfloat16_as_ushort(l0) | ((unsigned)__bfloat16_as_ushort(l1) << 16);
}

#define MMA_BF16(C, A0, A1, A2, A3, B0, B1)                                      \
    asm volatile("mma.sync.aligned.m16n8k16.row.col.f32.bf16.bf16.f32 "          \
                 "{%0,%1,%2,%3}, {%4,%5,%6,%7}, {%8,%9}, {%0,%1,%2,%3};\n"       \
                 : "+f"((C)[0]), "+f"((C)[1]), "+f"((C)[2]), "+f"((C)[3])        \
                 : "r"(A0), "r"(A1), "r"(A2), "r"(A3), "r"(B0), "r"(B1))

// ---------------- setup kernels ----------------
__global__ void k_zero() {
    int i = blockIdx.x * blockDim.x + threadIdx.x;
    if (i < NN) g_deg[i] = 0;
    if (i < 1024) g_stats[i] = 0.f;
}

// merged: blocks 0..255 -> prepW(W1,K=64,l0); 256..511 -> prepW(W2,K=256,l1); 512 -> ve
__global__ void k_setup(const float* __restrict__ We1, const float* __restrict__ at1,
                        const float* __restrict__ We2, const float* __restrict__ at2,
                        const float* __restrict__ W1, const float* __restrict__ W2) {
    int b = blockIdx.x;
    int t = threadIdx.x;
    if (b == 512) {
        if (t < 128) {
            int which = t >> 6;
            int u = t & 63;
            int j = u >> 2, h = u & 3;
            const float* We = which ? We2 : We1;
            const float* at = which ? at2 : at1;
            float s = 0.f;
            #pragma unroll 8
            for (int c = 0; c < 64; c++) s += We[j * HC + h * 64 + c] * at[h * 64 + c];
            if (which) g_ve2[u] = s; else g_ve1[u] = s;
        }
        return;
    }
    int layer = (b >= 256) ? 1 : 0;
    int n = layer ? (b - 256) : b;
    int K = layer ? 256 : 64;
    const float* W = layer ? W2 : W1;
    if (t >= K) return;
    float x = W[(size_t)t * 256 + n];
    __nv_bfloat16 h = __float2bfloat16_rn(x);
    float lo = x - __bfloat162float(h);
    __nv_bfloat16 l = __float2bfloat16_rn(lo);
    g_WtH[layer][n * K + t] = __bfloat16_as_ushort(h);
    g_WtL[layer][n * K + t] = __bfloat16_as_ushort(l);
}

// degree histogram only (dst reads, 3.2 MB)
__global__ void k_deg(const int* __restrict__ dst) {
    int e = blockIdx.x * blockDim.x + threadIdx.x;
    if (e < EE) atomicAdd(&g_deg[dst[e]], 1);
}

// ------------- 3-kernel exclusive scan of deg -> offs, cursor -------------
__global__ void k_scan1() {
    __shared__ int sh[256];
    int b = blockIdx.x, t = threadIdx.x;
    int i = b * 256 + t;
    sh[t] = (i < NN) ? g_deg[i] : 0;
    __syncthreads();
    for (int o = 128; o; o >>= 1) { if (t < o) sh[t] += sh[t + o]; __syncthreads(); }
    if (t == 0) g_bsum[b] = sh[0];
}

__global__ void k_scan2(int nb) {
    __shared__ int sh[256];
    int t = threadIdx.x;
    sh[t] = (t < nb) ? g_bsum[t] : 0;
    __syncthreads();
    for (int o = 1; o < 256; o <<= 1) {
        int v = (t >= o) ? sh[t - o] : 0;
        __syncthreads();
        sh[t] += v;
        __syncthreads();
    }
    g_bbase[t + 1] = sh[t];
    if (t == 0) { g_bbase[0] = 0; g_offs[NN] = EE; }
}

__global__ void k_scan3() {
    __shared__ int sh[256];
    int b = blockIdx.x, t = threadIdx.x;
    int i = b * 256 + t;
    int d = (i < NN) ? g_deg[i] : 0;
    sh[t] = d;
    __syncthreads();
    for (int o = 1; o < 256; o <<= 1) {
        int v = (t >= o) ? sh[t - o] : 0;
        __syncthreads();
        sh[t] += v;
        __syncthreads();
    }
    if (i < NN) {
        int off = g_bbase[b] + sh[t] - d;
        g_offs[i] = off;
        g_cursor[i] = off;
    }
}

// per-edge a_e for both layers, scattered DIRECTLY to CSR position
__global__ void k_edge(const float* __restrict__ eattr, const int* __restrict__ src,
                       const int* __restrict__ dst) {
    int e = blockIdx.x * blockDim.x + threadIdx.x;
    if (e >= EE) return;
    const float4* p = (const float4*)(eattr + (size_t)e * 16);
    float4 a = p[0], b = p[1], c = p[2], d = p[3];
    float v[16] = {a.x,a.y,a.z,a.w, b.x,b.y,b.z,b.w, c.x,c.y,c.z,c.w, d.x,d.y,d.z,d.w};
    float o1[4] = {0,0,0,0}, o2[4] = {0,0,0,0};
    #pragma unroll
    for (int j = 0; j < 16; j++) {
        #pragma unroll
        for (int h = 0; h < 4; h++) {
            o1[h] += v[j] * g_ve1[j * 4 + h];
            o2[h] += v[j] * g_ve2[j * 4 + h];
        }
    }
    int pos = atomicAdd(&g_cursor[dst[e]], 1);
    g_csrc[pos] = src[e];
    *(float4*)(g_ae1c + (size_t)pos * 4) = make_float4(o1[0], o1[1], o1[2], o1[3]);
    *(float4*)(g_ae2c + (size_t)pos * 4) = make_float4(o2[0], o2[1], o2[2], o2[3]);
}

// ---------------- tensor-core GEMM: C[M,256] = A[M,K] @ W, bf16 3-term split ----
// BM=128 BN=128 BK=16, 8 warps (2m x 4n), warp tile 64x32, mma m16n8k16.
// Double-buffered smem (one barrier per chunk). Fused: optional BN-ReLU on
// A-load (layer2), attdot epilogue, fp16 C store. sred overlays sAh[0].
__global__ void __launch_bounds__(256, 2)
k_gemm(const float* __restrict__ Aext, int M, int K, int layer, int bnflag,
       const float* __restrict__ atts, const float* __restrict__ attd) {
    const float* A = Aext ? Aext : g_hpre;
    __shared__ unsigned sAh[2][1536], sAl[2][1536];   // 128 rows x 12 words
    __shared__ unsigned sBh[2][1536], sBl[2][1536];   // total 48 KB
    int tid = threadIdx.x;
    int lane = tid & 31, wid = tid >> 5;
    int wm = (wid >> 2) * 64, wn = (wid & 3) * 32;
    int rowBlk = blockIdx.y * 128, colBlk = blockIdx.x * 128;

    int ar = tid >> 1;
    int ak = (tid & 1) * 8;
    bool aval = (rowBlk + ar) < M;
    const float* Ap = A + (size_t)(rowBlk + ar) * K + ak;
    int bn_ = tid & 127;
    int bsel = tid >> 7;
    const unsigned short* Bp =
        (bsel ? g_WtL[layer] : g_WtH[layer]) + (size_t)(colBlk + bn_) * K;

    float c[4][4][4];
    #pragma unroll
    for (int mt = 0; mt < 4; mt++)
        #pragma unroll
        for (int nt = 0; nt < 4; nt++)
            #pragma unroll
            for (int q = 0; q < 4; q++) c[mt][nt][q] = 0.f;

    int nch = K >> 4;
    float av[8];
    uint4 bq0, bq1;

    auto loadChunk = [&](int ch) {
        const float* Ap2 = Ap + ch * 16;
        float4 u = aval ? *(const float4*)(Ap2) : make_float4(0, 0, 0, 0);
        float4 v = aval ? *(const float4*)(Ap2 + 4) : make_float4(0, 0, 0, 0);
        av[0]=u.x; av[1]=u.y; av[2]=u.z; av[3]=u.w;
        av[4]=v.x; av[5]=v.y; av[6]=v.z; av[7]=v.w;
        if (bnflag && aval) {
            int kk = ch * 16 + ak;
            #pragma unroll
            for (int j = 0; j < 8; j++)
                av[j] = fmaxf(fmaf(g_bnsc[kk + j], av[j], g_bnsh[kk + j]), 0.f);
        }
        const uint4* Bc = (const uint4*)(Bp + ch * 16);
        bq0 = Bc[0];
        bq1 = Bc[1];
    };
    auto stage = [&](int nb) {
        unsigned h0, h1, h2, h3, l0, l1, l2, l3;
        split_pk(av[0], av[1], h0, l0);
        split_pk(av[2], av[3], h1, l1);
        split_pk(av[4], av[5], h2, l2);
        split_pk(av[6], av[7], h3, l3);
        int base = ar * 12 + (ak >> 1);
        *(uint4*)(&sAh[nb][base]) = make_uint4(h0, h1, h2, h3);
        *(uint4*)(&sAl[nb][base]) = make_uint4(l0, l1, l2, l3);
        unsigned* sB = bsel ? sBl[nb] : sBh[nb];
        int bb = bn_ * 12;
        *(uint4*)(sB + bb) = bq0;
        *(uint4*)(sB + bb + 4) = bq1;
    };

    loadChunk(0);
    stage(0);
    __syncthreads();

    for (int ch = 0; ch < nch; ch++) {
        int cur = ch & 1;
        if (ch + 1 < nch) loadChunk(ch + 1);
        // compute from smem[cur]
        unsigned bh0[4], bh1[4], bl0[4], bl1[4];
        #pragma unroll
        for (int nt = 0; nt < 4; nt++) {
            int nb = (wn + nt * 8 + (lane >> 2)) * 12 + (lane & 3);
            bh0[nt] = sBh[cur][nb]; bh1[nt] = sBh[cur][nb + 4];
            bl0[nt] = sBl[cur][nb]; bl1[nt] = sBl[cur][nb + 4];
        }
        #pragma unroll
        for (int mt = 0; mt < 4; mt++) {
            int ab = (wm + mt * 16 + (lane >> 2)) * 12 + (lane & 3);
            unsigned ah0 = sAh[cur][ab], ah1 = sAh[cur][ab + 96];
            unsigned ah2 = sAh[cur][ab + 4], ah3 = sAh[cur][ab + 100];
            unsigned al0 = sAl[cur][ab], al1 = sAl[cur][ab + 96];
            unsigned al2 = sAl[cur][ab + 4], al3 = sAl[cur][ab + 100];
            #pragma unroll
            for (int nt = 0; nt < 4; nt++) {
                MMA_BF16(c[mt][nt], ah0, ah1, ah2, ah3, bh0[nt], bh1[nt]);
                MMA_BF16(c[mt][nt], ah0, ah1, ah2, ah3, bl0[nt], bl1[nt]);
                MMA_BF16(c[mt][nt], al0, al1, al2, al3, bh0[nt], bh1[nt]);
            }
        }
        if (ch + 1 < nch) stage(cur ^ 1);   // write OTHER buffer: no pre-store sync
        __syncthreads();
    }

    // epilogue: write C as fp16 (only consumer is the agg gather)
    #pragma unroll
    for (int mt = 0; mt < 4; mt++) {
        int r0 = rowBlk + wm + mt * 16 + (lane >> 2);
        #pragma unroll
        for (int nt = 0; nt < 4; nt++) {
            int col = colBlk + wn + nt * 8 + (lane & 3) * 2;
            if (r0 < M)
                *(__half2*)(g_xsh + (size_t)r0 * 256 + col) =
                    __floats2half2_rn(c[mt][nt][0], c[mt][nt][1]);
            if (r0 + 8 < M)
                *(__half2*)(g_xsh + (size_t)(r0 + 8) * 256 + col) =
                    __floats2half2_rn(c[mt][nt][2], c[mt][nt][3]);
        }
    }
    // fused attdot: partial dots per n-warp -> sred (overlays sAh[0], safe: all
    // compute done after final loop barrier) -> reduce -> g_as/g_ad
    float2* sred = reinterpret_cast<float2*>(&sAh[0][0]);   // [4][128]
    float sv[4][2], dv[4][2];
    #pragma unroll
    for (int nt = 0; nt < 4; nt++)
        #pragma unroll
        for (int q = 0; q < 2; q++) {
            int col = colBlk + wn + nt * 8 + (lane & 3) * 2 + q;
            sv[nt][q] = atts[col];
            dv[nt][q] = attd[col];
        }
    #pragma unroll
    for (int mt = 0; mt < 4; mt++) {
        #pragma unroll
        for (int half = 0; half < 2; half++) {
            float ss = 0.f, dd = 0.f;
            #pragma unroll
            for (int nt = 0; nt < 4; nt++) {
                #pragma unroll
                for (int q = 0; q < 2; q++) {
                    ss = fmaf(c[mt][nt][half * 2 + q], sv[nt][q], ss);
                    dd = fmaf(c[mt][nt][half * 2 + q], dv[nt][q], dd);
                }
            }
            ss += __shfl_xor_sync(0xffffffffu, ss, 1);
            ss += __shfl_xor_sync(0xffffffffu, ss, 2);
            dd += __shfl_xor_sync(0xffffffffu, dd, 1);
            dd += __shfl_xor_sync(0xffffffffu, dd, 2);
            if ((lane & 3) == 0)
                sred[(wid & 3) * 128 + wm + mt * 16 + half * 8 + (lane >> 2)] =
                    make_float2(ss, dd);
        }
    }
    __syncthreads();
    {
        int row = tid >> 1, hl = tid & 1;
        int r = rowBlk + row;
        if (r < M) {
            float2 aa = sred[2 * hl * 128 + row], bb = sred[(2 * hl + 1) * 128 + row];
            int hidx = (colBlk >> 6) + hl;
            g_as[r * 4 + hidx] = aa.x + bb.x;
            g_ad[r * 4 + hidx] = aa.y + bb.y;
        }
    }
}

// ---------------- GAT aggregation: single pass, warp per dst node.
// fp16 row gather: one LDG.128 per edge per lane; fp32 accumulation. --------
__global__ void __launch_bounds__(256) k_agg(int layer, const float* __restrict__ bias) {
    __shared__ float4 sp[8][32];
    __shared__ int    si[8][32];
    int w = (blockIdx.x * blockDim.x + threadIdx.x) >> 5;
    if (w >= NN) return;
    int lane = threadIdx.x & 31;
    int wrp = threadIdx.x >> 5;
    const float4* aeC = (const float4*)(layer ? g_ae2c : g_ae1c);
    int beg = g_offs[w], end = g_offs[w + 1];
    float4 adv = *(const float4*)(g_ad + (size_t)w * 4);
    int h = lane >> 3;
    int f0 = lane * 8;
    float acc[8] = {0, 0, 0, 0, 0, 0, 0, 0};
    float den0 = 0, den1 = 0, den2 = 0, den3 = 0;
    float sa0 = 0, sa1 = 0, sa2 = 0, sa3 = 0;

    for (int base = beg; base < end; base += 32) {
        int i = base + lane;
        float p0 = 0, p1 = 0, p2 = 0, p3 = 0;
        int s = 0;
        if (i < end) {
            s = g_csrc[i];
            float4 ae = aeC[i];
            float4 as = *(const float4*)(g_as + (size_t)s * 4);
            sa0 += ae.x; sa1 += ae.y; sa2 += ae.z; sa3 += ae.w;
            p0 = __expf(lrelu(as.x + adv.x + ae.x));
            p1 = __expf(lrelu(as.y + adv.y + ae.y));
            p2 = __expf(lrelu(as.z + adv.z + ae.z));
            p3 = __expf(lrelu(as.w + adv.w + ae.w));
            den0 += p0; den1 += p1; den2 += p2; den3 += p3;
        }
        sp[wrp][lane] = make_float4(p0, p1, p2, p3);
        si[wrp][lane] = s;
        __syncwarp();
        int cnt = min(32, end - base);
        #pragma unroll 4
        for (int jj = 0; jj < cnt; jj++) {
            int ss = si[wrp][jj];
            float q = ((const float*)&sp[wrp][jj])[h];
            uint4 xv = *(const uint4*)(g_xsh + (size_t)ss * HC + f0);
            float2 x0 = __half22float2(*(__half2*)&xv.x);
            float2 x1 = __half22float2(*(__half2*)&xv.y);
            float2 x2 = __half22float2(*(__half2*)&xv.z);
            float2 x3 = __half22float2(*(__half2*)&xv.w);
            acc[0] = fmaf(q, x0.x, acc[0]); acc[1] = fmaf(q, x0.y, acc[1]);
            acc[2] = fmaf(q, x1.x, acc[2]); acc[3] = fmaf(q, x1.y, acc[3]);
            acc[4] = fmaf(q, x2.x, acc[4]); acc[5] = fmaf(q, x2.y, acc[5]);
            acc[6] = fmaf(q, x3.x, acc[6]); acc[7] = fmaf(q, x3.y, acc[7]);
        }
        __syncwarp();
    }
    #pragma unroll
    for (int o = 16; o; o >>= 1) {
        den0 += __shfl_xor_sync(0xffffffffu, den0, o);
        den1 += __shfl_xor_sync(0xffffffffu, den1, o);
        den2 += __shfl_xor_sync(0xffffffffu, den2, o);
        den3 += __shfl_xor_sync(0xffffffffu, den3, o);
        sa0 += __shfl_xor_sync(0xffffffffu, sa0, o);
        sa1 += __shfl_xor_sync(0xffffffffu, sa1, o);
        sa2 += __shfl_xor_sync(0xffffffffu, sa2, o);
        sa3 += __shfl_xor_sync(0xffffffffu, sa3, o);
    }
    int deg = end - beg;
    float invd = 1.0f / fmaxf((float)deg, 1.0f);
    float4 asn = *(const float4*)(g_as + (size_t)w * 4);
    float ps0 = __expf(lrelu(asn.x + adv.x + sa0 * invd));
    float ps1 = __expf(lrelu(asn.y + adv.y + sa1 * invd));
    float ps2 = __expf(lrelu(asn.z + adv.z + sa2 * invd));
    float ps3 = __expf(lrelu(asn.w + adv.w + sa3 * invd));
    den0 += ps0 + 1e-16f; den1 += ps1 + 1e-16f;
    den2 += ps2 + 1e-16f; den3 += ps3 + 1e-16f;
    {
        uint4 xv = *(const uint4*)(g_xsh + (size_t)w * HC + f0);
        float2 x0 = __half22float2(*(__half2*)&xv.x);
        float2 x1 = __half22float2(*(__half2*)&xv.y);
        float2 x2 = __half22float2(*(__half2*)&xv.z);
        float2 x3 = __half22float2(*(__half2*)&xv.w);
        float psh = (h == 0) ? ps0 : (h == 1) ? ps1 : (h == 2) ? ps2 : ps3;
        acc[0] = fmaf(psh, x0.x, acc[0]); acc[1] = fmaf(psh, x0.y, acc[1]);
        acc[2] = fmaf(psh, x1.x, acc[2]); acc[3] = fmaf(psh, x1.y, acc[3]);
        acc[4] = fmaf(psh, x2.x, acc[4]); acc[5] = fmaf(psh, x2.y, acc[5]);
        acc[6] = fmaf(psh, x3.x, acc[6]); acc[7] = fmaf(psh, x3.y, acc[7]);
    }
    float denh = (h == 0) ? den0 : (h == 1) ? den1 : (h == 2) ? den2 : den3;
    float r = 1.0f / denh;
    float4 b0 = *(const float4*)(bias + f0);
    float4 b1 = *(const float4*)(bias + f0 + 4);
    float* op = g_hpre + (size_t)w * HC + f0;
    *(float4*)(op)     = make_float4(fmaf(acc[0], r, b0.x), fmaf(acc[1], r, b0.y),
                                     fmaf(acc[2], r, b0.z), fmaf(acc[3], r, b0.w));
    *(float4*)(op + 4) = make_float4(fmaf(acc[4], r, b1.x), fmaf(acc[5], r, b1.y),
                                     fmaf(acc[6], r, b1.z), fmaf(acc[7], r, b1.w));
}

// ---------------- BN batch stats (sum, sumsq per column) ----------------
__global__ void k_stats(int off) {
    int c = threadIdx.x;    // 256
    int rows = (NN + gridDim.x - 1) / gridDim.x;
    int r0 = blockIdx.x * rows, r1 = min(r0 + rows, NN);
    float s = 0.f, s2 = 0.f;
    for (int r = r0; r < r1; r++) {
        float v = g_hpre[(size_t)r * HC + c];
        s += v;
        s2 = fmaf(v, v, s2);
    }
    atomicAdd(&g_stats[off + c], s);
    atomicAdd(&g_stats[off + 256 + c], s2);
}

// layer1 BN -> per-column scale/shift (consumed by GEMM2 A-load)
__global__ void k_bnprep(const float* __restrict__ g, const float* __restrict__ be) {
    int c = threadIdx.x;
    const float invN = 1.0f / NN;
    float mu = g_stats[c] * invN;
    float var = g_stats[256 + c] * invN - mu * mu;
    float sc = g[c] * rsqrtf(var + 1e-5f);
    g_bnsc[c] = sc;
    g_bnsh[c] = be[c] - sc * mu;
}

// ---------------- final: out[n] = relu(BN(hpre2)) . wout + bout ----------------
__global__ void k_final(const float* __restrict__ g, const float* __restrict__ be,
                        const float* __restrict__ wout, const float* __restrict__ bout,
                        float* __restrict__ out) {
    int w = (blockIdx.x * blockDim.x + threadIdx.x) >> 5;
    if (w >= NN) return;
    int lane = threadIdx.x & 31;
    const float invN = 1.0f / NN;
    float s = 0.f;
    #pragma unroll
    for (int j = 0; j < 8; j++) {
        int f = lane + 32 * j;
        float mu = g_stats[512 + f] * invN;
        float var = g_stats[768 + f] * invN - mu * mu;
        float sc = g[f] * rsqrtf(var + 1e-5f);
        float v = fmaxf(sc * (g_hpre[(size_t)w * HC + f] - mu) + be[f], 0.f);
        s = fmaf(v, wout[f], s);
    }
    #pragma unroll
    for (int o = 16; o; o >>= 1) s += __shfl_xor_sync(0xffffffffu, s, o);
    if (lane == 0) out[w] = s + bout[0];
}

// ---------------- launch ----------------
extern "C" void kernel_launch(void* const* d_in, const int* in_sizes, int n_in,
                              void* d_out, int out_size) {
    const float* x     = (const float*)d_in[0];
    const int*   esrc  = (const int*)d_in[1];
    const int*   edst  = (const int*)d_in[2];
    const float* eattr = (const float*)d_in[3];
    const float* W1    = (const float*)d_in[4];
    const float* atts1 = (const float*)d_in[5];
    const float* attd1 = (const float*)d_in[6];
    const float* We1   = (const float*)d_in[7];
    const float* atte1 = (const float*)d_in[8];
    const float* b1    = (const float*)d_in[9];
    const float* g1    = (const float*)d_in[10];
    const float* be1   = (const float*)d_in[11];
    const float* W2    = (const float*)d_in[12];
    const float* atts2 = (const float*)d_in[13];
    const float* attd2 = (const float*)d_in[14];
    const float* We2   = (const float*)d_in[15];
    const float* atte2 = (const float*)d_in[16];
    const float* b2    = (const float*)d_in[17];
    const float* g2    = (const float*)d_in[18];
    const float* be2   = (const float*)d_in[19];
    const float* Wout  = (const float*)d_in[20];
    const float* bout  = (const float*)d_in[21];
    float* out = (float*)d_out;

    const int EB = (EE + 255) / 256;
    const int NB = (NN + 255) / 256;
    const int WB = NN / 8;                 // warp-per-node kernels (256 thr)
    dim3 gg(2, (NN + 127) / 128);

    // setup — ordered so ncu's captured launch (#4) is GEMM layer-1
    k_zero<<<NB, 256>>>();                                      // 1
    k_setup<<<513, 256>>>(We1, atte1, We2, atte2, W1, W2);      // 2
    k_deg<<<EB, 256>>>(edst);                                   // 3
    k_gemm<<<gg, 256>>>(x, NN, 64, 0, 0, atts1, attd1);         // 4  <- profiled
    k_scan1<<<NB, 256>>>();                                     // 5
    k_scan2<<<1, 256>>>(NB);                                    // 6
    k_scan3<<<NB, 256>>>();                                     // 7
    k_edge<<<EB, 256>>>(eattr, esrc, edst);                     // 8

    // layer 1
    k_agg<<<WB, 256>>>(0, b1);                                  // 9
    k_stats<<<256, 256>>>(0);                                   // 10
    k_bnprep<<<1, 256>>>(g1, be1);                              // 11

    // layer 2 (BN-ReLU of layer1 fused into GEMM A-load)
    k_gemm<<<gg, 256>>>(nullptr, NN, 256, 1, 1, atts2, attd2);  // 12
    k_agg<<<WB, 256>>>(1, b2);                                  // 13
    k_stats<<<256, 256>>>(512);                                 // 14

    // output head
    k_final<<<WB, 256>>>(g2, be2, Wout, bout, out);             // 15
}

// round 9
// speedup vs baseline: 1.3541x; 1.0153x over previous
#include <cuda_runtime.h>
#include <cuda_bf16.h>
#include <cuda_fp16.h>

#define NN 50000
#define EE 800000
#define HC 256

// ---------------- scratch (device globals; no allocation allowed) ----------------
__device__ __align__(16) __half g_xsh[NN * HC];  // xs of current layer, fp16
__device__ float g_hpre[NN * HC];   // aggregated pre-BN output (fp32)
__device__ float g_as[NN * 4];
__device__ float g_ad[NN * 4];
__device__ float g_ae1c[EE * 4];    // a_e layer1, CSR order
__device__ float g_ae2c[EE * 4];    // a_e layer2, CSR order
__device__ int   g_deg[NN];
__device__ int   g_offs[NN + 1];
__device__ int   g_cursor[NN];
__device__ int   g_bsum[256];
__device__ int   g_bbase[257];
__device__ int   g_csrc[EE];
__device__ float g_ve1[64];         // [16,4]
__device__ float g_ve2[64];
__device__ float g_stats[1024];     // layer1: [0,512), layer2: [512,1024)
__device__ float g_bnsc[256];       // layer1 BN scale (fused into GEMM2 A-load)
__device__ float g_bnsh[256];       // layer1 BN shift
// W pre-transposed [n][k], bf16 hi/lo planes, per layer
__device__ __align__(16) unsigned short g_WtH[2][256 * 256];
__device__ __align__(16) unsigned short g_WtL[2][256 * 256];

__device__ __forceinline__ float lrelu(float x) { return fmaxf(x, 0.2f * x); }

__device__ __forceinline__ void split_pk(float x0, float x1, unsigned& h, unsigned& l) {
    __nv_bfloat16 h0 = __float2bfloat16_rn(x0), h1 = __float2bfloat16_rn(x1);
    float r0 = x0 - __bfloat162float(h0), r1 = x1 - __bfloat162float(h1);
    __nv_bfloat16 l0 = __float2bfloat16_rn(r0), l1 = __float2bfloat16_rn(r1);
    h = (unsigned)__bfloat16_as_ushort(h0) | ((unsigned)__bfloat16_as_ushort(h1) << 16);
    l = (unsigned)__bfloat16_as_ushort(l0) | ((unsigned)__bfloat16_as_ushort(l1) << 16);
}

#define MMA_BF16(C, A0, A1, A2, A3, B0, B1)                                      \
    asm volatile("mma.sync.aligned.m16n8k16.row.col.f32.bf16.bf16.f32 "          \
                 "{%0,%1,%2,%3}, {%4,%5,%6,%7}, {%8,%9}, {%0,%1,%2,%3};\n"       \
                 : "+f"((C)[0]), "+f"((C)[1]), "+f"((C)[2]), "+f"((C)[3])        \
                 : "r"(A0), "r"(A1), "r"(A2), "r"(A3), "r"(B0), "r"(B1))

// ---------------- setup kernels ----------------
__global__ void k_zero() {
    int i = blockIdx.x * blockDim.x + threadIdx.x;
    if (i < NN) g_deg[i] = 0;
    if (i < 1024) g_stats[i] = 0.f;
}

// merged: blocks 0..255 -> prepW(W1,K=64,l0); 256..511 -> prepW(W2,K=256,l1); 512 -> ve
__global__ void k_setup(const float* __restrict__ We1, const float* __restrict__ at1,
                        const float* __restrict__ We2, const float* __restrict__ at2,
                        const float* __restrict__ W1, const float* __restrict__ W2) {
    int b = blockIdx.x;
    int t = threadIdx.x;
    if (b == 512) {
        if (t < 128) {
            int which = t >> 6;
            int u = t & 63;
            int j = u >> 2, h = u & 3;
            const float* We = which ? We2 : We1;
            const float* at = which ? at2 : at1;
            float s = 0.f;
            #pragma unroll 8
            for (int c = 0; c < 64; c++) s += We[j * HC + h * 64 + c] * at[h * 64 + c];
            if (which) g_ve2[u] = s; else g_ve1[u] = s;
        }
        return;
    }
    int layer = (b >= 256) ? 1 : 0;
    int n = layer ? (b - 256) : b;
    int K = layer ? 256 : 64;
    const float* W = layer ? W2 : W1;
    if (t >= K) return;
    float x = W[(size_t)t * 256 + n];
    __nv_bfloat16 h = __float2bfloat16_rn(x);
    float lo = x - __bfloat162float(h);
    __nv_bfloat16 l = __float2bfloat16_rn(lo);
    g_WtH[layer][n * K + t] = __bfloat16_as_ushort(h);
    g_WtL[layer][n * K + t] = __bfloat16_as_ushort(l);
}

// degree histogram only (dst reads, 3.2 MB)
__global__ void k_deg(const int* __restrict__ dst) {
    int e = blockIdx.x * blockDim.x + threadIdx.x;
    if (e < EE) atomicAdd(&g_deg[dst[e]], 1);
}

// ------------- 3-kernel exclusive scan of deg -> offs, cursor -------------
__global__ void k_scan1() {
    __shared__ int sh[256];
    int b = blockIdx.x, t = threadIdx.x;
    int i = b * 256 + t;
    sh[t] = (i < NN) ? g_deg[i] : 0;
    __syncthreads();
    for (int o = 128; o; o >>= 1) { if (t < o) sh[t] += sh[t + o]; __syncthreads(); }
    if (t == 0) g_bsum[b] = sh[0];
}

__global__ void k_scan2(int nb) {
    __shared__ int sh[256];
    int t = threadIdx.x;
    sh[t] = (t < nb) ? g_bsum[t] : 0;
    __syncthreads();
    for (int o = 1; o < 256; o <<= 1) {
        int v = (t >= o) ? sh[t - o] : 0;
        __syncthreads();
        sh[t] += v;
        __syncthreads();
    }
    g_bbase[t + 1] = sh[t];
    if (t == 0) { g_bbase[0] = 0; g_offs[NN] = EE; }
}

__global__ void k_scan3() {
    __shared__ int sh[256];
    int b = blockIdx.x, t = threadIdx.x;
    int i = b * 256 + t;
    int d = (i < NN) ? g_deg[i] : 0;
    sh[t] = d;
    __syncthreads();
    for (int o = 1; o < 256; o <<= 1) {
        int v = (t >= o) ? sh[t - o] : 0;
        __syncthreads();
        sh[t] += v;
        __syncthreads();
    }
    if (i < NN) {
        int off = g_bbase[b] + sh[t] - d;
        g_offs[i] = off;
        g_cursor[i] = off;
    }
}

// per-edge a_e for both layers, scattered DIRECTLY to CSR position
__global__ void k_edge(const float* __restrict__ eattr, const int* __restrict__ src,
                       const int* __restrict__ dst) {
    int e = blockIdx.x * blockDim.x + threadIdx.x;
    if (e >= EE) return;
    const float4* p = (const float4*)(eattr + (size_t)e * 16);
    float4 a = p[0], b = p[1], c = p[2], d = p[3];
    float v[16] = {a.x,a.y,a.z,a.w, b.x,b.y,b.z,b.w, c.x,c.y,c.z,c.w, d.x,d.y,d.z,d.w};
    float o1[4] = {0,0,0,0}, o2[4] = {0,0,0,0};
    #pragma unroll
    for (int j = 0; j < 16; j++) {
        #pragma unroll
        for (int h = 0; h < 4; h++) {
            o1[h] += v[j] * g_ve1[j * 4 + h];
            o2[h] += v[j] * g_ve2[j * 4 + h];
        }
    }
    int pos = atomicAdd(&g_cursor[dst[e]], 1);
    g_csrc[pos] = src[e];
    *(float4*)(g_ae1c + (size_t)pos * 4) = make_float4(o1[0], o1[1], o1[2], o1[3]);
    *(float4*)(g_ae2c + (size_t)pos * 4) = make_float4(o2[0], o2[1], o2[2], o2[3]);
}

// ---------------- tensor-core GEMM: C[M,256] = A[M,K] @ W, bf16 3-term split ----
// BM=128 BN=128 BK=16, 8 warps (2m x 4n), warp tile 64x32, mma m16n8k16.
// smem: 8 words/row, k-pair-permuted units (u0={p0,p4} u1={p1,p5} u2={p2,p6}
// u3={p3,p7}) + XOR swizzle (unit ^= row&3). Frag loads are LDS.64,
// conflict-free per half-warp. Double buffered. Fused BN-ReLU / attdot / fp16 C.
__global__ void __launch_bounds__(256, 2)
k_gemm(const float* __restrict__ Aext, int M, int K, int layer, int bnflag,
       const float* __restrict__ atts, const float* __restrict__ attd) {
    const float* A = Aext ? Aext : g_hpre;
    __shared__ unsigned sAh[2][1024], sAl[2][1024];   // 128 rows x 8 words
    __shared__ unsigned sBh[2][1024], sBl[2][1024];   // total 32 KB
    int tid = threadIdx.x;
    int lane = tid & 31, wid = tid >> 5;
    int wm = (wid >> 2) * 64, wn = (wid & 3) * 32;
    int rowBlk = blockIdx.y * 128, colBlk = blockIdx.x * 128;

    // A loader: thread -> (row ar, half sel); owns k {sel*4..+3} U {sel*4+8..+3}
    int ar = tid >> 1;
    int sel = tid & 1;
    bool aval = (rowBlk + ar) < M;
    const float* Ap = A + (size_t)(rowBlk + ar) * K + sel * 4;
    int bn_ = tid & 127;
    int bsel = tid >> 7;
    const unsigned short* Bp =
        (bsel ? g_WtL[layer] : g_WtH[layer]) + (size_t)(colBlk + bn_) * K;

    float c[4][4][4];
    #pragma unroll
    for (int mt = 0; mt < 4; mt++)
        #pragma unroll
        for (int nt = 0; nt < 4; nt++)
            #pragma unroll
            for (int q = 0; q < 4; q++) c[mt][nt][q] = 0.f;

    int nch = K >> 4;
    float4 fu, fv;
    uint4 bq0, bq1;

    auto loadChunk = [&](int ch) {
        const float* Ap2 = Ap + ch * 16;
        fu = aval ? *(const float4*)(Ap2) : make_float4(0, 0, 0, 0);
        fv = aval ? *(const float4*)(Ap2 + 8) : make_float4(0, 0, 0, 0);
        if (bnflag && aval) {
            int kk = ch * 16 + sel * 4;
            float4 sc0 = *(const float4*)(g_bnsc + kk);
            float4 sh0 = *(const float4*)(g_bnsh + kk);
            float4 sc1 = *(const float4*)(g_bnsc + kk + 8);
            float4 sh1 = *(const float4*)(g_bnsh + kk + 8);
            fu.x = fmaxf(fmaf(sc0.x, fu.x, sh0.x), 0.f);
            fu.y = fmaxf(fmaf(sc0.y, fu.y, sh0.y), 0.f);
            fu.z = fmaxf(fmaf(sc0.z, fu.z, sh0.z), 0.f);
            fu.w = fmaxf(fmaf(sc0.w, fu.w, sh0.w), 0.f);
            fv.x = fmaxf(fmaf(sc1.x, fv.x, sh1.x), 0.f);
            fv.y = fmaxf(fmaf(sc1.y, fv.y, sh1.y), 0.f);
            fv.z = fmaxf(fmaf(sc1.z, fv.z, sh1.z), 0.f);
            fv.w = fmaxf(fmaf(sc1.w, fv.w, sh1.w), 0.f);
        }
        const uint4* Bc = (const uint4*)(Bp + ch * 16);
        bq0 = Bc[0];
        bq1 = Bc[1];
    };
    auto stage = [&](int nb) {
        // A: units (2sel, 2sel+1) = word pairs {pk(u01),pk(v01)} {pk(u23),pk(v23)}
        unsigned w0, w1, w2, w3, l0, l1, l2, l3;
        split_pk(fu.x, fu.y, w0, l0);
        split_pk(fv.x, fv.y, w1, l1);
        split_pk(fu.z, fu.w, w2, l2);
        split_pk(fv.z, fv.w, w3, l3);
        int s = ar & 3;
        int addr = ar * 8 + ((((2 * sel) ^ s) & ~1) << 1);
        if (s & 1) {
            *(uint4*)(&sAh[nb][addr]) = make_uint4(w2, w3, w0, w1);
            *(uint4*)(&sAl[nb][addr]) = make_uint4(l2, l3, l0, l1);
        } else {
            *(uint4*)(&sAh[nb][addr]) = make_uint4(w0, w1, w2, w3);
            *(uint4*)(&sAl[nb][addr]) = make_uint4(l0, l1, l2, l3);
        }
        // B: repack (bq0,bq1) into permuted units 0..3
        unsigned* sB = bsel ? sBl[nb] : sBh[nb];
        int t = bn_ & 3;
        uint4 W0 = make_uint4(bq0.x, bq1.x, bq0.y, bq1.y);
        uint4 W1 = make_uint4(bq0.z, bq1.z, bq0.w, bq1.w);
        if (t & 1) {
            W0 = make_uint4(W0.z, W0.w, W0.x, W0.y);
            W1 = make_uint4(W1.z, W1.w, W1.x, W1.y);
        }
        int a0 = bn_ * 8 + (((0 ^ t) & ~1) << 1);
        int a1 = bn_ * 8 + (((2 ^ t) & ~1) << 1);
        *(uint4*)(sB + a0) = W0;
        *(uint4*)(sB + a1) = W1;
    };

    loadChunk(0);
    stage(0);
    __syncthreads();

    for (int ch = 0; ch < nch; ch++) {
        int cur = ch & 1;
        if (ch + 1 < nch) loadChunk(ch + 1);
        // B frags: one LDS.64 per (nt, plane)
        uint2 bh[4], bl[4];
        #pragma unroll
        for (int nt = 0; nt < 4; nt++) {
            int n = wn + nt * 8 + (lane >> 2);
            int off = n * 8 + ((((lane & 3) ^ (n & 3)) & 3) * 2);
            bh[nt] = *(const uint2*)(&sBh[cur][off]);
            bl[nt] = *(const uint2*)(&sBl[cur][off]);
        }
        #pragma unroll
        for (int mt = 0; mt < 4; mt++) {
            int r = wm + mt * 16 + (lane >> 2);
            int uoff = (((lane & 3) ^ (r & 3)) & 3) * 2;
            uint2 h0 = *(const uint2*)(&sAh[cur][r * 8 + uoff]);        // (a0,a2)
            uint2 h1 = *(const uint2*)(&sAh[cur][(r + 8) * 8 + uoff]);  // (a1,a3)
            uint2 q0 = *(const uint2*)(&sAl[cur][r * 8 + uoff]);
            uint2 q1 = *(const uint2*)(&sAl[cur][(r + 8) * 8 + uoff]);
            #pragma unroll
            for (int nt = 0; nt < 4; nt++) {
                MMA_BF16(c[mt][nt], h0.x, h1.x, h0.y, h1.y, bh[nt].x, bh[nt].y);
                MMA_BF16(c[mt][nt], h0.x, h1.x, h0.y, h1.y, bl[nt].x, bl[nt].y);
                MMA_BF16(c[mt][nt], q0.x, q1.x, q0.y, q1.y, bh[nt].x, bh[nt].y);
            }
        }
        if (ch + 1 < nch) stage(cur ^ 1);   // write OTHER buffer: no pre-store sync
        __syncthreads();
    }

    // epilogue: write C as fp16 (only consumer is the agg gather)
    #pragma unroll
    for (int mt = 0; mt < 4; mt++) {
        int r0 = rowBlk + wm + mt * 16 + (lane >> 2);
        #pragma unroll
        for (int nt = 0; nt < 4; nt++) {
            int col = colBlk + wn + nt * 8 + (lane & 3) * 2;
            if (r0 < M)
                *(__half2*)(g_xsh + (size_t)r0 * 256 + col) =
                    __floats2half2_rn(c[mt][nt][0], c[mt][nt][1]);
            if (r0 + 8 < M)
                *(__half2*)(g_xsh + (size_t)(r0 + 8) * 256 + col) =
                    __floats2half2_rn(c[mt][nt][2], c[mt][nt][3]);
        }
    }
    // fused attdot: partial dots per n-warp -> sred (overlays sAh, safe after
    // final loop barrier) -> reduce -> g_as/g_ad
    float2* sred = reinterpret_cast<float2*>(&sAh[0][0]);   // [4][128] = 4KB
    float sv[4][2], dv[4][2];
    #pragma unroll
    for (int nt = 0; nt < 4; nt++)
        #pragma unroll
        for (int q = 0; q < 2; q++) {
            int col = colBlk + wn + nt * 8 + (lane & 3) * 2 + q;
            sv[nt][q] = atts[col];
            dv[nt][q] = attd[col];
        }
    #pragma unroll
    for (int mt = 0; mt < 4; mt++) {
        #pragma unroll
        for (int half = 0; half < 2; half++) {
            float ss = 0.f, dd = 0.f;
            #pragma unroll
            for (int nt = 0; nt < 4; nt++) {
                #pragma unroll
                for (int q = 0; q < 2; q++) {
                    ss = fmaf(c[mt][nt][half * 2 + q], sv[nt][q], ss);
                    dd = fmaf(c[mt][nt][half * 2 + q], dv[nt][q], dd);
                }
            }
            ss += __shfl_xor_sync(0xffffffffu, ss, 1);
            ss += __shfl_xor_sync(0xffffffffu, ss, 2);
            dd += __shfl_xor_sync(0xffffffffu, dd, 1);
            dd += __shfl_xor_sync(0xffffffffu, dd, 2);
            if ((lane & 3) == 0)
                sred[(wid & 3) * 128 + wm + mt * 16 + half * 8 + (lane >> 2)] =
                    make_float2(ss, dd);
        }
    }
    __syncthreads();
    {
        int row = tid >> 1, hl = tid & 1;
        int r = rowBlk + row;
        if (r < M) {
            float2 aa = sred[2 * hl * 128 + row], bb = sred[(2 * hl + 1) * 128 + row];
            int hidx = (colBlk >> 6) + hl;
            g_as[r * 4 + hidx] = aa.x + bb.x;
            g_ad[r * 4 + hidx] = aa.y + bb.y;
        }
    }
}

// ---------------- GAT aggregation: single pass, warp per dst node.
// fp16 row gather: one LDG.128 per edge per lane; fp32 accumulation. --------
__global__ void __launch_bounds__(256) k_agg(int layer, const float* __restrict__ bias) {
    __shared__ float4 sp[8][32];
    __shared__ int    si[8][32];
    int w = (blockIdx.x * blockDim.x + threadIdx.x) >> 5;
    if (w >= NN) return;
    int lane = threadIdx.x & 31;
    int wrp = threadIdx.x >> 5;
    const float4* aeC = (const float4*)(layer ? g_ae2c : g_ae1c);
    int beg = g_offs[w], end = g_offs[w + 1];
    float4 adv = *(const float4*)(g_ad + (size_t)w * 4);
    int h = lane >> 3;
    int f0 = lane * 8;
    float acc[8] = {0, 0, 0, 0, 0, 0, 0, 0};
    float den0 = 0, den1 = 0, den2 = 0, den3 = 0;
    float sa0 = 0, sa1 = 0, sa2 = 0, sa3 = 0;

    for (int base = beg; base < end; base += 32) {
        int i = base + lane;
        float p0 = 0, p1 = 0, p2 = 0, p3 = 0;
        int s = 0;
        if (i < end) {
            s = g_csrc[i];
            float4 ae = aeC[i];
            float4 as = *(const float4*)(g_as + (size_t)s * 4);
            sa0 += ae.x; sa1 += ae.y; sa2 += ae.z; sa3 += ae.w;
            p0 = __expf(lrelu(as.x + adv.x + ae.x));
            p1 = __expf(lrelu(as.y + adv.y + ae.y));
            p2 = __expf(lrelu(as.z + adv.z + ae.z));
            p3 = __expf(lrelu(as.w + adv.w + ae.w));
            den0 += p0; den1 += p1; den2 += p2; den3 += p3;
        }
        sp[wrp][lane] = make_float4(p0, p1, p2, p3);
        si[wrp][lane] = s;
        __syncwarp();
        int cnt = min(32, end - base);
        #pragma unroll 4
        for (int jj = 0; jj < cnt; jj++) {
            int ss = si[wrp][jj];
            float q = ((const float*)&sp[wrp][jj])[h];
            uint4 xv = *(const uint4*)(g_xsh + (size_t)ss * HC + f0);
            float2 x0 = __half22float2(*(__half2*)&xv.x);
            float2 x1 = __half22float2(*(__half2*)&xv.y);
            float2 x2 = __half22float2(*(__half2*)&xv.z);
            float2 x3 = __half22float2(*(__half2*)&xv.w);
            acc[0] = fmaf(q, x0.x, acc[0]); acc[1] = fmaf(q, x0.y, acc[1]);
            acc[2] = fmaf(q, x1.x, acc[2]); acc[3] = fmaf(q, x1.y, acc[3]);
            acc[4] = fmaf(q, x2.x, acc[4]); acc[5] = fmaf(q, x2.y, acc[5]);
            acc[6] = fmaf(q, x3.x, acc[6]); acc[7] = fmaf(q, x3.y, acc[7]);
        }
        __syncwarp();
    }
    #pragma unroll
    for (int o = 16; o; o >>= 1) {
        den0 += __shfl_xor_sync(0xffffffffu, den0, o);
        den1 += __shfl_xor_sync(0xffffffffu, den1, o);
        den2 += __shfl_xor_sync(0xffffffffu, den2, o);
        den3 += __shfl_xor_sync(0xffffffffu, den3, o);
        sa0 += __shfl_xor_sync(0xffffffffu, sa0, o);
        sa1 += __shfl_xor_sync(0xffffffffu, sa1, o);
        sa2 += __shfl_xor_sync(0xffffffffu, sa2, o);
        sa3 += __shfl_xor_sync(0xffffffffu, sa3, o);
    }
    int deg = end - beg;
    float invd = 1.0f / fmaxf((float)deg, 1.0f);
    float4 asn = *(const float4*)(g_as + (size_t)w * 4);
    float ps0 = __expf(lrelu(asn.x + adv.x + sa0 * invd));
    float ps1 = __expf(lrelu(asn.y + adv.y + sa1 * invd));
    float ps2 = __expf(lrelu(asn.z + adv.z + sa2 * invd));
    float ps3 = __expf(lrelu(asn.w + adv.w + sa3 * invd));
    den0 += ps0 + 1e-16f; den1 += ps1 + 1e-16f;
    den2 += ps2 + 1e-16f; den3 += ps3 + 1e-16f;
    {
        uint4 xv = *(const uint4*)(g_xsh + (size_t)w * HC + f0);
        float2 x0 = __half22float2(*(__half2*)&xv.x);
        float2 x1 = __half22float2(*(__half2*)&xv.y);
        float2 x2 = __half22float2(*(__half2*)&xv.z);
        float2 x3 = __half22float2(*(__half2*)&xv.w);
        float psh = (h == 0) ? ps0 : (h == 1) ? ps1 : (h == 2) ? ps2 : ps3;
        acc[0] = fmaf(psh, x0.x, acc[0]); acc[1] = fmaf(psh, x0.y, acc[1]);
        acc[2] = fmaf(psh, x1.x, acc[2]); acc[3] = fmaf(psh, x1.y, acc[3]);
        acc[4] = fmaf(psh, x2.x, acc[4]); acc[5] = fmaf(psh, x2.y, acc[5]);
        acc[6] = fmaf(psh, x3.x, acc[6]); acc[7] = fmaf(psh, x3.y, acc[7]);
    }
    float denh = (h == 0) ? den0 : (h == 1) ? den1 : (h == 2) ? den2 : den3;
    float r = 1.0f / denh;
    float4 b0 = *(const float4*)(bias + f0);
    float4 b1 = *(const float4*)(bias + f0 + 4);
    float* op = g_hpre + (size_t)w * HC + f0;
    *(float4*)(op)     = make_float4(fmaf(acc[0], r, b0.x), fmaf(acc[1], r, b0.y),
                                     fmaf(acc[2], r, b0.z), fmaf(acc[3], r, b0.w));
    *(float4*)(op + 4) = make_float4(fmaf(acc[4], r, b1.x), fmaf(acc[5], r, b1.y),
                                     fmaf(acc[6], r, b1.z), fmaf(acc[7], r, b1.w));
}

// ---------------- BN batch stats (sum, sumsq per column) ----------------
__global__ void k_stats(int off) {
    int c = threadIdx.x;    // 256
    int rows = (NN + gridDim.x - 1) / gridDim.x;
    int r0 = blockIdx.x * rows, r1 = min(r0 + rows, NN);
    float s = 0.f, s2 = 0.f;
    for (int r = r0; r < r1; r++) {
        float v = g_hpre[(size_t)r * HC + c];
        s += v;
        s2 = fmaf(v, v, s2);
    }
    atomicAdd(&g_stats[off + c], s);
    atomicAdd(&g_stats[off + 256 + c], s2);
}

// layer1 BN -> per-column scale/shift (consumed by GEMM2 A-load)
__global__ void k_bnprep(const float* __restrict__ g, const float* __restrict__ be) {
    int c = threadIdx.x;
    const float invN = 1.0f / NN;
    float mu = g_stats[c] * invN;
    float var = g_stats[256 + c] * invN - mu * mu;
    float sc = g[c] * rsqrtf(var + 1e-5f);
    g_bnsc[c] = sc;
    g_bnsh[c] = be[c] - sc * mu;
}

// ---------------- final: out[n] = relu(BN(hpre2)) . wout + bout ----------------
__global__ void k_final(const float* __restrict__ g, const float* __restrict__ be,
                        const float* __restrict__ wout, const float* __restrict__ bout,
                        float* __restrict__ out) {
    int w = (blockIdx.x * blockDim.x + threadIdx.x) >> 5;
    if (w >= NN) return;
    int lane = threadIdx.x & 31;
    const float invN = 1.0f / NN;
    float s = 0.f;
    #pragma unroll
    for (int j = 0; j < 8; j++) {
        int f = lane + 32 * j;
        float mu = g_stats[512 + f] * invN;
        float var = g_stats[768 + f] * invN - mu * mu;
        float sc = g[f] * rsqrtf(var + 1e-5f);
        float v = fmaxf(sc * (g_hpre[(size_t)w * HC + f] - mu) + be[f], 0.f);
        s = fmaf(v, wout[f], s);
    }
    #pragma unroll
    for (int o = 16; o; o >>= 1) s += __shfl_xor_sync(0xffffffffu, s, o);
    if (lane == 0) out[w] = s + bout[0];
}

// ---------------- launch ----------------
extern "C" void kernel_launch(void* const* d_in, const int* in_sizes, int n_in,
                              void* d_out, int out_size) {
    const float* x     = (const float*)d_in[0];
    const int*   esrc  = (const int*)d_in[1];
    const int*   edst  = (const int*)d_in[2];
    const float* eattr = (const float*)d_in[3];
    const float* W1    = (const float*)d_in[4];
    const float* atts1 = (const float*)d_in[5];
    const float* attd1 = (const float*)d_in[6];
    const float* We1   = (const float*)d_in[7];
    const float* atte1 = (const float*)d_in[8];
    const float* b1    = (const float*)d_in[9];
    const float* g1    = (const float*)d_in[10];
    const float* be1   = (const float*)d_in[11];
    const float* W2    = (const float*)d_in[12];
    const float* atts2 = (const float*)d_in[13];
    const float* attd2 = (const float*)d_in[14];
    const float* We2   = (const float*)d_in[15];
    const float* atte2 = (const float*)d_in[16];
    const float* b2    = (const float*)d_in[17];
    const float* g2    = (const float*)d_in[18];
    const float* be2   = (const float*)d_in[19];
    const float* Wout  = (const float*)d_in[20];
    const float* bout  = (const float*)d_in[21];
    float* out = (float*)d_out;

    const int EB = (EE + 255) / 256;
    const int NB = (NN + 255) / 256;
    const int WB = NN / 8;                 // warp-per-node kernels (256 thr)
    dim3 gg(2, (NN + 127) / 128);

    // setup — ordered so ncu's captured launch (#4) is GEMM layer-1
    k_zero<<<NB, 256>>>();                                      // 1
    k_setup<<<513, 256>>>(We1, atte1, We2, atte2, W1, W2);      // 2
    k_deg<<<EB, 256>>>(edst);                                   // 3
    k_gemm<<<gg, 256>>>(x, NN, 64, 0, 0, atts1, attd1);         // 4  <- profiled
    k_scan1<<<NB, 256>>>();                                     // 5
    k_scan2<<<1, 256>>>(NB);                                    // 6
    k_scan3<<<NB, 256>>>();                                     // 7
    k_edge<<<EB, 256>>>(eattr, esrc, edst);                     // 8

    // layer 1
    k_agg<<<WB, 256>>>(0, b1);                                  // 9
    k_stats<<<256, 256>>>(0);                                   // 10
    k_bnprep<<<1, 256>>>(g1, be1);                              // 11

    // layer 2 (BN-ReLU of layer1 fused into GEMM A-load)
    k_gemm<<<gg, 256>>>(nullptr, NN, 256, 1, 1, atts2, attd2);  // 12
    k_agg<<<WB, 256>>>(1, b2);                                  // 13
    k_stats<<<256, 256>>>(512);                                 // 14

    // output head
    k_final<<<WB, 256>>>(g2, be2, Wout, bout, out);             // 15
}

// round 10
// speedup vs baseline: 1.3938x; 1.0293x over previous
#include <cuda_runtime.h>
#include <cuda_bf16.h>
#include <cuda_fp16.h>

#define NN 50000
#define EE 800000
#define HC 256

// ---------------- scratch (device globals; no allocation allowed) ----------------
__device__ __align__(16) __half g_xsh[NN * HC];  // xs of current layer, fp16
__device__ float g_hpre[NN * HC];   // aggregated pre-BN output (fp32)
__device__ float g_as[NN * 4];
__device__ float g_ad[NN * 4];
__device__ float g_ae1c[EE * 4];    // a_e layer1, CSR order
__device__ float g_ae2c[EE * 4];    // a_e layer2, CSR order
__device__ int   g_deg[NN];
__device__ int   g_offs[NN + 1];
__device__ int   g_cursor[NN];
__device__ int   g_bsum[256];
__device__ int   g_bbase[257];
__device__ int   g_csrc[EE];
__device__ float g_ve1[64];         // [16,4]
__device__ float g_ve2[64];
__device__ float g_stats[1024];     // layer1: [0,512), layer2: [512,1024)
__device__ float g_bnsc[256];       // layer1 BN scale (fused into GEMM2 A-load)
__device__ float g_bnsh[256];       // layer1 BN shift
// W pre-transposed [n][k], bf16 hi/lo planes, per layer
__device__ __align__(16) unsigned short g_WtH[2][256 * 256];
__device__ __align__(16) unsigned short g_WtL[2][256 * 256];

__device__ __forceinline__ float lrelu(float x) { return fmaxf(x, 0.2f * x); }

__device__ __forceinline__ void split_pk(float x0, float x1, unsigned& h, unsigned& l) {
    __nv_bfloat16 h0 = __float2bfloat16_rn(x0), h1 = __float2bfloat16_rn(x1);
    float r0 = x0 - __bfloat162float(h0), r1 = x1 - __bfloat162float(h1);
    __nv_bfloat16 l0 = __float2bfloat16_rn(r0), l1 = __float2bfloat16_rn(r1);
    h = (unsigned)__bfloat16_as_ushort(h0) | ((unsigned)__bfloat16_as_ushort(h1) << 16);
    l = (unsigned)__bfloat16_as_ushort(l0) | ((unsigned)__bfloat16_as_ushort(l1) << 16);
}

#define MMA_BF16(C, A0, A1, A2, A3, B0, B1)                                      \
    asm volatile("mma.sync.aligned.m16n8k16.row.col.f32.bf16.bf16.f32 "          \
                 "{%0,%1,%2,%3}, {%4,%5,%6,%7}, {%8,%9}, {%0,%1,%2,%3};\n"       \
                 : "+f"((C)[0]), "+f"((C)[1]), "+f"((C)[2]), "+f"((C)[3])        \
                 : "r"(A0), "r"(A1), "r"(A2), "r"(A3), "r"(B0), "r"(B1))

// ---------------- setup kernels ----------------
__global__ void k_zero() {
    int i = blockIdx.x * blockDim.x + threadIdx.x;
    if (i < NN) g_deg[i] = 0;
    if (i < 1024) g_stats[i] = 0.f;
}

// merged: blocks 0..255 -> prepW(W1,K=64,l0); 256..511 -> prepW(W2,K=256,l1); 512 -> ve
__global__ void k_setup(const float* __restrict__ We1, const float* __restrict__ at1,
                        const float* __restrict__ We2, const float* __restrict__ at2,
                        const float* __restrict__ W1, const float* __restrict__ W2) {
    int b = blockIdx.x;
    int t = threadIdx.x;
    if (b == 512) {
        if (t < 128) {
            int which = t >> 6;
            int u = t & 63;
            int j = u >> 2, h = u & 3;
            const float* We = which ? We2 : We1;
            const float* at = which ? at2 : at1;
            float s = 0.f;
            #pragma unroll 8
            for (int c = 0; c < 64; c++) s += We[j * HC + h * 64 + c] * at[h * 64 + c];
            if (which) g_ve2[u] = s; else g_ve1[u] = s;
        }
        return;
    }
    int layer = (b >= 256) ? 1 : 0;
    int n = layer ? (b - 256) : b;
    int K = layer ? 256 : 64;
    const float* W = layer ? W2 : W1;
    if (t >= K) return;
    float x = W[(size_t)t * 256 + n];
    __nv_bfloat16 h = __float2bfloat16_rn(x);
    float lo = x - __bfloat162float(h);
    __nv_bfloat16 l = __float2bfloat16_rn(lo);
    g_WtH[layer][n * K + t] = __bfloat16_as_ushort(h);
    g_WtL[layer][n * K + t] = __bfloat16_as_ushort(l);
}

// degree histogram only (dst reads, 3.2 MB)
__global__ void k_deg(const int* __restrict__ dst) {
    int e = blockIdx.x * blockDim.x + threadIdx.x;
    if (e < EE) atomicAdd(&g_deg[dst[e]], 1);
}

// ------------- 3-kernel exclusive scan of deg -> offs, cursor -------------
__global__ void k_scan1() {
    __shared__ int sh[256];
    int b = blockIdx.x, t = threadIdx.x;
    int i = b * 256 + t;
    sh[t] = (i < NN) ? g_deg[i] : 0;
    __syncthreads();
    for (int o = 128; o; o >>= 1) { if (t < o) sh[t] += sh[t + o]; __syncthreads(); }
    if (t == 0) g_bsum[b] = sh[0];
}

__global__ void k_scan2(int nb) {
    __shared__ int sh[256];
    int t = threadIdx.x;
    sh[t] = (t < nb) ? g_bsum[t] : 0;
    __syncthreads();
    for (int o = 1; o < 256; o <<= 1) {
        int v = (t >= o) ? sh[t - o] : 0;
        __syncthreads();
        sh[t] += v;
        __syncthreads();
    }
    g_bbase[t + 1] = sh[t];
    if (t == 0) { g_bbase[0] = 0; g_offs[NN] = EE; }
}

__global__ void k_scan3() {
    __shared__ int sh[256];
    int b = blockIdx.x, t = threadIdx.x;
    int i = b * 256 + t;
    int d = (i < NN) ? g_deg[i] : 0;
    sh[t] = d;
    __syncthreads();
    for (int o = 1; o < 256; o <<= 1) {
        int v = (t >= o) ? sh[t - o] : 0;
        __syncthreads();
        sh[t] += v;
        __syncthreads();
    }
    if (i < NN) {
        int off = g_bbase[b] + sh[t] - d;
        g_offs[i] = off;
        g_cursor[i] = off;
    }
}

// per-edge a_e for both layers, scattered DIRECTLY to CSR position
__global__ void k_edge(const float* __restrict__ eattr, const int* __restrict__ src,
                       const int* __restrict__ dst) {
    int e = blockIdx.x * blockDim.x + threadIdx.x;
    if (e >= EE) return;
    const float4* p = (const float4*)(eattr + (size_t)e * 16);
    float4 a = p[0], b = p[1], c = p[2], d = p[3];
    float v[16] = {a.x,a.y,a.z,a.w, b.x,b.y,b.z,b.w, c.x,c.y,c.z,c.w, d.x,d.y,d.z,d.w};
    float o1[4] = {0,0,0,0}, o2[4] = {0,0,0,0};
    #pragma unroll
    for (int j = 0; j < 16; j++) {
        #pragma unroll
        for (int h = 0; h < 4; h++) {
            o1[h] += v[j] * g_ve1[j * 4 + h];
            o2[h] += v[j] * g_ve2[j * 4 + h];
        }
    }
    int pos = atomicAdd(&g_cursor[dst[e]], 1);
    g_csrc[pos] = src[e];
    *(float4*)(g_ae1c + (size_t)pos * 4) = make_float4(o1[0], o1[1], o1[2], o1[3]);
    *(float4*)(g_ae2c + (size_t)pos * 4) = make_float4(o2[0], o2[1], o2[2], o2[3]);
}

// ---------------- tensor-core GEMM: C[M,256] = A[M,K] @ W, bf16 3-term split ----
// BM=128 BN=128 BK=16, 8 warps (2m x 4n), warp tile 64x32, mma m16n8k16.
// smem: 8 words/row, k-pair-permuted units + XOR swizzle; frag loads LDS.64.
// Double buffered. Fused BN-ReLU / attdot / fp16 C.
__global__ void __launch_bounds__(256, 2)
k_gemm(const float* __restrict__ Aext, int M, int K, int layer, int bnflag,
       const float* __restrict__ atts, const float* __restrict__ attd) {
    const float* A = Aext ? Aext : g_hpre;
    __shared__ unsigned sAh[2][1024], sAl[2][1024];   // 128 rows x 8 words
    __shared__ unsigned sBh[2][1024], sBl[2][1024];   // total 32 KB
    int tid = threadIdx.x;
    int lane = tid & 31, wid = tid >> 5;
    int wm = (wid >> 2) * 64, wn = (wid & 3) * 32;
    int rowBlk = blockIdx.y * 128, colBlk = blockIdx.x * 128;

    int ar = tid >> 1;
    int sel = tid & 1;
    bool aval = (rowBlk + ar) < M;
    const float* Ap = A + (size_t)(rowBlk + ar) * K + sel * 4;
    int bn_ = tid & 127;
    int bsel = tid >> 7;
    const unsigned short* Bp =
        (bsel ? g_WtL[layer] : g_WtH[layer]) + (size_t)(colBlk + bn_) * K;

    float c[4][4][4];
    #pragma unroll
    for (int mt = 0; mt < 4; mt++)
        #pragma unroll
        for (int nt = 0; nt < 4; nt++)
            #pragma unroll
            for (int q = 0; q < 4; q++) c[mt][nt][q] = 0.f;

    int nch = K >> 4;
    float4 fu, fv;
    uint4 bq0, bq1;

    auto loadChunk = [&](int ch) {
        const float* Ap2 = Ap + ch * 16;
        fu = aval ? *(const float4*)(Ap2) : make_float4(0, 0, 0, 0);
        fv = aval ? *(const float4*)(Ap2 + 8) : make_float4(0, 0, 0, 0);
        if (bnflag && aval) {
            int kk = ch * 16 + sel * 4;
            float4 sc0 = *(const float4*)(g_bnsc + kk);
            float4 sh0 = *(const float4*)(g_bnsh + kk);
            float4 sc1 = *(const float4*)(g_bnsc + kk + 8);
            float4 sh1 = *(const float4*)(g_bnsh + kk + 8);
            fu.x = fmaxf(fmaf(sc0.x, fu.x, sh0.x), 0.f);
            fu.y = fmaxf(fmaf(sc0.y, fu.y, sh0.y), 0.f);
            fu.z = fmaxf(fmaf(sc0.z, fu.z, sh0.z), 0.f);
            fu.w = fmaxf(fmaf(sc0.w, fu.w, sh0.w), 0.f);
            fv.x = fmaxf(fmaf(sc1.x, fv.x, sh1.x), 0.f);
            fv.y = fmaxf(fmaf(sc1.y, fv.y, sh1.y), 0.f);
            fv.z = fmaxf(fmaf(sc1.z, fv.z, sh1.z), 0.f);
            fv.w = fmaxf(fmaf(sc1.w, fv.w, sh1.w), 0.f);
        }
        const uint4* Bc = (const uint4*)(Bp + ch * 16);
        bq0 = Bc[0];
        bq1 = Bc[1];
    };
    auto stage = [&](int nb) {
        unsigned w0, w1, w2, w3, l0, l1, l2, l3;
        split_pk(fu.x, fu.y, w0, l0);
        split_pk(fv.x, fv.y, w1, l1);
        split_pk(fu.z, fu.w, w2, l2);
        split_pk(fv.z, fv.w, w3, l3);
        int s = ar & 3;
        int addr = ar * 8 + ((((2 * sel) ^ s) & ~1) << 1);
        if (s & 1) {
            *(uint4*)(&sAh[nb][addr]) = make_uint4(w2, w3, w0, w1);
            *(uint4*)(&sAl[nb][addr]) = make_uint4(l2, l3, l0, l1);
        } else {
            *(uint4*)(&sAh[nb][addr]) = make_uint4(w0, w1, w2, w3);
            *(uint4*)(&sAl[nb][addr]) = make_uint4(l0, l1, l2, l3);
        }
        unsigned* sB = bsel ? sBl[nb] : sBh[nb];
        int t = bn_ & 3;
        uint4 W0 = make_uint4(bq0.x, bq1.x, bq0.y, bq1.y);
        uint4 W1 = make_uint4(bq0.z, bq1.z, bq0.w, bq1.w);
        if (t & 1) {
            W0 = make_uint4(W0.z, W0.w, W0.x, W0.y);
            W1 = make_uint4(W1.z, W1.w, W1.x, W1.y);
        }
        int a0 = bn_ * 8 + (((0 ^ t) & ~1) << 1);
        int a1 = bn_ * 8 + (((2 ^ t) & ~1) << 1);
        *(uint4*)(sB + a0) = W0;
        *(uint4*)(sB + a1) = W1;
    };

    loadChunk(0);
    stage(0);
    __syncthreads();

    for (int ch = 0; ch < nch; ch++) {
        int cur = ch & 1;
        if (ch + 1 < nch) loadChunk(ch + 1);
        uint2 bh[4], bl[4];
        #pragma unroll
        for (int nt = 0; nt < 4; nt++) {
            int n = wn + nt * 8 + (lane >> 2);
            int off = n * 8 + ((((lane & 3) ^ (n & 3)) & 3) * 2);
            bh[nt] = *(const uint2*)(&sBh[cur][off]);
            bl[nt] = *(const uint2*)(&sBl[cur][off]);
        }
        #pragma unroll
        for (int mt = 0; mt < 4; mt++) {
            int r = wm + mt * 16 + (lane >> 2);
            int uoff = (((lane & 3) ^ (r & 3)) & 3) * 2;
            uint2 h0 = *(const uint2*)(&sAh[cur][r * 8 + uoff]);
            uint2 h1 = *(const uint2*)(&sAh[cur][(r + 8) * 8 + uoff]);
            uint2 q0 = *(const uint2*)(&sAl[cur][r * 8 + uoff]);
            uint2 q1 = *(const uint2*)(&sAl[cur][(r + 8) * 8 + uoff]);
            #pragma unroll
            for (int nt = 0; nt < 4; nt++) {
                MMA_BF16(c[mt][nt], h0.x, h1.x, h0.y, h1.y, bh[nt].x, bh[nt].y);
                MMA_BF16(c[mt][nt], h0.x, h1.x, h0.y, h1.y, bl[nt].x, bl[nt].y);
                MMA_BF16(c[mt][nt], q0.x, q1.x, q0.y, q1.y, bh[nt].x, bh[nt].y);
            }
        }
        if (ch + 1 < nch) stage(cur ^ 1);
        __syncthreads();
    }

    // epilogue: write C as fp16 (only consumer is the agg gather)
    #pragma unroll
    for (int mt = 0; mt < 4; mt++) {
        int r0 = rowBlk + wm + mt * 16 + (lane >> 2);
        #pragma unroll
        for (int nt = 0; nt < 4; nt++) {
            int col = colBlk + wn + nt * 8 + (lane & 3) * 2;
            if (r0 < M)
                *(__half2*)(g_xsh + (size_t)r0 * 256 + col) =
                    __floats2half2_rn(c[mt][nt][0], c[mt][nt][1]);
            if (r0 + 8 < M)
                *(__half2*)(g_xsh + (size_t)(r0 + 8) * 256 + col) =
                    __floats2half2_rn(c[mt][nt][2], c[mt][nt][3]);
        }
    }
    // fused attdot
    float2* sred = reinterpret_cast<float2*>(&sAh[0][0]);   // [4][128] = 4KB
    float sv[4][2], dv[4][2];
    #pragma unroll
    for (int nt = 0; nt < 4; nt++)
        #pragma unroll
        for (int q = 0; q < 2; q++) {
            int col = colBlk + wn + nt * 8 + (lane & 3) * 2 + q;
            sv[nt][q] = atts[col];
            dv[nt][q] = attd[col];
        }
    #pragma unroll
    for (int mt = 0; mt < 4; mt++) {
        #pragma unroll
        for (int half = 0; half < 2; half++) {
            float ss = 0.f, dd = 0.f;
            #pragma unroll
            for (int nt = 0; nt < 4; nt++) {
                #pragma unroll
                for (int q = 0; q < 2; q++) {
                    ss = fmaf(c[mt][nt][half * 2 + q], sv[nt][q], ss);
                    dd = fmaf(c[mt][nt][half * 2 + q], dv[nt][q], dd);
                }
            }
            ss += __shfl_xor_sync(0xffffffffu, ss, 1);
            ss += __shfl_xor_sync(0xffffffffu, ss, 2);
            dd += __shfl_xor_sync(0xffffffffu, dd, 1);
            dd += __shfl_xor_sync(0xffffffffu, dd, 2);
            if ((lane & 3) == 0)
                sred[(wid & 3) * 128 + wm + mt * 16 + half * 8 + (lane >> 2)] =
                    make_float2(ss, dd);
        }
    }
    __syncthreads();
    {
        int row = tid >> 1, hl = tid & 1;
        int r = rowBlk + row;
        if (r < M) {
            float2 aa = sred[2 * hl * 128 + row], bb = sred[(2 * hl + 1) * 128 + row];
            int hidx = (colBlk >> 6) + hl;
            g_as[r * 4 + hidx] = aa.x + bb.x;
            g_ad[r * 4 + hidx] = aa.y + bb.y;
        }
    }
}

// ---------------- GAT aggregation: single pass, warp per dst node.
// fp16 row gather: one LDG.128 per edge per lane; fp32 accumulation. --------
__global__ void __launch_bounds__(256) k_agg(int layer, const float* __restrict__ bias) {
    __shared__ float4 sp[8][32];
    __shared__ int    si[8][32];
    int w = (blockIdx.x * blockDim.x + threadIdx.x) >> 5;
    if (w >= NN) return;
    int lane = threadIdx.x & 31;
    int wrp = threadIdx.x >> 5;
    const float4* aeC = (const float4*)(layer ? g_ae2c : g_ae1c);
    int beg = g_offs[w], end = g_offs[w + 1];
    float4 adv = *(const float4*)(g_ad + (size_t)w * 4);
    int h = lane >> 3;
    int f0 = lane * 8;
    float acc[8] = {0, 0, 0, 0, 0, 0, 0, 0};
    float den0 = 0, den1 = 0, den2 = 0, den3 = 0;
    float sa0 = 0, sa1 = 0, sa2 = 0, sa3 = 0;

    for (int base = beg; base < end; base += 32) {
        int i = base + lane;
        float p0 = 0, p1 = 0, p2 = 0, p3 = 0;
        int s = 0;
        if (i < end) {
            s = g_csrc[i];
            float4 ae = aeC[i];
            float4 as = *(const float4*)(g_as + (size_t)s * 4);
            sa0 += ae.x; sa1 += ae.y; sa2 += ae.z; sa3 += ae.w;
            p0 = __expf(lrelu(as.x + adv.x + ae.x));
            p1 = __expf(lrelu(as.y + adv.y + ae.y));
            p2 = __expf(lrelu(as.z + adv.z + ae.z));
            p3 = __expf(lrelu(as.w + adv.w + ae.w));
            den0 += p0; den1 += p1; den2 += p2; den3 += p3;
        }
        sp[wrp][lane] = make_float4(p0, p1, p2, p3);
        si[wrp][lane] = s;
        __syncwarp();
        int cnt = min(32, end - base);
        #pragma unroll 4
        for (int jj = 0; jj < cnt; jj++) {
            int ss = si[wrp][jj];
            float q = ((const float*)&sp[wrp][jj])[h];
            uint4 xv = *(const uint4*)(g_xsh + (size_t)ss * HC + f0);
            float2 x0 = __half22float2(*(__half2*)&xv.x);
            float2 x1 = __half22float2(*(__half2*)&xv.y);
            float2 x2 = __half22float2(*(__half2*)&xv.z);
            float2 x3 = __half22float2(*(__half2*)&xv.w);
            acc[0] = fmaf(q, x0.x, acc[0]); acc[1] = fmaf(q, x0.y, acc[1]);
            acc[2] = fmaf(q, x1.x, acc[2]); acc[3] = fmaf(q, x1.y, acc[3]);
            acc[4] = fmaf(q, x2.x, acc[4]); acc[5] = fmaf(q, x2.y, acc[5]);
            acc[6] = fmaf(q, x3.x, acc[6]); acc[7] = fmaf(q, x3.y, acc[7]);
        }
        __syncwarp();
    }
    #pragma unroll
    for (int o = 16; o; o >>= 1) {
        den0 += __shfl_xor_sync(0xffffffffu, den0, o);
        den1 += __shfl_xor_sync(0xffffffffu, den1, o);
        den2 += __shfl_xor_sync(0xffffffffu, den2, o);
        den3 += __shfl_xor_sync(0xffffffffu, den3, o);
        sa0 += __shfl_xor_sync(0xffffffffu, sa0, o);
        sa1 += __shfl_xor_sync(0xffffffffu, sa1, o);
        sa2 += __shfl_xor_sync(0xffffffffu, sa2, o);
        sa3 += __shfl_xor_sync(0xffffffffu, sa3, o);
    }
    int deg = end - beg;
    float invd = 1.0f / fmaxf((float)deg, 1.0f);
    float4 asn = *(const float4*)(g_as + (size_t)w * 4);
    float ps0 = __expf(lrelu(asn.x + adv.x + sa0 * invd));
    float ps1 = __expf(lrelu(asn.y + adv.y + sa1 * invd));
    float ps2 = __expf(lrelu(asn.z + adv.z + sa2 * invd));
    float ps3 = __expf(lrelu(asn.w + adv.w + sa3 * invd));
    den0 += ps0 + 1e-16f; den1 += ps1 + 1e-16f;
    den2 += ps2 + 1e-16f; den3 += ps3 + 1e-16f;
    {
        uint4 xv = *(const uint4*)(g_xsh + (size_t)w * HC + f0);
        float2 x0 = __half22float2(*(__half2*)&xv.x);
        float2 x1 = __half22float2(*(__half2*)&xv.y);
        float2 x2 = __half22float2(*(__half2*)&xv.z);
        float2 x3 = __half22float2(*(__half2*)&xv.w);
        float psh = (h == 0) ? ps0 : (h == 1) ? ps1 : (h == 2) ? ps2 : ps3;
        acc[0] = fmaf(psh, x0.x, acc[0]); acc[1] = fmaf(psh, x0.y, acc[1]);
        acc[2] = fmaf(psh, x1.x, acc[2]); acc[3] = fmaf(psh, x1.y, acc[3]);
        acc[4] = fmaf(psh, x2.x, acc[4]); acc[5] = fmaf(psh, x2.y, acc[5]);
        acc[6] = fmaf(psh, x3.x, acc[6]); acc[7] = fmaf(psh, x3.y, acc[7]);
    }
    float denh = (h == 0) ? den0 : (h == 1) ? den1 : (h == 2) ? den2 : den3;
    float r = 1.0f / denh;
    float4 b0 = *(const float4*)(bias + f0);
    float4 b1 = *(const float4*)(bias + f0 + 4);
    float* op = g_hpre + (size_t)w * HC + f0;
    *(float4*)(op)     = make_float4(fmaf(acc[0], r, b0.x), fmaf(acc[1], r, b0.y),
                                     fmaf(acc[2], r, b0.z), fmaf(acc[3], r, b0.w));
    *(float4*)(op + 4) = make_float4(fmaf(acc[4], r, b1.x), fmaf(acc[5], r, b1.y),
                                     fmaf(acc[6], r, b1.z), fmaf(acc[7], r, b1.w));
}

// ---------------- BN batch stats (sum, sumsq per column) ----------------
__global__ void k_stats(int off) {
    int c = threadIdx.x;    // 256
    int rows = (NN + gridDim.x - 1) / gridDim.x;
    int r0 = blockIdx.x * rows, r1 = min(r0 + rows, NN);
    float s = 0.f, s2 = 0.f;
    for (int r = r0; r < r1; r++) {
        float v = g_hpre[(size_t)r * HC + c];
        s += v;
        s2 = fmaf(v, v, s2);
    }
    atomicAdd(&g_stats[off + c], s);
    atomicAdd(&g_stats[off + 256 + c], s2);
}

// layer1 BN -> per-column scale/shift (consumed by GEMM2 A-load)
__global__ void k_bnprep(const float* __restrict__ g, const float* __restrict__ be) {
    int c = threadIdx.x;
    const float invN = 1.0f / NN;
    float mu = g_stats[c] * invN;
    float var = g_stats[256 + c] * invN - mu * mu;
    float sc = g[c] * rsqrtf(var + 1e-5f);
    g_bnsc[c] = sc;
    g_bnsh[c] = be[c] - sc * mu;
}

// ---------------- final: out[n] = relu(BN(hpre2)) . wout + bout ----------------
__global__ void k_final(const float* __restrict__ g, const float* __restrict__ be,
                        const float* __restrict__ wout, const float* __restrict__ bout,
                        float* __restrict__ out) {
    int w = (blockIdx.x * blockDim.x + threadIdx.x) >> 5;
    if (w >= NN) return;
    int lane = threadIdx.x & 31;
    const float invN = 1.0f / NN;
    float s = 0.f;
    #pragma unroll
    for (int j = 0; j < 8; j++) {
        int f = lane + 32 * j;
        float mu = g_stats[512 + f] * invN;
        float var = g_stats[768 + f] * invN - mu * mu;
        float sc = g[f] * rsqrtf(var + 1e-5f);
        float v = fmaxf(sc * (g_hpre[(size_t)w * HC + f] - mu) + be[f], 0.f);
        s = fmaf(v, wout[f], s);
    }
    #pragma unroll
    for (int o = 16; o; o >>= 1) s += __shfl_xor_sync(0xffffffffu, s, o);
    if (lane == 0) out[w] = s + bout[0];
}

// ---------------- stream fork/join resources (created once, OUTSIDE capture:
// the harness's correctness call precedes graph capture; no device memory) -----
struct ForkRes {
    cudaStream_t side;
    cudaEvent_t evFork, evJoin;
    ForkRes() {
        cudaStreamCreateWithFlags(&side, cudaStreamNonBlocking);
        cudaEventCreateWithFlags(&evFork, cudaEventDisableTiming);
        cudaEventCreateWithFlags(&evJoin, cudaEventDisableTiming);
    }
};

// ---------------- launch ----------------
extern "C" void kernel_launch(void* const* d_in, const int* in_sizes, int n_in,
                              void* d_out, int out_size) {
    const float* x     = (const float*)d_in[0];
    const int*   esrc  = (const int*)d_in[1];
    const int*   edst  = (const int*)d_in[2];
    const float* eattr = (const float*)d_in[3];
    const float* W1    = (const float*)d_in[4];
    const float* atts1 = (const float*)d_in[5];
    const float* attd1 = (const float*)d_in[6];
    const float* We1   = (const float*)d_in[7];
    const float* atte1 = (const float*)d_in[8];
    const float* b1    = (const float*)d_in[9];
    const float* g1    = (const float*)d_in[10];
    const float* be1   = (const float*)d_in[11];
    const float* W2    = (const float*)d_in[12];
    const float* atts2 = (const float*)d_in[13];
    const float* attd2 = (const float*)d_in[14];
    const float* We2   = (const float*)d_in[15];
    const float* atte2 = (const float*)d_in[16];
    const float* b2    = (const float*)d_in[17];
    const float* g2    = (const float*)d_in[18];
    const float* be2   = (const float*)d_in[19];
    const float* Wout  = (const float*)d_in[20];
    const float* bout  = (const float*)d_in[21];
    float* out = (float*)d_out;

    static ForkRes fr;      // created on first (correctness) call, pre-capture

    const int EB = (EE + 255) / 256;
    const int NB = (NN + 255) / 256;
    const int WB = NN / 8;                 // warp-per-node kernels (256 thr)
    dim3 gg(2, (NN + 127) / 128);

    // main stream: setup + zero, then fork
    k_setup<<<513, 256>>>(We1, atte1, We2, atte2, W1, W2);      // 1
    k_zero<<<NB, 256>>>();                                      // 2
    cudaEventRecord(fr.evFork, 0);
    cudaStreamWaitEvent(fr.side, fr.evFork, 0);

    // side stream: CSR build chain (independent of GEMM1)
    k_deg<<<EB, 256, 0, fr.side>>>(edst);                       // 3
    // main stream: GEMM layer-1 runs CONCURRENTLY with the CSR chain
    k_gemm<<<gg, 256>>>(x, NN, 64, 0, 0, atts1, attd1);         // 4  <- profiled
    k_scan1<<<NB, 256, 0, fr.side>>>();                         // 5
    k_scan2<<<1, 256, 0, fr.side>>>(NB);                        // 6
    k_scan3<<<NB, 256, 0, fr.side>>>();                         // 7
    k_edge<<<EB, 256, 0, fr.side>>>(eattr, esrc, edst);         // 8
    cudaEventRecord(fr.evJoin, fr.side);
    cudaStreamWaitEvent(0, fr.evJoin, 0);

    // layer 1 (needs gemm1 + CSR)
    k_agg<<<WB, 256>>>(0, b1);                                  // 9
    k_stats<<<256, 256>>>(0);                                   // 10
    k_bnprep<<<1, 256>>>(g1, be1);                              // 11

    // layer 2 (BN-ReLU of layer1 fused into GEMM A-load)
    k_gemm<<<gg, 256>>>(nullptr, NN, 256, 1, 1, atts2, attd2);  // 12
    k_agg<<<WB, 256>>>(1, b2);                                  // 13
    k_stats<<<256, 256>>>(512);                                 // 14

    // output head
    k_final<<<WB, 256>>>(g2, be2, Wout, bout, out);             // 15
}

// round 11
// speedup vs baseline: 1.4052x; 1.0082x over previous
#include <cuda_runtime.h>
#include <cuda_bf16.h>
#include <cuda_fp16.h>

#define NN 50000
#define EE 800000
#define HC 256

// ---------------- scratch (device globals; no allocation allowed) ----------------
__device__ __align__(16) __half g_xsh[NN * HC];  // xs of current layer, fp16
__device__ float g_hpre[NN * HC];   // aggregated pre-BN output (fp32)
__device__ float g_as[NN * 4];
__device__ float g_ad[NN * 4];
__device__ float g_ae1c[EE * 4];    // a_e layer1, CSR order
__device__ float g_ae2c[EE * 4];    // a_e layer2, CSR order
__device__ int   g_deg[NN];
__device__ int   g_offs[NN + 1];
__device__ int   g_cursor[NN];
__device__ int   g_bsum[256];
__device__ int   g_bbase[257];
__device__ int   g_csrc[EE];
__device__ float g_ve1[64];         // [16,4]
__device__ float g_ve2[64];
__device__ float g_stats[1024];     // layer1: [0,512), layer2: [512,1024)
// W pre-transposed [n][k], bf16 hi/lo planes, per layer
__device__ __align__(16) unsigned short g_WtH[2][256 * 256];
__device__ __align__(16) unsigned short g_WtL[2][256 * 256];

__device__ __forceinline__ float lrelu(float x) { return fmaxf(x, 0.2f * x); }

__device__ __forceinline__ void split_pk(float x0, float x1, unsigned& h, unsigned& l) {
    __nv_bfloat16 h0 = __float2bfloat16_rn(x0), h1 = __float2bfloat16_rn(x1);
    float r0 = x0 - __bfloat162float(h0), r1 = x1 - __bfloat162float(h1);
    __nv_bfloat16 l0 = __float2bfloat16_rn(r0), l1 = __float2bfloat16_rn(r1);
    h = (unsigned)__bfloat16_as_ushort(h0) | ((unsigned)__bfloat16_as_ushort(h1) << 16);
    l = (unsigned)__bfloat16_as_ushort(l0) | ((unsigned)__bfloat16_as_ushort(l1) << 16);
}

#define MMA_BF16(C, A0, A1, A2, A3, B0, B1)                                      \
    asm volatile("mma.sync.aligned.m16n8k16.row.col.f32.bf16.bf16.f32 "          \
                 "{%0,%1,%2,%3}, {%4,%5,%6,%7}, {%8,%9}, {%0,%1,%2,%3};\n"       \
                 : "+f"((C)[0]), "+f"((C)[1]), "+f"((C)[2]), "+f"((C)[3])        \
                 : "r"(A0), "r"(A1), "r"(A2), "r"(A3), "r"(B0), "r"(B1))

// ---------------- setup: prepW both layers + ve + zero deg/stats ----------------
// blocks 0..255 -> prepW(W1,K=64,l0); 256..511 -> prepW(W2,K=256,l1); 512 -> ve+stats0
// blocks 0..195 additionally zero g_deg.
__global__ void k_setup(const float* __restrict__ We1, const float* __restrict__ at1,
                        const float* __restrict__ We2, const float* __restrict__ at2,
                        const float* __restrict__ W1, const float* __restrict__ W2) {
    int b = blockIdx.x;
    int t = threadIdx.x;
    int zi = b * 256 + t;
    if (zi < NN) g_deg[zi] = 0;
    if (b == 512) {
        #pragma unroll
        for (int j = 0; j < 4; j++) g_stats[t + 256 * j] = 0.f;
        if (t < 128) {
            int which = t >> 6;
            int u = t & 63;
            int j = u >> 2, h = u & 3;
            const float* We = which ? We2 : We1;
            const float* at = which ? at2 : at1;
            float s = 0.f;
            #pragma unroll 8
            for (int c = 0; c < 64; c++) s += We[j * HC + h * 64 + c] * at[h * 64 + c];
            if (which) g_ve2[u] = s; else g_ve1[u] = s;
        }
        return;
    }
    int layer = (b >= 256) ? 1 : 0;
    int n = layer ? (b - 256) : b;
    int K = layer ? 256 : 64;
    const float* W = layer ? W2 : W1;
    if (t >= K) return;
    float x = W[(size_t)t * 256 + n];
    __nv_bfloat16 h = __float2bfloat16_rn(x);
    float lo = x - __bfloat162float(h);
    __nv_bfloat16 l = __float2bfloat16_rn(lo);
    g_WtH[layer][n * K + t] = __bfloat16_as_ushort(h);
    g_WtL[layer][n * K + t] = __bfloat16_as_ushort(l);
}

// degree histogram only (dst reads, 3.2 MB)
__global__ void k_deg(const int* __restrict__ dst) {
    int e = blockIdx.x * blockDim.x + threadIdx.x;
    if (e < EE) atomicAdd(&g_deg[dst[e]], 1);
}

// ------------- 3-kernel exclusive scan of deg -> offs, cursor -------------
__global__ void k_scan1() {
    __shared__ int sh[256];
    int b = blockIdx.x, t = threadIdx.x;
    int i = b * 256 + t;
    sh[t] = (i < NN) ? g_deg[i] : 0;
    __syncthreads();
    for (int o = 128; o; o >>= 1) { if (t < o) sh[t] += sh[t + o]; __syncthreads(); }
    if (t == 0) g_bsum[b] = sh[0];
}

__global__ void k_scan2(int nb) {
    __shared__ int sh[256];
    int t = threadIdx.x;
    sh[t] = (t < nb) ? g_bsum[t] : 0;
    __syncthreads();
    for (int o = 1; o < 256; o <<= 1) {
        int v = (t >= o) ? sh[t - o] : 0;
        __syncthreads();
        sh[t] += v;
        __syncthreads();
    }
    g_bbase[t + 1] = sh[t];
    if (t == 0) { g_bbase[0] = 0; g_offs[NN] = EE; }
}

__global__ void k_scan3() {
    __shared__ int sh[256];
    int b = blockIdx.x, t = threadIdx.x;
    int i = b * 256 + t;
    int d = (i < NN) ? g_deg[i] : 0;
    sh[t] = d;
    __syncthreads();
    for (int o = 1; o < 256; o <<= 1) {
        int v = (t >= o) ? sh[t - o] : 0;
        __syncthreads();
        sh[t] += v;
        __syncthreads();
    }
    if (i < NN) {
        int off = g_bbase[b] + sh[t] - d;
        g_offs[i] = off;
        g_cursor[i] = off;
    }
}

// per-edge a_e for both layers, scattered DIRECTLY to CSR position
__global__ void k_edge(const float* __restrict__ eattr, const int* __restrict__ src,
                       const int* __restrict__ dst) {
    int e = blockIdx.x * blockDim.x + threadIdx.x;
    if (e >= EE) return;
    const float4* p = (const float4*)(eattr + (size_t)e * 16);
    float4 a = p[0], b = p[1], c = p[2], d = p[3];
    float v[16] = {a.x,a.y,a.z,a.w, b.x,b.y,b.z,b.w, c.x,c.y,c.z,c.w, d.x,d.y,d.z,d.w};
    float o1[4] = {0,0,0,0}, o2[4] = {0,0,0,0};
    #pragma unroll
    for (int j = 0; j < 16; j++) {
        #pragma unroll
        for (int h = 0; h < 4; h++) {
            o1[h] += v[j] * g_ve1[j * 4 + h];
            o2[h] += v[j] * g_ve2[j * 4 + h];
        }
    }
    int pos = atomicAdd(&g_cursor[dst[e]], 1);
    g_csrc[pos] = src[e];
    *(float4*)(g_ae1c + (size_t)pos * 4) = make_float4(o1[0], o1[1], o1[2], o1[3]);
    *(float4*)(g_ae2c + (size_t)pos * 4) = make_float4(o2[0], o2[1], o2[2], o2[3]);
}

// ---------------- tensor-core GEMM: C[M,256] = A[M,K] @ W, bf16 3-term split ----
// BM=128 BN=128 BK=16, 8 warps (2m x 4n), warp tile 64x32, mma m16n8k16.
// smem: 8 words/row, k-pair-permuted units + XOR swizzle; frag loads LDS.64.
// Double buffered. Fused: BN-prep+BN-ReLU on A (layer2), attdot epilogue, fp16 C.
__global__ void __launch_bounds__(256, 2)
k_gemm(const float* __restrict__ Aext, int M, int K, int layer, int bnflag,
       const float* __restrict__ atts, const float* __restrict__ attd,
       const float* __restrict__ bng, const float* __restrict__ bnbe) {
    const float* A = Aext ? Aext : g_hpre;
    __shared__ unsigned sAh[2][1024], sAl[2][1024];   // 128 rows x 8 words
    __shared__ unsigned sBh[2][1024], sBl[2][1024];   // 32 KB
    __shared__ float s_bnsc[256], s_bnsh[256];
    int tid = threadIdx.x;
    int lane = tid & 31, wid = tid >> 5;
    int wm = (wid >> 2) * 64, wn = (wid & 3) * 32;
    int rowBlk = blockIdx.y * 128, colBlk = blockIdx.x * 128;

    // fused BN-prep (layer2): per-CTA compute of per-column scale/shift from stats
    if (bnflag) {
        const float invN = 1.0f / NN;
        float mu = g_stats[tid] * invN;
        float var = g_stats[256 + tid] * invN - mu * mu;
        float scv = bng[tid] * rsqrtf(var + 1e-5f);
        s_bnsc[tid] = scv;
        s_bnsh[tid] = bnbe[tid] - scv * mu;
        __syncthreads();
    }

    int ar = tid >> 1;
    int sel = tid & 1;
    bool aval = (rowBlk + ar) < M;
    const float* Ap = A + (size_t)(rowBlk + ar) * K + sel * 4;
    int bn_ = tid & 127;
    int bsel = tid >> 7;
    const unsigned short* Bp =
        (bsel ? g_WtL[layer] : g_WtH[layer]) + (size_t)(colBlk + bn_) * K;

    float c[4][4][4];
    #pragma unroll
    for (int mt = 0; mt < 4; mt++)
        #pragma unroll
        for (int nt = 0; nt < 4; nt++)
            #pragma unroll
            for (int q = 0; q < 4; q++) c[mt][nt][q] = 0.f;

    int nch = K >> 4;
    float4 fu, fv;
    uint4 bq0, bq1;

    auto loadChunk = [&](int ch) {
        const float* Ap2 = Ap + ch * 16;
        fu = aval ? *(const float4*)(Ap2) : make_float4(0, 0, 0, 0);
        fv = aval ? *(const float4*)(Ap2 + 8) : make_float4(0, 0, 0, 0);
        if (bnflag && aval) {
            int kk = ch * 16 + sel * 4;
            float4 sc0 = *(const float4*)(s_bnsc + kk);
            float4 sh0 = *(const float4*)(s_bnsh + kk);
            float4 sc1 = *(const float4*)(s_bnsc + kk + 8);
            float4 sh1 = *(const float4*)(s_bnsh + kk + 8);
            fu.x = fmaxf(fmaf(sc0.x, fu.x, sh0.x), 0.f);
            fu.y = fmaxf(fmaf(sc0.y, fu.y, sh0.y), 0.f);
            fu.z = fmaxf(fmaf(sc0.z, fu.z, sh0.z), 0.f);
            fu.w = fmaxf(fmaf(sc0.w, fu.w, sh0.w), 0.f);
            fv.x = fmaxf(fmaf(sc1.x, fv.x, sh1.x), 0.f);
            fv.y = fmaxf(fmaf(sc1.y, fv.y, sh1.y), 0.f);
            fv.z = fmaxf(fmaf(sc1.z, fv.z, sh1.z), 0.f);
            fv.w = fmaxf(fmaf(sc1.w, fv.w, sh1.w), 0.f);
        }
        const uint4* Bc = (const uint4*)(Bp + ch * 16);
        bq0 = Bc[0];
        bq1 = Bc[1];
    };
    auto stage = [&](int nb) {
        unsigned w0, w1, w2, w3, l0, l1, l2, l3;
        split_pk(fu.x, fu.y, w0, l0);
        split_pk(fv.x, fv.y, w1, l1);
        split_pk(fu.z, fu.w, w2, l2);
        split_pk(fv.z, fv.w, w3, l3);
        int s = ar & 3;
        int addr = ar * 8 + ((((2 * sel) ^ s) & ~1) << 1);
        if (s & 1) {
            *(uint4*)(&sAh[nb][addr]) = make_uint4(w2, w3, w0, w1);
            *(uint4*)(&sAl[nb][addr]) = make_uint4(l2, l3, l0, l1);
        } else {
            *(uint4*)(&sAh[nb][addr]) = make_uint4(w0, w1, w2, w3);
            *(uint4*)(&sAl[nb][addr]) = make_uint4(l0, l1, l2, l3);
        }
        unsigned* sB = bsel ? sBl[nb] : sBh[nb];
        int t = bn_ & 3;
        uint4 W0 = make_uint4(bq0.x, bq1.x, bq0.y, bq1.y);
        uint4 W1 = make_uint4(bq0.z, bq1.z, bq0.w, bq1.w);
        if (t & 1) {
            W0 = make_uint4(W0.z, W0.w, W0.x, W0.y);
            W1 = make_uint4(W1.z, W1.w, W1.x, W1.y);
        }
        int a0 = bn_ * 8 + (((0 ^ t) & ~1) << 1);
        int a1 = bn_ * 8 + (((2 ^ t) & ~1) << 1);
        *(uint4*)(sB + a0) = W0;
        *(uint4*)(sB + a1) = W1;
    };

    loadChunk(0);
    stage(0);
    __syncthreads();

    for (int ch = 0; ch < nch; ch++) {
        int cur = ch & 1;
        if (ch + 1 < nch) loadChunk(ch + 1);
        uint2 bh[4], bl[4];
        #pragma unroll
        for (int nt = 0; nt < 4; nt++) {
            int n = wn + nt * 8 + (lane >> 2);
            int off = n * 8 + ((((lane & 3) ^ (n & 3)) & 3) * 2);
            bh[nt] = *(const uint2*)(&sBh[cur][off]);
            bl[nt] = *(const uint2*)(&sBl[cur][off]);
        }
        #pragma unroll
        for (int mt = 0; mt < 4; mt++) {
            int r = wm + mt * 16 + (lane >> 2);
            int uoff = (((lane & 3) ^ (r & 3)) & 3) * 2;
            uint2 h0 = *(const uint2*)(&sAh[cur][r * 8 + uoff]);
            uint2 h1 = *(const uint2*)(&sAh[cur][(r + 8) * 8 + uoff]);
            uint2 q0 = *(const uint2*)(&sAl[cur][r * 8 + uoff]);
            uint2 q1 = *(const uint2*)(&sAl[cur][(r + 8) * 8 + uoff]);
            #pragma unroll
            for (int nt = 0; nt < 4; nt++) {
                MMA_BF16(c[mt][nt], h0.x, h1.x, h0.y, h1.y, bh[nt].x, bh[nt].y);
                MMA_BF16(c[mt][nt], h0.x, h1.x, h0.y, h1.y, bl[nt].x, bl[nt].y);
                MMA_BF16(c[mt][nt], q0.x, q1.x, q0.y, q1.y, bh[nt].x, bh[nt].y);
            }
        }
        if (ch + 1 < nch) stage(cur ^ 1);
        __syncthreads();
    }

    // epilogue: write C as fp16 (only consumer is the agg gather)
    #pragma unroll
    for (int mt = 0; mt < 4; mt++) {
        int r0 = rowBlk + wm + mt * 16 + (lane >> 2);
        #pragma unroll
        for (int nt = 0; nt < 4; nt++) {
            int col = colBlk + wn + nt * 8 + (lane & 3) * 2;
            if (r0 < M)
                *(__half2*)(g_xsh + (size_t)r0 * 256 + col) =
                    __floats2half2_rn(c[mt][nt][0], c[mt][nt][1]);
            if (r0 + 8 < M)
                *(__half2*)(g_xsh + (size_t)(r0 + 8) * 256 + col) =
                    __floats2half2_rn(c[mt][nt][2], c[mt][nt][3]);
        }
    }
    // fused attdot
    float2* sred = reinterpret_cast<float2*>(&sAh[0][0]);   // [4][128] = 4KB
    float sv[4][2], dv[4][2];
    #pragma unroll
    for (int nt = 0; nt < 4; nt++)
        #pragma unroll
        for (int q = 0; q < 2; q++) {
            int col = colBlk + wn + nt * 8 + (lane & 3) * 2 + q;
            sv[nt][q] = atts[col];
            dv[nt][q] = attd[col];
        }
    #pragma unroll
    for (int mt = 0; mt < 4; mt++) {
        #pragma unroll
        for (int half = 0; half < 2; half++) {
            float ss = 0.f, dd = 0.f;
            #pragma unroll
            for (int nt = 0; nt < 4; nt++) {
                #pragma unroll
                for (int q = 0; q < 2; q++) {
                    ss = fmaf(c[mt][nt][half * 2 + q], sv[nt][q], ss);
                    dd = fmaf(c[mt][nt][half * 2 + q], dv[nt][q], dd);
                }
            }
            ss += __shfl_xor_sync(0xffffffffu, ss, 1);
            ss += __shfl_xor_sync(0xffffffffu, ss, 2);
            dd += __shfl_xor_sync(0xffffffffu, dd, 1);
            dd += __shfl_xor_sync(0xffffffffu, dd, 2);
            if ((lane & 3) == 0)
                sred[(wid & 3) * 128 + wm + mt * 16 + half * 8 + (lane >> 2)] =
                    make_float2(ss, dd);
        }
    }
    __syncthreads();
    {
        int row = tid >> 1, hl = tid & 1;
        int r = rowBlk + row;
        if (r < M) {
            float2 aa = sred[2 * hl * 128 + row], bb = sred[(2 * hl + 1) * 128 + row];
            int hidx = (colBlk >> 6) + hl;
            g_as[r * 4 + hidx] = aa.x + bb.x;
            g_ad[r * 4 + hidx] = aa.y + bb.y;
        }
    }
}

// ---------------- GAT aggregation: single pass, warp per dst node.
// fp16 row gather: one LDG.128 per edge per lane; fp32 accumulation. --------
__global__ void __launch_bounds__(256) k_agg(int layer, const float* __restrict__ bias) {
    __shared__ float4 sp[8][32];
    __shared__ int    si[8][32];
    int w = (blockIdx.x * blockDim.x + threadIdx.x) >> 5;
    if (w >= NN) return;
    int lane = threadIdx.x & 31;
    int wrp = threadIdx.x >> 5;
    const float4* aeC = (const float4*)(layer ? g_ae2c : g_ae1c);
    int beg = g_offs[w], end = g_offs[w + 1];
    float4 adv = *(const float4*)(g_ad + (size_t)w * 4);
    int h = lane >> 3;
    int f0 = lane * 8;
    float acc[8] = {0, 0, 0, 0, 0, 0, 0, 0};
    float den0 = 0, den1 = 0, den2 = 0, den3 = 0;
    float sa0 = 0, sa1 = 0, sa2 = 0, sa3 = 0;

    for (int base = beg; base < end; base += 32) {
        int i = base + lane;
        float p0 = 0, p1 = 0, p2 = 0, p3 = 0;
        int s = 0;
        if (i < end) {
            s = g_csrc[i];
            float4 ae = aeC[i];
            float4 as = *(const float4*)(g_as + (size_t)s * 4);
            sa0 += ae.x; sa1 += ae.y; sa2 += ae.z; sa3 += ae.w;
            p0 = __expf(lrelu(as.x + adv.x + ae.x));
            p1 = __expf(lrelu(as.y + adv.y + ae.y));
            p2 = __expf(lrelu(as.z + adv.z + ae.z));
            p3 = __expf(lrelu(as.w + adv.w + ae.w));
            den0 += p0; den1 += p1; den2 += p2; den3 += p3;
        }
        sp[wrp][lane] = make_float4(p0, p1, p2, p3);
        si[wrp][lane] = s;
        __syncwarp();
        int cnt = min(32, end - base);
        #pragma unroll 4
        for (int jj = 0; jj < cnt; jj++) {
            int ss = si[wrp][jj];
            float q = ((const float*)&sp[wrp][jj])[h];
            uint4 xv = *(const uint4*)(g_xsh + (size_t)ss * HC + f0);
            float2 x0 = __half22float2(*(__half2*)&xv.x);
            float2 x1 = __half22float2(*(__half2*)&xv.y);
            float2 x2 = __half22float2(*(__half2*)&xv.z);
            float2 x3 = __half22float2(*(__half2*)&xv.w);
            acc[0] = fmaf(q, x0.x, acc[0]); acc[1] = fmaf(q, x0.y, acc[1]);
            acc[2] = fmaf(q, x1.x, acc[2]); acc[3] = fmaf(q, x1.y, acc[3]);
            acc[4] = fmaf(q, x2.x, acc[4]); acc[5] = fmaf(q, x2.y, acc[5]);
            acc[6] = fmaf(q, x3.x, acc[6]); acc[7] = fmaf(q, x3.y, acc[7]);
        }
        __syncwarp();
    }
    #pragma unroll
    for (int o = 16; o; o >>= 1) {
        den0 += __shfl_xor_sync(0xffffffffu, den0, o);
        den1 += __shfl_xor_sync(0xffffffffu, den1, o);
        den2 += __shfl_xor_sync(0xffffffffu, den2, o);
        den3 += __shfl_xor_sync(0xffffffffu, den3, o);
        sa0 += __shfl_xor_sync(0xffffffffu, sa0, o);
        sa1 += __shfl_xor_sync(0xffffffffu, sa1, o);
        sa2 += __shfl_xor_sync(0xffffffffu, sa2, o);
        sa3 += __shfl_xor_sync(0xffffffffu, sa3, o);
    }
    int deg = end - beg;
    float invd = 1.0f / fmaxf((float)deg, 1.0f);
    float4 asn = *(const float4*)(g_as + (size_t)w * 4);
    float ps0 = __expf(lrelu(asn.x + adv.x + sa0 * invd));
    float ps1 = __expf(lrelu(asn.y + adv.y + sa1 * invd));
    float ps2 = __expf(lrelu(asn.z + adv.z + sa2 * invd));
    float ps3 = __expf(lrelu(asn.w + adv.w + sa3 * invd));
    den0 += ps0 + 1e-16f; den1 += ps1 + 1e-16f;
    den2 += ps2 + 1e-16f; den3 += ps3 + 1e-16f;
    {
        uint4 xv = *(const uint4*)(g_xsh + (size_t)w * HC + f0);
        float2 x0 = __half22float2(*(__half2*)&xv.x);
        float2 x1 = __half22float2(*(__half2*)&xv.y);
        float2 x2 = __half22float2(*(__half2*)&xv.z);
        float2 x3 = __half22float2(*(__half2*)&xv.w);
        float psh = (h == 0) ? ps0 : (h == 1) ? ps1 : (h == 2) ? ps2 : ps3;
        acc[0] = fmaf(psh, x0.x, acc[0]); acc[1] = fmaf(psh, x0.y, acc[1]);
        acc[2] = fmaf(psh, x1.x, acc[2]); acc[3] = fmaf(psh, x1.y, acc[3]);
        acc[4] = fmaf(psh, x2.x, acc[4]); acc[5] = fmaf(psh, x2.y, acc[5]);
        acc[6] = fmaf(psh, x3.x, acc[6]); acc[7] = fmaf(psh, x3.y, acc[7]);
    }
    float denh = (h == 0) ? den0 : (h == 1) ? den1 : (h == 2) ? den2 : den3;
    float r = 1.0f / denh;
    float4 b0 = *(const float4*)(bias + f0);
    float4 b1 = *(const float4*)(bias + f0 + 4);
    float* op = g_hpre + (size_t)w * HC + f0;
    *(float4*)(op)     = make_float4(fmaf(acc[0], r, b0.x), fmaf(acc[1], r, b0.y),
                                     fmaf(acc[2], r, b0.z), fmaf(acc[3], r, b0.w));
    *(float4*)(op + 4) = make_float4(fmaf(acc[4], r, b1.x), fmaf(acc[5], r, b1.y),
                                     fmaf(acc[6], r, b1.z), fmaf(acc[7], r, b1.w));
}

// ---------------- BN batch stats (sum, sumsq per column) ----------------
__global__ void k_stats(int off) {
    int c = threadIdx.x;    // 256
    int rows = (NN + gridDim.x - 1) / gridDim.x;
    int r0 = blockIdx.x * rows, r1 = min(r0 + rows, NN);
    float s = 0.f, s2 = 0.f;
    for (int r = r0; r < r1; r++) {
        float v = g_hpre[(size_t)r * HC + c];
        s += v;
        s2 = fmaf(v, v, s2);
    }
    atomicAdd(&g_stats[off + c], s);
    atomicAdd(&g_stats[off + 256 + c], s2);
}

// ---------------- final: out[n] = relu(BN(hpre2)) . wout + bout ----------------
__global__ void k_final(const float* __restrict__ g, const float* __restrict__ be,
                        const float* __restrict__ wout, const float* __restrict__ bout,
                        float* __restrict__ out) {
    int w = (blockIdx.x * blockDim.x + threadIdx.x) >> 5;
    if (w >= NN) return;
    int lane = threadIdx.x & 31;
    const float invN = 1.0f / NN;
    float s = 0.f;
    #pragma unroll
    for (int j = 0; j < 8; j++) {
        int f = lane + 32 * j;
        float mu = g_stats[512 + f] * invN;
        float var = g_stats[768 + f] * invN - mu * mu;
        float sc = g[f] * rsqrtf(var + 1e-5f);
        float v = fmaxf(sc * (g_hpre[(size_t)w * HC + f] - mu) + be[f], 0.f);
        s = fmaf(v, wout[f], s);
    }
    #pragma unroll
    for (int o = 16; o; o >>= 1) s += __shfl_xor_sync(0xffffffffu, s, o);
    if (lane == 0) out[w] = s + bout[0];
}

// ---------------- stream fork/join resources (created once, OUTSIDE capture:
// the harness's correctness call precedes graph capture; no device memory) -----
struct ForkRes {
    cudaStream_t side;
    cudaEvent_t evFork, evJoin;
    ForkRes() {
        cudaStreamCreateWithFlags(&side, cudaStreamNonBlocking);
        cudaEventCreateWithFlags(&evFork, cudaEventDisableTiming);
        cudaEventCreateWithFlags(&evJoin, cudaEventDisableTiming);
    }
};

// ---------------- launch ----------------
extern "C" void kernel_launch(void* const* d_in, const int* in_sizes, int n_in,
                              void* d_out, int out_size) {
    const float* x     = (const float*)d_in[0];
    const int*   esrc  = (const int*)d_in[1];
    const int*   edst  = (const int*)d_in[2];
    const float* eattr = (const float*)d_in[3];
    const float* W1    = (const float*)d_in[4];
    const float* atts1 = (const float*)d_in[5];
    const float* attd1 = (const float*)d_in[6];
    const float* We1   = (const float*)d_in[7];
    const float* atte1 = (const float*)d_in[8];
    const float* b1    = (const float*)d_in[9];
    const float* g1    = (const float*)d_in[10];
    const float* be1   = (const float*)d_in[11];
    const float* W2    = (const float*)d_in[12];
    const float* atts2 = (const float*)d_in[13];
    const float* attd2 = (const float*)d_in[14];
    const float* We2   = (const float*)d_in[15];
    const float* atte2 = (const float*)d_in[16];
    const float* b2    = (const float*)d_in[17];
    const float* g2    = (const float*)d_in[18];
    const float* be2   = (const float*)d_in[19];
    const float* Wout  = (const float*)d_in[20];
    const float* bout  = (const float*)d_in[21];
    float* out = (float*)d_out;

    static ForkRes fr;      // created on first (correctness) call, pre-capture

    const int EB = (EE + 255) / 256;
    const int NB = (NN + 255) / 256;
    const int WB = NN / 8;                 // warp-per-node kernels (256 thr)
    dim3 gg(2, (NN + 127) / 128);

    // main stream: setup (prepW + ve + zero), then fork
    k_setup<<<513, 256>>>(We1, atte1, We2, atte2, W1, W2);      // 1
    cudaEventRecord(fr.evFork, 0);
    cudaStreamWaitEvent(fr.side, fr.evFork, 0);

    // side stream: CSR build chain; main: GEMM1 concurrently
    k_deg<<<EB, 256, 0, fr.side>>>(edst);                       // 2
    k_scan1<<<NB, 256, 0, fr.side>>>();                         // 3
    k_gemm<<<gg, 256>>>(x, NN, 64, 0, 0, atts1, attd1,
                        nullptr, nullptr);                      // 4  <- profiled
    k_scan2<<<1, 256, 0, fr.side>>>(NB);                        // 5
    k_scan3<<<NB, 256, 0, fr.side>>>();                         // 6
    k_edge<<<EB, 256, 0, fr.side>>>(eattr, esrc, edst);         // 7
    cudaEventRecord(fr.evJoin, fr.side);
    cudaStreamWaitEvent(0, fr.evJoin, 0);

    // layer 1 (needs gemm1 + CSR)
    k_agg<<<WB, 256>>>(0, b1);                                  // 8
    k_stats<<<256, 256>>>(0);                                   // 9

    // layer 2 (BN-prep + BN-ReLU of layer1 fused into GEMM)
    k_gemm<<<gg, 256>>>(nullptr, NN, 256, 1, 1, atts2, attd2,
                        g1, be1);                               // 10
    k_agg<<<WB, 256>>>(1, b2);                                  // 11
    k_stats<<<256, 256>>>(512);                                 // 12

    // output head
    k_final<<<WB, 256>>>(g2, be2, Wout, bout, out);             // 13
}

// round 12
// speedup vs baseline: 1.4709x; 1.0468x over previous
#include <cuda_runtime.h>
#include <cuda_bf16.h>
#include <cuda_fp16.h>

#define NN 50000
#define EE 800000
#define HC 256

// ---------------- scratch (device globals; no allocation allowed) ----------------
__device__ __align__(16) __half g_xsh[NN * HC];   // xs of current layer, fp16
__device__ __align__(16) __half g_hpreh[NN * HC]; // aggregated pre-BN output, fp16
__device__ float g_as[NN * 4];
__device__ float g_ad[NN * 4];
__device__ float g_ae1c[EE * 4];    // a_e layer1, CSR order
__device__ float g_ae2c[EE * 4];    // a_e layer2, CSR order
__device__ int   g_epos[EE];        // edge -> CSR position (edge1 -> edge2)
__device__ int   g_deg[NN];
__device__ int   g_offs[NN + 1];
__device__ int   g_cursor[NN];
__device__ int   g_bsum[256];
__device__ int   g_bbase[257];
__device__ int   g_csrc[EE];
__device__ float g_ve1[64];         // [16,4]
__device__ float g_ve2[64];
__device__ float g_stats[1024];     // layer1: [0,512), layer2: [512,1024)
// W pre-transposed [n][k], bf16 hi/lo planes, per layer
__device__ __align__(16) unsigned short g_WtH[2][256 * 256];
__device__ __align__(16) unsigned short g_WtL[2][256 * 256];

__device__ __forceinline__ float lrelu(float x) { return fmaxf(x, 0.2f * x); }

__device__ __forceinline__ void split_pk(float x0, float x1, unsigned& h, unsigned& l) {
    __nv_bfloat16 h0 = __float2bfloat16_rn(x0), h1 = __float2bfloat16_rn(x1);
    float r0 = x0 - __bfloat162float(h0), r1 = x1 - __bfloat162float(h1);
    __nv_bfloat16 l0 = __float2bfloat16_rn(r0), l1 = __float2bfloat16_rn(r1);
    h = (unsigned)__bfloat16_as_ushort(h0) | ((unsigned)__bfloat16_as_ushort(h1) << 16);
    l = (unsigned)__bfloat16_as_ushort(l0) | ((unsigned)__bfloat16_as_ushort(l1) << 16);
}

#define MMA_BF16(C, A0, A1, A2, A3, B0, B1)                                      \
    asm volatile("mma.sync.aligned.m16n8k16.row.col.f32.bf16.bf16.f32 "          \
                 "{%0,%1,%2,%3}, {%4,%5,%6,%7}, {%8,%9}, {%0,%1,%2,%3};\n"       \
                 : "+f"((C)[0]), "+f"((C)[1]), "+f"((C)[2]), "+f"((C)[3])        \
                 : "r"(A0), "r"(A1), "r"(A2), "r"(A3), "r"(B0), "r"(B1))

// ---------------- setup: prepW both layers + ve + zero deg/stats ----------------
__global__ void k_setup(const float* __restrict__ We1, const float* __restrict__ at1,
                        const float* __restrict__ We2, const float* __restrict__ at2,
                        const float* __restrict__ W1, const float* __restrict__ W2) {
    int b = blockIdx.x;
    int t = threadIdx.x;
    int zi = b * 256 + t;
    if (zi < NN) g_deg[zi] = 0;
    if (b == 512) {
        #pragma unroll
        for (int j = 0; j < 4; j++) g_stats[t + 256 * j] = 0.f;
        if (t < 128) {
            int which = t >> 6;
            int u = t & 63;
            int j = u >> 2, h = u & 3;
            const float* We = which ? We2 : We1;
            const float* at = which ? at2 : at1;
            float s = 0.f;
            #pragma unroll 8
            for (int c = 0; c < 64; c++) s += We[j * HC + h * 64 + c] * at[h * 64 + c];
            if (which) g_ve2[u] = s; else g_ve1[u] = s;
        }
        return;
    }
    int layer = (b >= 256) ? 1 : 0;
    int n = layer ? (b - 256) : b;
    int K = layer ? 256 : 64;
    const float* W = layer ? W2 : W1;
    if (t >= K) return;
    float x = W[(size_t)t * 256 + n];
    __nv_bfloat16 h = __float2bfloat16_rn(x);
    float lo = x - __bfloat162float(h);
    __nv_bfloat16 l = __float2bfloat16_rn(lo);
    g_WtH[layer][n * K + t] = __bfloat16_as_ushort(h);
    g_WtL[layer][n * K + t] = __bfloat16_as_ushort(l);
}

// degree histogram only (dst reads, 3.2 MB)
__global__ void k_deg(const int* __restrict__ dst) {
    int e = blockIdx.x * blockDim.x + threadIdx.x;
    if (e < EE) atomicAdd(&g_deg[dst[e]], 1);
}

// ------------- 3-kernel exclusive scan of deg -> offs, cursor -------------
__global__ void k_scan1() {
    __shared__ int sh[256];
    int b = blockIdx.x, t = threadIdx.x;
    int i = b * 256 + t;
    sh[t] = (i < NN) ? g_deg[i] : 0;
    __syncthreads();
    for (int o = 128; o; o >>= 1) { if (t < o) sh[t] += sh[t + o]; __syncthreads(); }
    if (t == 0) g_bsum[b] = sh[0];
}

__global__ void k_scan2(int nb) {
    __shared__ int sh[256];
    int t = threadIdx.x;
    sh[t] = (t < nb) ? g_bsum[t] : 0;
    __syncthreads();
    for (int o = 1; o < 256; o <<= 1) {
        int v = (t >= o) ? sh[t - o] : 0;
        __syncthreads();
        sh[t] += v;
        __syncthreads();
    }
    g_bbase[t + 1] = sh[t];
    if (t == 0) { g_bbase[0] = 0; g_offs[NN] = EE; }
}

__global__ void k_scan3() {
    __shared__ int sh[256];
    int b = blockIdx.x, t = threadIdx.x;
    int i = b * 256 + t;
    int d = (i < NN) ? g_deg[i] : 0;
    sh[t] = d;
    __syncthreads();
    for (int o = 1; o < 256; o <<= 1) {
        int v = (t >= o) ? sh[t - o] : 0;
        __syncthreads();
        sh[t] += v;
        __syncthreads();
    }
    if (i < NN) {
        int off = g_bbase[b] + sh[t] - d;
        g_offs[i] = off;
        g_cursor[i] = off;
    }
}

// edge1 (join-critical): layer-1 a_e + CSR src + saved position
__global__ void k_edge1(const float* __restrict__ eattr, const int* __restrict__ src,
                        const int* __restrict__ dst) {
    int e = blockIdx.x * blockDim.x + threadIdx.x;
    if (e >= EE) return;
    const float4* p = (const float4*)(eattr + (size_t)e * 16);
    float4 a = p[0], b = p[1], c = p[2], d = p[3];
    float v[16] = {a.x,a.y,a.z,a.w, b.x,b.y,b.z,b.w, c.x,c.y,c.z,c.w, d.x,d.y,d.z,d.w};
    float o1[4] = {0, 0, 0, 0};
    #pragma unroll
    for (int j = 0; j < 16; j++)
        #pragma unroll
        for (int h = 0; h < 4; h++) o1[h] += v[j] * g_ve1[j * 4 + h];
    int pos = atomicAdd(&g_cursor[dst[e]], 1);
    g_csrc[pos] = src[e];
    g_epos[e] = pos;
    *(float4*)(g_ae1c + (size_t)pos * 4) = make_float4(o1[0], o1[1], o1[2], o1[3]);
}

// edge2 (deferred, overlaps agg1/stats/gemm2): layer-2 a_e into CSR order
__global__ void k_edge2(const float* __restrict__ eattr) {
    int e = blockIdx.x * blockDim.x + threadIdx.x;
    if (e >= EE) return;
    const float4* p = (const float4*)(eattr + (size_t)e * 16);
    float4 a = p[0], b = p[1], c = p[2], d = p[3];
    float v[16] = {a.x,a.y,a.z,a.w, b.x,b.y,b.z,b.w, c.x,c.y,c.z,c.w, d.x,d.y,d.z,d.w};
    float o2[4] = {0, 0, 0, 0};
    #pragma unroll
    for (int j = 0; j < 16; j++)
        #pragma unroll
        for (int h = 0; h < 4; h++) o2[h] += v[j] * g_ve2[j * 4 + h];
    int pos = g_epos[e];
    *(float4*)(g_ae2c + (size_t)pos * 4) = make_float4(o2[0], o2[1], o2[2], o2[3]);
}

// ---------------- tensor-core GEMM: C[M,256] = A[M,K] @ W, bf16 3-term split ----
// A source: external fp32 (layer1) or g_hpreh fp16 (layer2, with fused BN-ReLU).
__global__ void __launch_bounds__(256, 2)
k_gemm(const float* __restrict__ Aext, int M, int K, int layer, int bnflag,
       const float* __restrict__ atts, const float* __restrict__ attd,
       const float* __restrict__ bng, const float* __restrict__ bnbe) {
    __shared__ unsigned sAh[2][1024], sAl[2][1024];   // 128 rows x 8 words
    __shared__ unsigned sBh[2][1024], sBl[2][1024];   // 32 KB
    __shared__ float s_bnsc[256], s_bnsh[256];
    int tid = threadIdx.x;
    int lane = tid & 31, wid = tid >> 5;
    int wm = (wid >> 2) * 64, wn = (wid & 3) * 32;
    int rowBlk = blockIdx.y * 128, colBlk = blockIdx.x * 128;

    if (bnflag) {
        const float invN = 1.0f / NN;
        float mu = g_stats[tid] * invN;
        float var = g_stats[256 + tid] * invN - mu * mu;
        float scv = bng[tid] * rsqrtf(var + 1e-5f);
        s_bnsc[tid] = scv;
        s_bnsh[tid] = bnbe[tid] - scv * mu;
        __syncthreads();
    }

    int ar = tid >> 1;
    int sel = tid & 1;
    bool aval = (rowBlk + ar) < M;
    const float* Ap = Aext ? (Aext + (size_t)(rowBlk + ar) * K + sel * 4) : nullptr;
    const __half* Aph = g_hpreh + (size_t)(rowBlk + ar) * K + sel * 4;
    int bn_ = tid & 127;
    int bsel = tid >> 7;
    const unsigned short* Bp =
        (bsel ? g_WtL[layer] : g_WtH[layer]) + (size_t)(colBlk + bn_) * K;

    float c[4][4][4];
    #pragma unroll
    for (int mt = 0; mt < 4; mt++)
        #pragma unroll
        for (int nt = 0; nt < 4; nt++)
            #pragma unroll
            for (int q = 0; q < 4; q++) c[mt][nt][q] = 0.f;

    int nch = K >> 4;
    float4 fu, fv;
    uint4 bq0, bq1;

    auto loadChunk = [&](int ch) {
        if (Aext) {
            const float* Ap2 = Ap + ch * 16;
            fu = aval ? *(const float4*)(Ap2) : make_float4(0, 0, 0, 0);
            fv = aval ? *(const float4*)(Ap2 + 8) : make_float4(0, 0, 0, 0);
        } else {
            const __half* Ah2 = Aph + ch * 16;
            uint2 u0 = aval ? *(const uint2*)(Ah2) : make_uint2(0, 0);
            uint2 u1 = aval ? *(const uint2*)(Ah2 + 8) : make_uint2(0, 0);
            float2 p0 = __half22float2(*(__half2*)&u0.x);
            float2 p1 = __half22float2(*(__half2*)&u0.y);
            float2 p2 = __half22float2(*(__half2*)&u1.x);
            float2 p3 = __half22float2(*(__half2*)&u1.y);
            fu = make_float4(p0.x, p0.y, p1.x, p1.y);
            fv = make_float4(p2.x, p2.y, p3.x, p3.y);
        }
        if (bnflag && aval) {
            int kk = ch * 16 + sel * 4;
            float4 sc0 = *(const float4*)(s_bnsc + kk);
            float4 sh0 = *(const float4*)(s_bnsh + kk);
            float4 sc1 = *(const float4*)(s_bnsc + kk + 8);
            float4 sh1 = *(const float4*)(s_bnsh + kk + 8);
            fu.x = fmaxf(fmaf(sc0.x, fu.x, sh0.x), 0.f);
            fu.y = fmaxf(fmaf(sc0.y, fu.y, sh0.y), 0.f);
            fu.z = fmaxf(fmaf(sc0.z, fu.z, sh0.z), 0.f);
            fu.w = fmaxf(fmaf(sc0.w, fu.w, sh0.w), 0.f);
            fv.x = fmaxf(fmaf(sc1.x, fv.x, sh1.x), 0.f);
            fv.y = fmaxf(fmaf(sc1.y, fv.y, sh1.y), 0.f);
            fv.z = fmaxf(fmaf(sc1.z, fv.z, sh1.z), 0.f);
            fv.w = fmaxf(fmaf(sc1.w, fv.w, sh1.w), 0.f);
        }
        const uint4* Bc = (const uint4*)(Bp + ch * 16);
        bq0 = Bc[0];
        bq1 = Bc[1];
    };
    auto stage = [&](int nb) {
        unsigned w0, w1, w2, w3, l0, l1, l2, l3;
        split_pk(fu.x, fu.y, w0, l0);
        split_pk(fv.x, fv.y, w1, l1);
        split_pk(fu.z, fu.w, w2, l2);
        split_pk(fv.z, fv.w, w3, l3);
        int s = ar & 3;
        int addr = ar * 8 + ((((2 * sel) ^ s) & ~1) << 1);
        if (s & 1) {
            *(uint4*)(&sAh[nb][addr]) = make_uint4(w2, w3, w0, w1);
            *(uint4*)(&sAl[nb][addr]) = make_uint4(l2, l3, l0, l1);
        } else {
            *(uint4*)(&sAh[nb][addr]) = make_uint4(w0, w1, w2, w3);
            *(uint4*)(&sAl[nb][addr]) = make_uint4(l0, l1, l2, l3);
        }
        unsigned* sB = bsel ? sBl[nb] : sBh[nb];
        int t = bn_ & 3;
        uint4 W0 = make_uint4(bq0.x, bq1.x, bq0.y, bq1.y);
        uint4 W1 = make_uint4(bq0.z, bq1.z, bq0.w, bq1.w);
        if (t & 1) {
            W0 = make_uint4(W0.z, W0.w, W0.x, W0.y);
            W1 = make_uint4(W1.z, W1.w, W1.x, W1.y);
        }
        int a0 = bn_ * 8 + (((0 ^ t) & ~1) << 1);
        int a1 = bn_ * 8 + (((2 ^ t) & ~1) << 1);
        *(uint4*)(sB + a0) = W0;
        *(uint4*)(sB + a1) = W1;
    };

    loadChunk(0);
    stage(0);
    __syncthreads();

    for (int ch = 0; ch < nch; ch++) {
        int cur = ch & 1;
        if (ch + 1 < nch) loadChunk(ch + 1);
        uint2 bh[4], bl[4];
        #pragma unroll
        for (int nt = 0; nt < 4; nt++) {
            int n = wn + nt * 8 + (lane >> 2);
            int off = n * 8 + ((((lane & 3) ^ (n & 3)) & 3) * 2);
            bh[nt] = *(const uint2*)(&sBh[cur][off]);
            bl[nt] = *(const uint2*)(&sBl[cur][off]);
        }
        #pragma unroll
        for (int mt = 0; mt < 4; mt++) {
            int r = wm + mt * 16 + (lane >> 2);
            int uoff = (((lane & 3) ^ (r & 3)) & 3) * 2;
            uint2 h0 = *(const uint2*)(&sAh[cur][r * 8 + uoff]);
            uint2 h1 = *(const uint2*)(&sAh[cur][(r + 8) * 8 + uoff]);
            uint2 q0 = *(const uint2*)(&sAl[cur][r * 8 + uoff]);
            uint2 q1 = *(const uint2*)(&sAl[cur][(r + 8) * 8 + uoff]);
            #pragma unroll
            for (int nt = 0; nt < 4; nt++) {
                MMA_BF16(c[mt][nt], h0.x, h1.x, h0.y, h1.y, bh[nt].x, bh[nt].y);
                MMA_BF16(c[mt][nt], h0.x, h1.x, h0.y, h1.y, bl[nt].x, bl[nt].y);
                MMA_BF16(c[mt][nt], q0.x, q1.x, q0.y, q1.y, bh[nt].x, bh[nt].y);
            }
        }
        if (ch + 1 < nch) stage(cur ^ 1);
        __syncthreads();
    }

    // epilogue: write C as fp16 (only consumer is the agg gather)
    #pragma unroll
    for (int mt = 0; mt < 4; mt++) {
        int r0 = rowBlk + wm + mt * 16 + (lane >> 2);
        #pragma unroll
        for (int nt = 0; nt < 4; nt++) {
            int col = colBlk + wn + nt * 8 + (lane & 3) * 2;
            if (r0 < M)
                *(__half2*)(g_xsh + (size_t)r0 * 256 + col) =
                    __floats2half2_rn(c[mt][nt][0], c[mt][nt][1]);
            if (r0 + 8 < M)
                *(__half2*)(g_xsh + (size_t)(r0 + 8) * 256 + col) =
                    __floats2half2_rn(c[mt][nt][2], c[mt][nt][3]);
        }
    }
    // fused attdot
    float2* sred = reinterpret_cast<float2*>(&sAh[0][0]);   // [4][128] = 4KB
    float sv[4][2], dv[4][2];
    #pragma unroll
    for (int nt = 0; nt < 4; nt++)
        #pragma unroll
        for (int q = 0; q < 2; q++) {
            int col = colBlk + wn + nt * 8 + (lane & 3) * 2 + q;
            sv[nt][q] = atts[col];
            dv[nt][q] = attd[col];
        }
    #pragma unroll
    for (int mt = 0; mt < 4; mt++) {
        #pragma unroll
        for (int half = 0; half < 2; half++) {
            float ss = 0.f, dd = 0.f;
            #pragma unroll
            for (int nt = 0; nt < 4; nt++) {
                #pragma unroll
                for (int q = 0; q < 2; q++) {
                    ss = fmaf(c[mt][nt][half * 2 + q], sv[nt][q], ss);
                    dd = fmaf(c[mt][nt][half * 2 + q], dv[nt][q], dd);
                }
            }
            ss += __shfl_xor_sync(0xffffffffu, ss, 1);
            ss += __shfl_xor_sync(0xffffffffu, ss, 2);
            dd += __shfl_xor_sync(0xffffffffu, dd, 1);
            dd += __shfl_xor_sync(0xffffffffu, dd, 2);
            if ((lane & 3) == 0)
                sred[(wid & 3) * 128 + wm + mt * 16 + half * 8 + (lane >> 2)] =
                    make_float2(ss, dd);
        }
    }
    __syncthreads();
    {
        int row = tid >> 1, hl = tid & 1;
        int r = rowBlk + row;
        if (r < M) {
            float2 aa = sred[2 * hl * 128 + row], bb = sred[(2 * hl + 1) * 128 + row];
            int hidx = (colBlk >> 6) + hl;
            g_as[r * 4 + hidx] = aa.x + bb.x;
            g_ad[r * 4 + hidx] = aa.y + bb.y;
        }
    }
}

// ---------------- GAT aggregation: single pass, warp per dst node.
// fp16 row gather; fp32 accumulation; fp16 hpre store. --------
__global__ void __launch_bounds__(256) k_agg(int layer, const float* __restrict__ bias) {
    __shared__ float4 sp[8][32];
    __shared__ int    si[8][32];
    int w = (blockIdx.x * blockDim.x + threadIdx.x) >> 5;
    if (w >= NN) return;
    int lane = threadIdx.x & 31;
    int wrp = threadIdx.x >> 5;
    const float4* aeC = (const float4*)(layer ? g_ae2c : g_ae1c);
    int beg = g_offs[w], end = g_offs[w + 1];
    float4 adv = *(const float4*)(g_ad + (size_t)w * 4);
    int h = lane >> 3;
    int f0 = lane * 8;
    float acc[8] = {0, 0, 0, 0, 0, 0, 0, 0};
    float den0 = 0, den1 = 0, den2 = 0, den3 = 0;
    float sa0 = 0, sa1 = 0, sa2 = 0, sa3 = 0;

    for (int base = beg; base < end; base += 32) {
        int i = base + lane;
        float p0 = 0, p1 = 0, p2 = 0, p3 = 0;
        int s = 0;
        if (i < end) {
            s = g_csrc[i];
            float4 ae = aeC[i];
            float4 as = *(const float4*)(g_as + (size_t)s * 4);
            sa0 += ae.x; sa1 += ae.y; sa2 += ae.z; sa3 += ae.w;
            p0 = __expf(lrelu(as.x + adv.x + ae.x));
            p1 = __expf(lrelu(as.y + adv.y + ae.y));
            p2 = __expf(lrelu(as.z + adv.z + ae.z));
            p3 = __expf(lrelu(as.w + adv.w + ae.w));
            den0 += p0; den1 += p1; den2 += p2; den3 += p3;
        }
        sp[wrp][lane] = make_float4(p0, p1, p2, p3);
        si[wrp][lane] = s;
        __syncwarp();
        int cnt = min(32, end - base);
        #pragma unroll 4
        for (int jj = 0; jj < cnt; jj++) {
            int ss = si[wrp][jj];
            float q = ((const float*)&sp[wrp][jj])[h];
            uint4 xv = *(const uint4*)(g_xsh + (size_t)ss * HC + f0);
            float2 x0 = __half22float2(*(__half2*)&xv.x);
            float2 x1 = __half22float2(*(__half2*)&xv.y);
            float2 x2 = __half22float2(*(__half2*)&xv.z);
            float2 x3 = __half22float2(*(__half2*)&xv.w);
            acc[0] = fmaf(q, x0.x, acc[0]); acc[1] = fmaf(q, x0.y, acc[1]);
            acc[2] = fmaf(q, x1.x, acc[2]); acc[3] = fmaf(q, x1.y, acc[3]);
            acc[4] = fmaf(q, x2.x, acc[4]); acc[5] = fmaf(q, x2.y, acc[5]);
            acc[6] = fmaf(q, x3.x, acc[6]); acc[7] = fmaf(q, x3.y, acc[7]);
        }
        __syncwarp();
    }
    #pragma unroll
    for (int o = 16; o; o >>= 1) {
        den0 += __shfl_xor_sync(0xffffffffu, den0, o);
        den1 += __shfl_xor_sync(0xffffffffu, den1, o);
        den2 += __shfl_xor_sync(0xffffffffu, den2, o);
        den3 += __shfl_xor_sync(0xffffffffu, den3, o);
        sa0 += __shfl_xor_sync(0xffffffffu, sa0, o);
        sa1 += __shfl_xor_sync(0xffffffffu, sa1, o);
        sa2 += __shfl_xor_sync(0xffffffffu, sa2, o);
        sa3 += __shfl_xor_sync(0xffffffffu, sa3, o);
    }
    int deg = end - beg;
    float invd = 1.0f / fmaxf((float)deg, 1.0f);
    float4 asn = *(const float4*)(g_as + (size_t)w * 4);
    float ps0 = __expf(lrelu(asn.x + adv.x + sa0 * invd));
    float ps1 = __expf(lrelu(asn.y + adv.y + sa1 * invd));
    float ps2 = __expf(lrelu(asn.z + adv.z + sa2 * invd));
    float ps3 = __expf(lrelu(asn.w + adv.w + sa3 * invd));
    den0 += ps0 + 1e-16f; den1 += ps1 + 1e-16f;
    den2 += ps2 + 1e-16f; den3 += ps3 + 1e-16f;
    {
        uint4 xv = *(const uint4*)(g_xsh + (size_t)w * HC + f0);
        float2 x0 = __half22float2(*(__half2*)&xv.x);
        float2 x1 = __half22float2(*(__half2*)&xv.y);
        float2 x2 = __half22float2(*(__half2*)&xv.z);
        float2 x3 = __half22float2(*(__half2*)&xv.w);
        float psh = (h == 0) ? ps0 : (h == 1) ? ps1 : (h == 2) ? ps2 : ps3;
        acc[0] = fmaf(psh, x0.x, acc[0]); acc[1] = fmaf(psh, x0.y, acc[1]);
        acc[2] = fmaf(psh, x1.x, acc[2]); acc[3] = fmaf(psh, x1.y, acc[3]);
        acc[4] = fmaf(psh, x2.x, acc[4]); acc[5] = fmaf(psh, x2.y, acc[5]);
        acc[6] = fmaf(psh, x3.x, acc[6]); acc[7] = fmaf(psh, x3.y, acc[7]);
    }
    float denh = (h == 0) ? den0 : (h == 1) ? den1 : (h == 2) ? den2 : den3;
    float r = 1.0f / denh;
    float4 b0 = *(const float4*)(bias + f0);
    float4 b1 = *(const float4*)(bias + f0 + 4);
    __half2 o0 = __floats2half2_rn(fmaf(acc[0], r, b0.x), fmaf(acc[1], r, b0.y));
    __half2 o1 = __floats2half2_rn(fmaf(acc[2], r, b0.z), fmaf(acc[3], r, b0.w));
    __half2 o2 = __floats2half2_rn(fmaf(acc[4], r, b1.x), fmaf(acc[5], r, b1.y));
    __half2 o3 = __floats2half2_rn(fmaf(acc[6], r, b1.z), fmaf(acc[7], r, b1.w));
    uint4 pack;
    pack.x = *(unsigned*)&o0; pack.y = *(unsigned*)&o1;
    pack.z = *(unsigned*)&o2; pack.w = *(unsigned*)&o3;
    *(uint4*)(g_hpreh + (size_t)w * HC + f0) = pack;
}

// ---------------- BN batch stats (sum, sumsq per column), fp16 source ----------------
__global__ void k_stats(int off) {
    int c = threadIdx.x;    // 256
    int rows = (NN + gridDim.x - 1) / gridDim.x;
    int r0 = blockIdx.x * rows, r1 = min(r0 + rows, NN);
    float s = 0.f, s2 = 0.f;
    for (int r = r0; r < r1; r++) {
        float v = __half2float(g_hpreh[(size_t)r * HC + c]);
        s += v;
        s2 = fmaf(v, v, s2);
    }
    atomicAdd(&g_stats[off + c], s);
    atomicAdd(&g_stats[off + 256 + c], s2);
}

// ---------------- final: out[n] = relu(BN(hpre2)) . wout + bout ----------------
__global__ void k_final(const float* __restrict__ g, const float* __restrict__ be,
                        const float* __restrict__ wout, const float* __restrict__ bout,
                        float* __restrict__ out) {
    int w = (blockIdx.x * blockDim.x + threadIdx.x) >> 5;
    if (w >= NN) return;
    int lane = threadIdx.x & 31;
    const float invN = 1.0f / NN;
    float s = 0.f;
    #pragma unroll
    for (int j = 0; j < 8; j++) {
        int f = lane + 32 * j;
        float mu = g_stats[512 + f] * invN;
        float var = g_stats[768 + f] * invN - mu * mu;
        float sc = g[f] * rsqrtf(var + 1e-5f);
        float hv = __half2float(g_hpreh[(size_t)w * HC + f]);
        float v = fmaxf(sc * (hv - mu) + be[f], 0.f);
        s = fmaf(v, wout[f], s);
    }
    #pragma unroll
    for (int o = 16; o; o >>= 1) s += __shfl_xor_sync(0xffffffffu, s, o);
    if (lane == 0) out[w] = s + bout[0];
}

// ---------------- stream fork/join resources (created once, OUTSIDE capture) -----
struct ForkRes {
    cudaStream_t side;
    cudaEvent_t evFork, evJoin, evJoin2;
    ForkRes() {
        cudaStreamCreateWithFlags(&side, cudaStreamNonBlocking);
        cudaEventCreateWithFlags(&evFork, cudaEventDisableTiming);
        cudaEventCreateWithFlags(&evJoin, cudaEventDisableTiming);
        cudaEventCreateWithFlags(&evJoin2, cudaEventDisableTiming);
    }
};

// ---------------- launch ----------------
extern "C" void kernel_launch(void* const* d_in, const int* in_sizes, int n_in,
                              void* d_out, int out_size) {
    const float* x     = (const float*)d_in[0];
    const int*   esrc  = (const int*)d_in[1];
    const int*   edst  = (const int*)d_in[2];
    const float* eattr = (const float*)d_in[3];
    const float* W1    = (const float*)d_in[4];
    const float* atts1 = (const float*)d_in[5];
    const float* attd1 = (const float*)d_in[6];
    const float* We1   = (const float*)d_in[7];
    const float* atte1 = (const float*)d_in[8];
    const float* b1    = (const float*)d_in[9];
    const float* g1    = (const float*)d_in[10];
    const float* be1   = (const float*)d_in[11];
    const float* W2    = (const float*)d_in[12];
    const float* atts2 = (const float*)d_in[13];
    const float* attd2 = (const float*)d_in[14];
    const float* We2   = (const float*)d_in[15];
    const float* atte2 = (const float*)d_in[16];
    const float* b2    = (const float*)d_in[17];
    const float* g2    = (const float*)d_in[18];
    const float* be2   = (const float*)d_in[19];
    const float* Wout  = (const float*)d_in[20];
    const float* bout  = (const float*)d_in[21];
    float* out = (float*)d_out;

    static ForkRes fr;      // created on first (correctness) call, pre-capture

    const int EB = (EE + 255) / 256;
    const int NB = (NN + 255) / 256;
    const int WB = NN / 8;                 // warp-per-node kernels (256 thr)
    dim3 gg(2, (NN + 127) / 128);

    // main stream: setup (prepW + ve + zero), then fork
    k_setup<<<513, 256>>>(We1, atte1, We2, atte2, W1, W2);      // 1
    cudaEventRecord(fr.evFork, 0);
    cudaStreamWaitEvent(fr.side, fr.evFork, 0);

    // side stream: CSR build chain; main: GEMM1 concurrently
    k_deg<<<EB, 256, 0, fr.side>>>(edst);                       // 2
    k_scan1<<<NB, 256, 0, fr.side>>>();                         // 3
    k_gemm<<<gg, 256>>>(x, NN, 64, 0, 0, atts1, attd1,
                        nullptr, nullptr);                      // 4  <- profiled
    k_scan2<<<1, 256, 0, fr.side>>>(NB);                        // 5
    k_scan3<<<NB, 256, 0, fr.side>>>();                         // 6
    k_edge1<<<EB, 256, 0, fr.side>>>(eattr, esrc, edst);        // 7
    cudaEventRecord(fr.evJoin, fr.side);
    // edge2 stays on side stream: overlaps agg1/stats/gemm2 on main
    k_edge2<<<EB, 256, 0, fr.side>>>(eattr);                    // 8
    cudaEventRecord(fr.evJoin2, fr.side);
    cudaStreamWaitEvent(0, fr.evJoin, 0);

    // layer 1 (needs gemm1 + CSR layer-1 data)
    k_agg<<<WB, 256>>>(0, b1);                                  // 9
    k_stats<<<256, 256>>>(0);                                   // 10

    // layer 2 (BN-prep + BN-ReLU of layer1 fused into GEMM, fp16 A)
    k_gemm<<<gg, 256>>>(nullptr, NN, 256, 1, 1, atts2, attd2,
                        g1, be1);                               // 11
    cudaStreamWaitEvent(0, fr.evJoin2, 0);                      // ae2c ready
    k_agg<<<WB, 256>>>(1, b2);                                  // 12
    k_stats<<<256, 256>>>(512);                                 // 13

    // output head
    k_final<<<WB, 256>>>(g2, be2, Wout, bout, out);             // 14
}

// round 13
// speedup vs baseline: 1.5600x; 1.0605x over previous
#include <cuda_runtime.h>
#include <cuda_bf16.h>
#include <cuda_fp16.h>

#define NN 50000
#define EE 800000
#define HC 256

// ---------------- scratch (device globals; no allocation allowed) ----------------
__device__ __align__(16) __half g_xsh[NN * HC];   // xs of current layer, fp16
__device__ __align__(16) __half g_hpreh[NN * HC]; // aggregated pre-BN output, fp16
__device__ float g_as[NN * 4];
__device__ float g_ad[NN * 4];
__device__ float g_ae1c[EE * 4];    // a_e layer1, CSR order
__device__ float g_ae2c[EE * 4];    // a_e layer2, CSR order
__device__ int   g_epos[EE];        // edge -> CSR position (edge1 -> edge2)
__device__ int   g_deg[NN];
__device__ int   g_offs[NN + 1];
__device__ int   g_cursor[NN];
__device__ int   g_bsum[256];
__device__ int   g_bbase[257];
__device__ int   g_csrc[EE];
__device__ float g_ve1[64];         // [16,4]
__device__ float g_ve2[64];
__device__ float g_stats[1024];     // layer1: [0,512), layer2: [512,1024)
// W pre-transposed [n][k], single fp16 plane, per layer
__device__ __align__(16) unsigned short g_Wt[2][256 * 256];

__device__ __forceinline__ float lrelu(float x) { return fmaxf(x, 0.2f * x); }

// exact 2-term fp16 split of two fp32 values, packed as fp16x2 words
__device__ __forceinline__ void split_pk16(float x0, float x1, unsigned& h, unsigned& l) {
    __half h0 = __float2half_rn(x0), h1 = __float2half_rn(x1);
    float r0 = x0 - __half2float(h0), r1 = x1 - __half2float(h1);
    __half l0 = __float2half_rn(r0), l1 = __float2half_rn(r1);
    h = (unsigned)__half_as_ushort(h0) | ((unsigned)__half_as_ushort(h1) << 16);
    l = (unsigned)__half_as_ushort(l0) | ((unsigned)__half_as_ushort(l1) << 16);
}

#define MMA_FP16(C, A0, A1, A2, A3, B0, B1)                                      \
    asm volatile("mma.sync.aligned.m16n8k16.row.col.f32.f16.f16.f32 "            \
                 "{%0,%1,%2,%3}, {%4,%5,%6,%7}, {%8,%9}, {%0,%1,%2,%3};\n"       \
                 : "+f"((C)[0]), "+f"((C)[1]), "+f"((C)[2]), "+f"((C)[3])        \
                 : "r"(A0), "r"(A1), "r"(A2), "r"(A3), "r"(B0), "r"(B1))

// ---------------- setup: prepW both layers (fp16) + ve + zero deg/stats ----------
__global__ void k_setup(const float* __restrict__ We1, const float* __restrict__ at1,
                        const float* __restrict__ We2, const float* __restrict__ at2,
                        const float* __restrict__ W1, const float* __restrict__ W2) {
    int b = blockIdx.x;
    int t = threadIdx.x;
    int zi = b * 256 + t;
    if (zi < NN) g_deg[zi] = 0;
    if (b == 512) {
        #pragma unroll
        for (int j = 0; j < 4; j++) g_stats[t + 256 * j] = 0.f;
        if (t < 128) {
            int which = t >> 6;
            int u = t & 63;
            int j = u >> 2, h = u & 3;
            const float* We = which ? We2 : We1;
            const float* at = which ? at2 : at1;
            float s = 0.f;
            #pragma unroll 8
            for (int c = 0; c < 64; c++) s += We[j * HC + h * 64 + c] * at[h * 64 + c];
            if (which) g_ve2[u] = s; else g_ve1[u] = s;
        }
        return;
    }
    int layer = (b >= 256) ? 1 : 0;
    int n = layer ? (b - 256) : b;
    int K = layer ? 256 : 64;
    const float* W = layer ? W2 : W1;
    if (t >= K) return;
    float x = W[(size_t)t * 256 + n];
    g_Wt[layer][n * K + t] = __half_as_ushort(__float2half_rn(x));
}

// degree histogram only (dst reads, 3.2 MB)
__global__ void k_deg(const int* __restrict__ dst) {
    int e = blockIdx.x * blockDim.x + threadIdx.x;
    if (e < EE) atomicAdd(&g_deg[dst[e]], 1);
}

// ------------- 3-kernel exclusive scan of deg -> offs, cursor -------------
__global__ void k_scan1() {
    __shared__ int sh[256];
    int b = blockIdx.x, t = threadIdx.x;
    int i = b * 256 + t;
    sh[t] = (i < NN) ? g_deg[i] : 0;
    __syncthreads();
    for (int o = 128; o; o >>= 1) { if (t < o) sh[t] += sh[t + o]; __syncthreads(); }
    if (t == 0) g_bsum[b] = sh[0];
}

__global__ void k_scan2(int nb) {
    __shared__ int sh[256];
    int t = threadIdx.x;
    sh[t] = (t < nb) ? g_bsum[t] : 0;
    __syncthreads();
    for (int o = 1; o < 256; o <<= 1) {
        int v = (t >= o) ? sh[t - o] : 0;
        __syncthreads();
        sh[t] += v;
        __syncthreads();
    }
    g_bbase[t + 1] = sh[t];
    if (t == 0) { g_bbase[0] = 0; g_offs[NN] = EE; }
}

__global__ void k_scan3() {
    __shared__ int sh[256];
    int b = blockIdx.x, t = threadIdx.x;
    int i = b * 256 + t;
    int d = (i < NN) ? g_deg[i] : 0;
    sh[t] = d;
    __syncthreads();
    for (int o = 1; o < 256; o <<= 1) {
        int v = (t >= o) ? sh[t - o] : 0;
        __syncthreads();
        sh[t] += v;
        __syncthreads();
    }
    if (i < NN) {
        int off = g_bbase[b] + sh[t] - d;
        g_offs[i] = off;
        g_cursor[i] = off;
    }
}

// edge1 (join-critical): layer-1 a_e + CSR src + saved position
__global__ void k_edge1(const float* __restrict__ eattr, const int* __restrict__ src,
                        const int* __restrict__ dst) {
    int e = blockIdx.x * blockDim.x + threadIdx.x;
    if (e >= EE) return;
    const float4* p = (const float4*)(eattr + (size_t)e * 16);
    float4 a = p[0], b = p[1], c = p[2], d = p[3];
    float v[16] = {a.x,a.y,a.z,a.w, b.x,b.y,b.z,b.w, c.x,c.y,c.z,c.w, d.x,d.y,d.z,d.w};
    float o1[4] = {0, 0, 0, 0};
    #pragma unroll
    for (int j = 0; j < 16; j++)
        #pragma unroll
        for (int h = 0; h < 4; h++) o1[h] += v[j] * g_ve1[j * 4 + h];
    int pos = atomicAdd(&g_cursor[dst[e]], 1);
    g_csrc[pos] = src[e];
    g_epos[e] = pos;
    *(float4*)(g_ae1c + (size_t)pos * 4) = make_float4(o1[0], o1[1], o1[2], o1[3]);
}

// edge2 (deferred, overlaps agg1/stats/gemm2): layer-2 a_e into CSR order
__global__ void k_edge2(const float* __restrict__ eattr) {
    int e = blockIdx.x * blockDim.x + threadIdx.x;
    if (e >= EE) return;
    const float4* p = (const float4*)(eattr + (size_t)e * 16);
    float4 a = p[0], b = p[1], c = p[2], d = p[3];
    float v[16] = {a.x,a.y,a.z,a.w, b.x,b.y,b.z,b.w, c.x,c.y,c.z,c.w, d.x,d.y,d.z,d.w};
    float o2[4] = {0, 0, 0, 0};
    #pragma unroll
    for (int j = 0; j < 16; j++)
        #pragma unroll
        for (int h = 0; h < 4; h++) o2[h] += v[j] * g_ve2[j * 4 + h];
    int pos = g_epos[e];
    *(float4*)(g_ae2c + (size_t)pos * 4) = make_float4(o2[0], o2[1], o2[2], o2[3]);
}

// ---------------- tensor-core GEMM: C[M,256] = A[M,K] @ W, fp16 2-term ----------
// A split exactly into fp16 hi+lo; B single fp16 plane. 32 MMAs/chunk.
// BM=128 BN=128 BK=16, 8 warps, warp tile 64x32, mma m16n8k16 f16.
// smem: 8 words/row, k-pair-permuted units + XOR swizzle; frag loads LDS.64.
// Double buffered. Fused: BN-prep+BN-ReLU on A (layer2), attdot epilogue, fp16 C.
__global__ void __launch_bounds__(256, 2)
k_gemm(const float* __restrict__ Aext, int M, int K, int layer, int bnflag,
       const float* __restrict__ atts, const float* __restrict__ attd,
       const float* __restrict__ bng, const float* __restrict__ bnbe) {
    __shared__ unsigned sAh[2][1024], sAl[2][1024];   // 128 rows x 8 words
    __shared__ unsigned sB[2][1024];                  // 24 KB total
    __shared__ float s_bnsc[256], s_bnsh[256];
    int tid = threadIdx.x;
    int lane = tid & 31, wid = tid >> 5;
    int wm = (wid >> 2) * 64, wn = (wid & 3) * 32;
    int rowBlk = blockIdx.y * 128, colBlk = blockIdx.x * 128;

    if (bnflag) {
        const float invN = 1.0f / NN;
        float mu = g_stats[tid] * invN;
        float var = g_stats[256 + tid] * invN - mu * mu;
        float scv = bng[tid] * rsqrtf(var + 1e-5f);
        s_bnsc[tid] = scv;
        s_bnsh[tid] = bnbe[tid] - scv * mu;
        __syncthreads();
    }

    int ar = tid >> 1;
    int sel = tid & 1;
    bool aval = (rowBlk + ar) < M;
    const float* Ap = Aext ? (Aext + (size_t)(rowBlk + ar) * K + sel * 4) : nullptr;
    const __half* Aph = g_hpreh + (size_t)(rowBlk + ar) * K + sel * 4;
    int bn_ = tid & 127;
    int bsel = tid >> 7;
    const unsigned short* Bp = g_Wt[layer] + (size_t)(colBlk + bn_) * K;

    float c[4][4][4];
    #pragma unroll
    for (int mt = 0; mt < 4; mt++)
        #pragma unroll
        for (int nt = 0; nt < 4; nt++)
            #pragma unroll
            for (int q = 0; q < 4; q++) c[mt][nt][q] = 0.f;

    int nch = K >> 4;
    float4 fu, fv;
    uint4 bq0, bq1;

    auto loadChunk = [&](int ch) {
        if (Aext) {
            const float* Ap2 = Ap + ch * 16;
            fu = aval ? *(const float4*)(Ap2) : make_float4(0, 0, 0, 0);
            fv = aval ? *(const float4*)(Ap2 + 8) : make_float4(0, 0, 0, 0);
        } else {
            const __half* Ah2 = Aph + ch * 16;
            uint2 u0 = aval ? *(const uint2*)(Ah2) : make_uint2(0, 0);
            uint2 u1 = aval ? *(const uint2*)(Ah2 + 8) : make_uint2(0, 0);
            float2 p0 = __half22float2(*(__half2*)&u0.x);
            float2 p1 = __half22float2(*(__half2*)&u0.y);
            float2 p2 = __half22float2(*(__half2*)&u1.x);
            float2 p3 = __half22float2(*(__half2*)&u1.y);
            fu = make_float4(p0.x, p0.y, p1.x, p1.y);
            fv = make_float4(p2.x, p2.y, p3.x, p3.y);
        }
        if (bnflag && aval) {
            int kk = ch * 16 + sel * 4;
            float4 sc0 = *(const float4*)(s_bnsc + kk);
            float4 sh0 = *(const float4*)(s_bnsh + kk);
            float4 sc1 = *(const float4*)(s_bnsc + kk + 8);
            float4 sh1 = *(const float4*)(s_bnsh + kk + 8);
            fu.x = fmaxf(fmaf(sc0.x, fu.x, sh0.x), 0.f);
            fu.y = fmaxf(fmaf(sc0.y, fu.y, sh0.y), 0.f);
            fu.z = fmaxf(fmaf(sc0.z, fu.z, sh0.z), 0.f);
            fu.w = fmaxf(fmaf(sc0.w, fu.w, sh0.w), 0.f);
            fv.x = fmaxf(fmaf(sc1.x, fv.x, sh1.x), 0.f);
            fv.y = fmaxf(fmaf(sc1.y, fv.y, sh1.y), 0.f);
            fv.z = fmaxf(fmaf(sc1.z, fv.z, sh1.z), 0.f);
            fv.w = fmaxf(fmaf(sc1.w, fv.w, sh1.w), 0.f);
        }
        if (!bsel) {
            const uint4* Bc = (const uint4*)(Bp + ch * 16);
            bq0 = Bc[0];
            bq1 = Bc[1];
        }
    };
    auto stage = [&](int nb) {
        unsigned w0, w1, w2, w3, l0, l1, l2, l3;
        split_pk16(fu.x, fu.y, w0, l0);
        split_pk16(fv.x, fv.y, w1, l1);
        split_pk16(fu.z, fu.w, w2, l2);
        split_pk16(fv.z, fv.w, w3, l3);
        int s = ar & 3;
        int addr = ar * 8 + ((((2 * sel) ^ s) & ~1) << 1);
        if (s & 1) {
            *(uint4*)(&sAh[nb][addr]) = make_uint4(w2, w3, w0, w1);
            *(uint4*)(&sAl[nb][addr]) = make_uint4(l2, l3, l0, l1);
        } else {
            *(uint4*)(&sAh[nb][addr]) = make_uint4(w0, w1, w2, w3);
            *(uint4*)(&sAl[nb][addr]) = make_uint4(l0, l1, l2, l3);
        }
        if (!bsel) {
            int t = bn_ & 3;
            uint4 W0 = make_uint4(bq0.x, bq1.x, bq0.y, bq1.y);
            uint4 W1 = make_uint4(bq0.z, bq1.z, bq0.w, bq1.w);
            if (t & 1) {
                W0 = make_uint4(W0.z, W0.w, W0.x, W0.y);
                W1 = make_uint4(W1.z, W1.w, W1.x, W1.y);
            }
            int a0 = bn_ * 8 + (((0 ^ t) & ~1) << 1);
            int a1 = bn_ * 8 + (((2 ^ t) & ~1) << 1);
            *(uint4*)(&sB[nb][a0]) = W0;
            *(uint4*)(&sB[nb][a1]) = W1;
        }
    };

    loadChunk(0);
    stage(0);
    __syncthreads();

    for (int ch = 0; ch < nch; ch++) {
        int cur = ch & 1;
        if (ch + 1 < nch) loadChunk(ch + 1);
        uint2 bh[4];
        #pragma unroll
        for (int nt = 0; nt < 4; nt++) {
            int n = wn + nt * 8 + (lane >> 2);
            int off = n * 8 + ((((lane & 3) ^ (n & 3)) & 3) * 2);
            bh[nt] = *(const uint2*)(&sB[cur][off]);
        }
        #pragma unroll
        for (int mt = 0; mt < 4; mt++) {
            int r = wm + mt * 16 + (lane >> 2);
            int uoff = (((lane & 3) ^ (r & 3)) & 3) * 2;
            uint2 h0 = *(const uint2*)(&sAh[cur][r * 8 + uoff]);
            uint2 h1 = *(const uint2*)(&sAh[cur][(r + 8) * 8 + uoff]);
            uint2 q0 = *(const uint2*)(&sAl[cur][r * 8 + uoff]);
            uint2 q1 = *(const uint2*)(&sAl[cur][(r + 8) * 8 + uoff]);
            #pragma unroll
            for (int nt = 0; nt < 4; nt++) {
                MMA_FP16(c[mt][nt], h0.x, h1.x, h0.y, h1.y, bh[nt].x, bh[nt].y);
                MMA_FP16(c[mt][nt], q0.x, q1.x, q0.y, q1.y, bh[nt].x, bh[nt].y);
            }
        }
        if (ch + 1 < nch) stage(cur ^ 1);
        __syncthreads();
    }

    // epilogue: write C as fp16 (only consumer is the agg gather)
    #pragma unroll
    for (int mt = 0; mt < 4; mt++) {
        int r0 = rowBlk + wm + mt * 16 + (lane >> 2);
        #pragma unroll
        for (int nt = 0; nt < 4; nt++) {
            int col = colBlk + wn + nt * 8 + (lane & 3) * 2;
            if (r0 < M)
                *(__half2*)(g_xsh + (size_t)r0 * 256 + col) =
                    __floats2half2_rn(c[mt][nt][0], c[mt][nt][1]);
            if (r0 + 8 < M)
                *(__half2*)(g_xsh + (size_t)(r0 + 8) * 256 + col) =
                    __floats2half2_rn(c[mt][nt][2], c[mt][nt][3]);
        }
    }
    // fused attdot
    float2* sred = reinterpret_cast<float2*>(&sAh[0][0]);   // [4][128] = 4KB
    float sv[4][2], dv[4][2];
    #pragma unroll
    for (int nt = 0; nt < 4; nt++)
        #pragma unroll
        for (int q = 0; q < 2; q++) {
            int col = colBlk + wn + nt * 8 + (lane & 3) * 2 + q;
            sv[nt][q] = atts[col];
            dv[nt][q] = attd[col];
        }
    #pragma unroll
    for (int mt = 0; mt < 4; mt++) {
        #pragma unroll
        for (int half = 0; half < 2; half++) {
            float ss = 0.f, dd = 0.f;
            #pragma unroll
            for (int nt = 0; nt < 4; nt++) {
                #pragma unroll
                for (int q = 0; q < 2; q++) {
                    ss = fmaf(c[mt][nt][half * 2 + q], sv[nt][q], ss);
                    dd = fmaf(c[mt][nt][half * 2 + q], dv[nt][q], dd);
                }
            }
            ss += __shfl_xor_sync(0xffffffffu, ss, 1);
            ss += __shfl_xor_sync(0xffffffffu, ss, 2);
            dd += __shfl_xor_sync(0xffffffffu, dd, 1);
            dd += __shfl_xor_sync(0xffffffffu, dd, 2);
            if ((lane & 3) == 0)
                sred[(wid & 3) * 128 + wm + mt * 16 + half * 8 + (lane >> 2)] =
                    make_float2(ss, dd);
        }
    }
    __syncthreads();
    {
        int row = tid >> 1, hl = tid & 1;
        int r = rowBlk + row;
        if (r < M) {
            float2 aa = sred[2 * hl * 128 + row], bb = sred[(2 * hl + 1) * 128 + row];
            int hidx = (colBlk >> 6) + hl;
            g_as[r * 4 + hidx] = aa.x + bb.x;
            g_ad[r * 4 + hidx] = aa.y + bb.y;
        }
    }
}

// ---------------- GAT aggregation: single pass, warp per dst node.
// fp16 row gather; fp32 accumulation; fp16 hpre store. --------
__global__ void __launch_bounds__(256) k_agg(int layer, const float* __restrict__ bias) {
    __shared__ float4 sp[8][32];
    __shared__ int    si[8][32];
    int w = (blockIdx.x * blockDim.x + threadIdx.x) >> 5;
    if (w >= NN) return;
    int lane = threadIdx.x & 31;
    int wrp = threadIdx.x >> 5;
    const float4* aeC = (const float4*)(layer ? g_ae2c : g_ae1c);
    int beg = g_offs[w], end = g_offs[w + 1];
    float4 adv = *(const float4*)(g_ad + (size_t)w * 4);
    int h = lane >> 3;
    int f0 = lane * 8;
    float acc[8] = {0, 0, 0, 0, 0, 0, 0, 0};
    float den0 = 0, den1 = 0, den2 = 0, den3 = 0;
    float sa0 = 0, sa1 = 0, sa2 = 0, sa3 = 0;

    for (int base = beg; base < end; base += 32) {
        int i = base + lane;
        float p0 = 0, p1 = 0, p2 = 0, p3 = 0;
        int s = 0;
        if (i < end) {
            s = g_csrc[i];
            float4 ae = aeC[i];
            float4 as = *(const float4*)(g_as + (size_t)s * 4);
            sa0 += ae.x; sa1 += ae.y; sa2 += ae.z; sa3 += ae.w;
            p0 = __expf(lrelu(as.x + adv.x + ae.x));
            p1 = __expf(lrelu(as.y + adv.y + ae.y));
            p2 = __expf(lrelu(as.z + adv.z + ae.z));
            p3 = __expf(lrelu(as.w + adv.w + ae.w));
            den0 += p0; den1 += p1; den2 += p2; den3 += p3;
        }
        sp[wrp][lane] = make_float4(p0, p1, p2, p3);
        si[wrp][lane] = s;
        __syncwarp();
        int cnt = min(32, end - base);
        #pragma unroll 4
        for (int jj = 0; jj < cnt; jj++) {
            int ss = si[wrp][jj];
            float q = ((const float*)&sp[wrp][jj])[h];
            uint4 xv = *(const uint4*)(g_xsh + (size_t)ss * HC + f0);
            float2 x0 = __half22float2(*(__half2*)&xv.x);
            float2 x1 = __half22float2(*(__half2*)&xv.y);
            float2 x2 = __half22float2(*(__half2*)&xv.z);
            float2 x3 = __half22float2(*(__half2*)&xv.w);
            acc[0] = fmaf(q, x0.x, acc[0]); acc[1] = fmaf(q, x0.y, acc[1]);
            acc[2] = fmaf(q, x1.x, acc[2]); acc[3] = fmaf(q, x1.y, acc[3]);
            acc[4] = fmaf(q, x2.x, acc[4]); acc[5] = fmaf(q, x2.y, acc[5]);
            acc[6] = fmaf(q, x3.x, acc[6]); acc[7] = fmaf(q, x3.y, acc[7]);
        }
        __syncwarp();
    }
    #pragma unroll
    for (int o = 16; o; o >>= 1) {
        den0 += __shfl_xor_sync(0xffffffffu, den0, o);
        den1 += __shfl_xor_sync(0xffffffffu, den1, o);
        den2 += __shfl_xor_sync(0xffffffffu, den2, o);
        den3 += __shfl_xor_sync(0xffffffffu, den3, o);
        sa0 += __shfl_xor_sync(0xffffffffu, sa0, o);
        sa1 += __shfl_xor_sync(0xffffffffu, sa1, o);
        sa2 += __shfl_xor_sync(0xffffffffu, sa2, o);
        sa3 += __shfl_xor_sync(0xffffffffu, sa3, o);
    }
    int deg = end - beg;
    float invd = 1.0f / fmaxf((float)deg, 1.0f);
    float4 asn = *(const float4*)(g_as + (size_t)w * 4);
    float ps0 = __expf(lrelu(asn.x + adv.x + sa0 * invd));
    float ps1 = __expf(lrelu(asn.y + adv.y + sa1 * invd));
    float ps2 = __expf(lrelu(asn.z + adv.z + sa2 * invd));
    float ps3 = __expf(lrelu(asn.w + adv.w + sa3 * invd));
    den0 += ps0 + 1e-16f; den1 += ps1 + 1e-16f;
    den2 += ps2 + 1e-16f; den3 += ps3 + 1e-16f;
    {
        uint4 xv = *(const uint4*)(g_xsh + (size_t)w * HC + f0);
        float2 x0 = __half22float2(*(__half2*)&xv.x);
        float2 x1 = __half22float2(*(__half2*)&xv.y);
        float2 x2 = __half22float2(*(__half2*)&xv.z);
        float2 x3 = __half22float2(*(__half2*)&xv.w);
        float psh = (h == 0) ? ps0 : (h == 1) ? ps1 : (h == 2) ? ps2 : ps3;
        acc[0] = fmaf(psh, x0.x, acc[0]); acc[1] = fmaf(psh, x0.y, acc[1]);
        acc[2] = fmaf(psh, x1.x, acc[2]); acc[3] = fmaf(psh, x1.y, acc[3]);
        acc[4] = fmaf(psh, x2.x, acc[4]); acc[5] = fmaf(psh, x2.y, acc[5]);
        acc[6] = fmaf(psh, x3.x, acc[6]); acc[7] = fmaf(psh, x3.y, acc[7]);
    }
    float denh = (h == 0) ? den0 : (h == 1) ? den1 : (h == 2) ? den2 : den3;
    float r = 1.0f / denh;
    float4 b0 = *(const float4*)(bias + f0);
    float4 b1 = *(const float4*)(bias + f0 + 4);
    __half2 o0 = __floats2half2_rn(fmaf(acc[0], r, b0.x), fmaf(acc[1], r, b0.y));
    __half2 o1 = __floats2half2_rn(fmaf(acc[2], r, b0.z), fmaf(acc[3], r, b0.w));
    __half2 o2 = __floats2half2_rn(fmaf(acc[4], r, b1.x), fmaf(acc[5], r, b1.y));
    __half2 o3 = __floats2half2_rn(fmaf(acc[6], r, b1.z), fmaf(acc[7], r, b1.w));
    uint4 pack;
    pack.x = *(unsigned*)&o0; pack.y = *(unsigned*)&o1;
    pack.z = *(unsigned*)&o2; pack.w = *(unsigned*)&o3;
    *(uint4*)(g_hpreh + (size_t)w * HC + f0) = pack;
}

// ---------------- BN batch stats (sum, sumsq per column), fp16 source ----------------
__global__ void k_stats(int off) {
    int c = threadIdx.x;    // 256
    int rows = (NN + gridDim.x - 1) / gridDim.x;
    int r0 = blockIdx.x * rows, r1 = min(r0 + rows, NN);
    float s = 0.f, s2 = 0.f;
    for (int r = r0; r < r1; r++) {
        float v = __half2float(g_hpreh[(size_t)r * HC + c]);
        s += v;
        s2 = fmaf(v, v, s2);
    }
    atomicAdd(&g_stats[off + c], s);
    atomicAdd(&g_stats[off + 256 + c], s2);
}

// ---------------- final: out[n] = relu(BN(hpre2)) . wout + bout ----------------
__global__ void k_final(const float* __restrict__ g, const float* __restrict__ be,
                        const float* __restrict__ wout, const float* __restrict__ bout,
                        float* __restrict__ out) {
    int w = (blockIdx.x * blockDim.x + threadIdx.x) >> 5;
    if (w >= NN) return;
    int lane = threadIdx.x & 31;
    const float invN = 1.0f / NN;
    float s = 0.f;
    #pragma unroll
    for (int j = 0; j < 8; j++) {
        int f = lane + 32 * j;
        float mu = g_stats[512 + f] * invN;
        float var = g_stats[768 + f] * invN - mu * mu;
        float sc = g[f] * rsqrtf(var + 1e-5f);
        float hv = __half2float(g_hpreh[(size_t)w * HC + f]);
        float v = fmaxf(sc * (hv - mu) + be[f], 0.f);
        s = fmaf(v, wout[f], s);
    }
    #pragma unroll
    for (int o = 16; o; o >>= 1) s += __shfl_xor_sync(0xffffffffu, s, o);
    if (lane == 0) out[w] = s + bout[0];
}

// ---------------- stream fork/join resources (created once, OUTSIDE capture) -----
struct ForkRes {
    cudaStream_t side;
    cudaEvent_t evFork, evJoin, evJoin2;
    ForkRes() {
        cudaStreamCreateWithFlags(&side, cudaStreamNonBlocking);
        cudaEventCreateWithFlags(&evFork, cudaEventDisableTiming);
        cudaEventCreateWithFlags(&evJoin, cudaEventDisableTiming);
        cudaEventCreateWithFlags(&evJoin2, cudaEventDisableTiming);
    }
};

// ---------------- launch ----------------
extern "C" void kernel_launch(void* const* d_in, const int* in_sizes, int n_in,
                              void* d_out, int out_size) {
    const float* x     = (const float*)d_in[0];
    const int*   esrc  = (const int*)d_in[1];
    const int*   edst  = (const int*)d_in[2];
    const float* eattr = (const float*)d_in[3];
    const float* W1    = (const float*)d_in[4];
    const float* atts1 = (const float*)d_in[5];
    const float* attd1 = (const float*)d_in[6];
    const float* We1   = (const float*)d_in[7];
    const float* atte1 = (const float*)d_in[8];
    const float* b1    = (const float*)d_in[9];
    const float* g1    = (const float*)d_in[10];
    const float* be1   = (const float*)d_in[11];
    const float* W2    = (const float*)d_in[12];
    const float* atts2 = (const float*)d_in[13];
    const float* attd2 = (const float*)d_in[14];
    const float* We2   = (const float*)d_in[15];
    const float* atte2 = (const float*)d_in[16];
    const float* b2    = (const float*)d_in[17];
    const float* g2    = (const float*)d_in[18];
    const float* be2   = (const float*)d_in[19];
    const float* Wout  = (const float*)d_in[20];
    const float* bout  = (const float*)d_in[21];
    float* out = (float*)d_out;

    static ForkRes fr;      // created on first (correctness) call, pre-capture

    const int EB = (EE + 255) / 256;
    const int NB = (NN + 255) / 256;
    const int WB = NN / 8;                 // warp-per-node kernels (256 thr)
    dim3 gg(2, (NN + 127) / 128);

    // main stream: setup (prepW + ve + zero), then fork
    k_setup<<<513, 256>>>(We1, atte1, We2, atte2, W1, W2);      // 1
    cudaEventRecord(fr.evFork, 0);
    cudaStreamWaitEvent(fr.side, fr.evFork, 0);

    // side stream: CSR build chain; main: GEMM1 concurrently
    k_deg<<<EB, 256, 0, fr.side>>>(edst);                       // 2
    k_scan1<<<NB, 256, 0, fr.side>>>();                         // 3
    k_gemm<<<gg, 256>>>(x, NN, 64, 0, 0, atts1, attd1,
                        nullptr, nullptr);                      // 4  <- profiled
    k_scan2<<<1, 256, 0, fr.side>>>(NB);                        // 5
    k_scan3<<<NB, 256, 0, fr.side>>>();                         // 6
    k_edge1<<<EB, 256, 0, fr.side>>>(eattr, esrc, edst);        // 7
    cudaEventRecord(fr.evJoin, fr.side);
    // edge2 stays on side stream: overlaps agg1/stats/gemm2 on main
    k_edge2<<<EB, 256, 0, fr.side>>>(eattr);                    // 8
    cudaEventRecord(fr.evJoin2, fr.side);
    cudaStreamWaitEvent(0, fr.evJoin, 0);

    // layer 1 (needs gemm1 + CSR layer-1 data)
    k_agg<<<WB, 256>>>(0, b1);                                  // 9
    k_stats<<<256, 256>>>(0);                                   // 10

    // layer 2 (BN-prep + BN-ReLU of layer1 fused into GEMM, fp16 A)
    k_gemm<<<gg, 256>>>(nullptr, NN, 256, 1, 1, atts2, attd2,
                        g1, be1);                               // 11
    cudaStreamWaitEvent(0, fr.evJoin2, 0);                      // ae2c ready
    k_agg<<<WB, 256>>>(1, b2);                                  // 12
    k_stats<<<256, 256>>>(512);                                 // 13

    // output head
    k_final<<<WB, 256>>>(g2, be2, Wout, bout, out);             // 14
}

// round 14
// speedup vs baseline: 1.5693x; 1.0060x over previous
#include <cuda_runtime.h>
#include <cuda_bf16.h>
#include <cuda_fp16.h>

#define NN 50000
#define EE 800000
#define HC 256

// ---------------- scratch (device globals; no allocation allowed) ----------------
__device__ __align__(16) __half g_xsh[NN * HC];   // xs of current layer, fp16
__device__ __align__(16) __half g_hpreh[NN * HC]; // aggregated pre-BN output, fp16
__device__ float g_as[NN * 4];
__device__ float g_ad[NN * 4];
__device__ float g_ae1c[EE * 4];    // a_e layer1, CSR order
__device__ float g_ae2c[EE * 4];    // a_e layer2, CSR order
__device__ int   g_epos[EE];        // edge -> CSR position (edge1 -> edge2)
__device__ int   g_deg[NN];
__device__ int   g_offs[NN + 1];
__device__ int   g_cursor[NN];
__device__ int   g_bsum[256];
__device__ int   g_bbase[257];
__device__ int   g_csrc[EE];
__device__ float g_ve1[64];         // [16,4]
__device__ float g_ve2[64];
__device__ float g_stats[1024];     // layer1: [0,512), layer2: [512,1024)
// W pre-transposed [n][k], single fp16 plane, per layer
__device__ __align__(16) unsigned short g_Wt[2][256 * 256];

__device__ __forceinline__ float lrelu(float x) { return fmaxf(x, 0.2f * x); }

// exact 2-term fp16 split of two fp32 values, packed as fp16x2 words
__device__ __forceinline__ void split_pk16(float x0, float x1, unsigned& h, unsigned& l) {
    __half h0 = __float2half_rn(x0), h1 = __float2half_rn(x1);
    float r0 = x0 - __half2float(h0), r1 = x1 - __half2float(h1);
    __half l0 = __float2half_rn(r0), l1 = __float2half_rn(r1);
    h = (unsigned)__half_as_ushort(h0) | ((unsigned)__half_as_ushort(h1) << 16);
    l = (unsigned)__half_as_ushort(l0) | ((unsigned)__half_as_ushort(l1) << 16);
}

#define MMA_FP16(C, A0, A1, A2, A3, B0, B1)                                      \
    asm volatile("mma.sync.aligned.m16n8k16.row.col.f32.f16.f16.f32 "            \
                 "{%0,%1,%2,%3}, {%4,%5,%6,%7}, {%8,%9}, {%0,%1,%2,%3};\n"       \
                 : "+f"((C)[0]), "+f"((C)[1]), "+f"((C)[2]), "+f"((C)[3])        \
                 : "r"(A0), "r"(A1), "r"(A2), "r"(A3), "r"(B0), "r"(B1))

// ---------------- setup: prepW both layers (fp16) + ve + zero deg/stats ----------
__global__ void k_setup(const float* __restrict__ We1, const float* __restrict__ at1,
                        const float* __restrict__ We2, const float* __restrict__ at2,
                        const float* __restrict__ W1, const float* __restrict__ W2) {
    int b = blockIdx.x;
    int t = threadIdx.x;
    int zi = b * 256 + t;
    if (zi < NN) g_deg[zi] = 0;
    if (b == 512) {
        #pragma unroll
        for (int j = 0; j < 4; j++) g_stats[t + 256 * j] = 0.f;
        if (t < 128) {
            int which = t >> 6;
            int u = t & 63;
            int j = u >> 2, h = u & 3;
            const float* We = which ? We2 : We1;
            const float* at = which ? at2 : at1;
            float s = 0.f;
            #pragma unroll 8
            for (int c = 0; c < 64; c++) s += We[j * HC + h * 64 + c] * at[h * 64 + c];
            if (which) g_ve2[u] = s; else g_ve1[u] = s;
        }
        return;
    }
    int layer = (b >= 256) ? 1 : 0;
    int n = layer ? (b - 256) : b;
    int K = layer ? 256 : 64;
    const float* W = layer ? W2 : W1;
    if (t >= K) return;
    float x = W[(size_t)t * 256 + n];
    g_Wt[layer][n * K + t] = __half_as_ushort(__float2half_rn(x));
}

// degree histogram only (dst reads, 3.2 MB)
__global__ void k_deg(const int* __restrict__ dst) {
    int e = blockIdx.x * blockDim.x + threadIdx.x;
    if (e < EE) atomicAdd(&g_deg[dst[e]], 1);
}

// ------------- 3-kernel exclusive scan of deg -> offs, cursor -------------
__global__ void k_scan1() {
    __shared__ int sh[256];
    int b = blockIdx.x, t = threadIdx.x;
    int i = b * 256 + t;
    sh[t] = (i < NN) ? g_deg[i] : 0;
    __syncthreads();
    for (int o = 128; o; o >>= 1) { if (t < o) sh[t] += sh[t + o]; __syncthreads(); }
    if (t == 0) g_bsum[b] = sh[0];
}

__global__ void k_scan2(int nb) {
    __shared__ int sh[256];
    int t = threadIdx.x;
    sh[t] = (t < nb) ? g_bsum[t] : 0;
    __syncthreads();
    for (int o = 1; o < 256; o <<= 1) {
        int v = (t >= o) ? sh[t - o] : 0;
        __syncthreads();
        sh[t] += v;
        __syncthreads();
    }
    g_bbase[t + 1] = sh[t];
    if (t == 0) { g_bbase[0] = 0; g_offs[NN] = EE; }
}

__global__ void k_scan3() {
    __shared__ int sh[256];
    int b = blockIdx.x, t = threadIdx.x;
    int i = b * 256 + t;
    int d = (i < NN) ? g_deg[i] : 0;
    sh[t] = d;
    __syncthreads();
    for (int o = 1; o < 256; o <<= 1) {
        int v = (t >= o) ? sh[t - o] : 0;
        __syncthreads();
        sh[t] += v;
        __syncthreads();
    }
    if (i < NN) {
        int off = g_bbase[b] + sh[t] - d;
        g_offs[i] = off;
        g_cursor[i] = off;
    }
}

// edge1 (join-critical): layer-1 a_e + CSR src + saved position
__global__ void k_edge1(const float* __restrict__ eattr, const int* __restrict__ src,
                        const int* __restrict__ dst) {
    int e = blockIdx.x * blockDim.x + threadIdx.x;
    if (e >= EE) return;
    const float4* p = (const float4*)(eattr + (size_t)e * 16);
    float4 a = p[0], b = p[1], c = p[2], d = p[3];
    float v[16] = {a.x,a.y,a.z,a.w, b.x,b.y,b.z,b.w, c.x,c.y,c.z,c.w, d.x,d.y,d.z,d.w};
    float o1[4] = {0, 0, 0, 0};
    #pragma unroll
    for (int j = 0; j < 16; j++)
        #pragma unroll
        for (int h = 0; h < 4; h++) o1[h] += v[j] * g_ve1[j * 4 + h];
    int pos = atomicAdd(&g_cursor[dst[e]], 1);
    g_csrc[pos] = src[e];
    g_epos[e] = pos;
    *(float4*)(g_ae1c + (size_t)pos * 4) = make_float4(o1[0], o1[1], o1[2], o1[3]);
}

// edge2 (deferred, overlaps agg1/gemm2): layer-2 a_e into CSR order
__global__ void k_edge2(const float* __restrict__ eattr) {
    int e = blockIdx.x * blockDim.x + threadIdx.x;
    if (e >= EE) return;
    const float4* p = (const float4*)(eattr + (size_t)e * 16);
    float4 a = p[0], b = p[1], c = p[2], d = p[3];
    float v[16] = {a.x,a.y,a.z,a.w, b.x,b.y,b.z,b.w, c.x,c.y,c.z,c.w, d.x,d.y,d.z,d.w};
    float o2[4] = {0, 0, 0, 0};
    #pragma unroll
    for (int j = 0; j < 16; j++)
        #pragma unroll
        for (int h = 0; h < 4; h++) o2[h] += v[j] * g_ve2[j * 4 + h];
    int pos = g_epos[e];
    *(float4*)(g_ae2c + (size_t)pos * 4) = make_float4(o2[0], o2[1], o2[2], o2[3]);
}

// ---------------- tensor-core GEMM: C[M,256] = A[M,K] @ W, fp16 2-term ----------
__global__ void __launch_bounds__(256, 2)
k_gemm(const float* __restrict__ Aext, int M, int K, int layer, int bnflag,
       const float* __restrict__ atts, const float* __restrict__ attd,
       const float* __restrict__ bng, const float* __restrict__ bnbe) {
    __shared__ unsigned sAh[2][1024], sAl[2][1024];   // 128 rows x 8 words
    __shared__ unsigned sB[2][1024];                  // 24 KB total
    __shared__ float s_bnsc[256], s_bnsh[256];
    int tid = threadIdx.x;
    int lane = tid & 31, wid = tid >> 5;
    int wm = (wid >> 2) * 64, wn = (wid & 3) * 32;
    int rowBlk = blockIdx.y * 128, colBlk = blockIdx.x * 128;

    if (bnflag) {
        const float invN = 1.0f / NN;
        float mu = g_stats[tid] * invN;
        float var = g_stats[256 + tid] * invN - mu * mu;
        float scv = bng[tid] * rsqrtf(var + 1e-5f);
        s_bnsc[tid] = scv;
        s_bnsh[tid] = bnbe[tid] - scv * mu;
        __syncthreads();
    }

    int ar = tid >> 1;
    int sel = tid & 1;
    bool aval = (rowBlk + ar) < M;
    const float* Ap = Aext ? (Aext + (size_t)(rowBlk + ar) * K + sel * 4) : nullptr;
    const __half* Aph = g_hpreh + (size_t)(rowBlk + ar) * K + sel * 4;
    int bn_ = tid & 127;
    int bsel = tid >> 7;
    const unsigned short* Bp = g_Wt[layer] + (size_t)(colBlk + bn_) * K;

    float c[4][4][4];
    #pragma unroll
    for (int mt = 0; mt < 4; mt++)
        #pragma unroll
        for (int nt = 0; nt < 4; nt++)
            #pragma unroll
            for (int q = 0; q < 4; q++) c[mt][nt][q] = 0.f;

    int nch = K >> 4;
    float4 fu, fv;
    uint4 bq0, bq1;

    auto loadChunk = [&](int ch) {
        if (Aext) {
            const float* Ap2 = Ap + ch * 16;
            fu = aval ? *(const float4*)(Ap2) : make_float4(0, 0, 0, 0);
            fv = aval ? *(const float4*)(Ap2 + 8) : make_float4(0, 0, 0, 0);
        } else {
            const __half* Ah2 = Aph + ch * 16;
            uint2 u0 = aval ? *(const uint2*)(Ah2) : make_uint2(0, 0);
            uint2 u1 = aval ? *(const uint2*)(Ah2 + 8) : make_uint2(0, 0);
            float2 p0 = __half22float2(*(__half2*)&u0.x);
            float2 p1 = __half22float2(*(__half2*)&u0.y);
            float2 p2 = __half22float2(*(__half2*)&u1.x);
            float2 p3 = __half22float2(*(__half2*)&u1.y);
            fu = make_float4(p0.x, p0.y, p1.x, p1.y);
            fv = make_float4(p2.x, p2.y, p3.x, p3.y);
        }
        if (bnflag && aval) {
            int kk = ch * 16 + sel * 4;
            float4 sc0 = *(const float4*)(s_bnsc + kk);
            float4 sh0 = *(const float4*)(s_bnsh + kk);
            float4 sc1 = *(const float4*)(s_bnsc + kk + 8);
            float4 sh1 = *(const float4*)(s_bnsh + kk + 8);
            fu.x = fmaxf(fmaf(sc0.x, fu.x, sh0.x), 0.f);
            fu.y = fmaxf(fmaf(sc0.y, fu.y, sh0.y), 0.f);
            fu.z = fmaxf(fmaf(sc0.z, fu.z, sh0.z), 0.f);
            fu.w = fmaxf(fmaf(sc0.w, fu.w, sh0.w), 0.f);
            fv.x = fmaxf(fmaf(sc1.x, fv.x, sh1.x), 0.f);
            fv.y = fmaxf(fmaf(sc1.y, fv.y, sh1.y), 0.f);
            fv.z = fmaxf(fmaf(sc1.z, fv.z, sh1.z), 0.f);
            fv.w = fmaxf(fmaf(sc1.w, fv.w, sh1.w), 0.f);
        }
        if (!bsel) {
            const uint4* Bc = (const uint4*)(Bp + ch * 16);
            bq0 = Bc[0];
            bq1 = Bc[1];
        }
    };
    auto stage = [&](int nb) {
        unsigned w0, w1, w2, w3, l0, l1, l2, l3;
        split_pk16(fu.x, fu.y, w0, l0);
        split_pk16(fv.x, fv.y, w1, l1);
        split_pk16(fu.z, fu.w, w2, l2);
        split_pk16(fv.z, fv.w, w3, l3);
        int s = ar & 3;
        int addr = ar * 8 + ((((2 * sel) ^ s) & ~1) << 1);
        if (s & 1) {
            *(uint4*)(&sAh[nb][addr]) = make_uint4(w2, w3, w0, w1);
            *(uint4*)(&sAl[nb][addr]) = make_uint4(l2, l3, l0, l1);
        } else {
            *(uint4*)(&sAh[nb][addr]) = make_uint4(w0, w1, w2, w3);
            *(uint4*)(&sAl[nb][addr]) = make_uint4(l0, l1, l2, l3);
        }
        if (!bsel) {
            int t = bn_ & 3;
            uint4 W0 = make_uint4(bq0.x, bq1.x, bq0.y, bq1.y);
            uint4 W1 = make_uint4(bq0.z, bq1.z, bq0.w, bq1.w);
            if (t & 1) {
                W0 = make_uint4(W0.z, W0.w, W0.x, W0.y);
                W1 = make_uint4(W1.z, W1.w, W1.x, W1.y);
            }
            int a0 = bn_ * 8 + (((0 ^ t) & ~1) << 1);
            int a1 = bn_ * 8 + (((2 ^ t) & ~1) << 1);
            *(uint4*)(&sB[nb][a0]) = W0;
            *(uint4*)(&sB[nb][a1]) = W1;
        }
    };

    loadChunk(0);
    stage(0);
    __syncthreads();

    for (int ch = 0; ch < nch; ch++) {
        int cur = ch & 1;
        if (ch + 1 < nch) loadChunk(ch + 1);
        uint2 bh[4];
        #pragma unroll
        for (int nt = 0; nt < 4; nt++) {
            int n = wn + nt * 8 + (lane >> 2);
            int off = n * 8 + ((((lane & 3) ^ (n & 3)) & 3) * 2);
            bh[nt] = *(const uint2*)(&sB[cur][off]);
        }
        #pragma unroll
        for (int mt = 0; mt < 4; mt++) {
            int r = wm + mt * 16 + (lane >> 2);
            int uoff = (((lane & 3) ^ (r & 3)) & 3) * 2;
            uint2 h0 = *(const uint2*)(&sAh[cur][r * 8 + uoff]);
            uint2 h1 = *(const uint2*)(&sAh[cur][(r + 8) * 8 + uoff]);
            uint2 q0 = *(const uint2*)(&sAl[cur][r * 8 + uoff]);
            uint2 q1 = *(const uint2*)(&sAl[cur][(r + 8) * 8 + uoff]);
            #pragma unroll
            for (int nt = 0; nt < 4; nt++) {
                MMA_FP16(c[mt][nt], h0.x, h1.x, h0.y, h1.y, bh[nt].x, bh[nt].y);
                MMA_FP16(c[mt][nt], q0.x, q1.x, q0.y, q1.y, bh[nt].x, bh[nt].y);
            }
        }
        if (ch + 1 < nch) stage(cur ^ 1);
        __syncthreads();
    }

    // epilogue: write C as fp16 (only consumer is the agg gather)
    #pragma unroll
    for (int mt = 0; mt < 4; mt++) {
        int r0 = rowBlk + wm + mt * 16 + (lane >> 2);
        #pragma unroll
        for (int nt = 0; nt < 4; nt++) {
            int col = colBlk + wn + nt * 8 + (lane & 3) * 2;
            if (r0 < M)
                *(__half2*)(g_xsh + (size_t)r0 * 256 + col) =
                    __floats2half2_rn(c[mt][nt][0], c[mt][nt][1]);
            if (r0 + 8 < M)
                *(__half2*)(g_xsh + (size_t)(r0 + 8) * 256 + col) =
                    __floats2half2_rn(c[mt][nt][2], c[mt][nt][3]);
        }
    }
    // fused attdot
    float2* sred = reinterpret_cast<float2*>(&sAh[0][0]);   // [4][128] = 4KB
    float sv[4][2], dv[4][2];
    #pragma unroll
    for (int nt = 0; nt < 4; nt++)
        #pragma unroll
        for (int q = 0; q < 2; q++) {
            int col = colBlk + wn + nt * 8 + (lane & 3) * 2 + q;
            sv[nt][q] = atts[col];
            dv[nt][q] = attd[col];
        }
    #pragma unroll
    for (int mt = 0; mt < 4; mt++) {
        #pragma unroll
        for (int half = 0; half < 2; half++) {
            float ss = 0.f, dd = 0.f;
            #pragma unroll
            for (int nt = 0; nt < 4; nt++) {
                #pragma unroll
                for (int q = 0; q < 2; q++) {
                    ss = fmaf(c[mt][nt][half * 2 + q], sv[nt][q], ss);
                    dd = fmaf(c[mt][nt][half * 2 + q], dv[nt][q], dd);
                }
            }
            ss += __shfl_xor_sync(0xffffffffu, ss, 1);
            ss += __shfl_xor_sync(0xffffffffu, ss, 2);
            dd += __shfl_xor_sync(0xffffffffu, dd, 1);
            dd += __shfl_xor_sync(0xffffffffu, dd, 2);
            if ((lane & 3) == 0)
                sred[(wid & 3) * 128 + wm + mt * 16 + half * 8 + (lane >> 2)] =
                    make_float2(ss, dd);
        }
    }
    __syncthreads();
    {
        int row = tid >> 1, hl = tid & 1;
        int r = rowBlk + row;
        if (r < M) {
            float2 aa = sred[2 * hl * 128 + row], bb = sred[(2 * hl + 1) * 128 + row];
            int hidx = (colBlk >> 6) + hl;
            g_as[r * 4 + hidx] = aa.x + bb.x;
            g_ad[r * 4 + hidx] = aa.y + bb.y;
        }
    }
}

// ---------------- GAT aggregation + fused BN stats (tree reduce, no smem atomics).
// Warp per dst node; fp16 gather; fp32 accum; fp16 hpre store.
// Grid exactly NN/8 blocks x 8 warps: all threads alive (syncthreads-safe). ------
__global__ void __launch_bounds__(256) k_agg(int layer, const float* __restrict__ bias,
                                             int statsOff) {
    __shared__ float4 sp[8][32];
    __shared__ int    si[8][32];
    __shared__ float  s_part[8][256];   // 8 KB, reused for sum then sumsq
    int tid = threadIdx.x;
    int w = (blockIdx.x * blockDim.x + tid) >> 5;
    int lane = tid & 31;
    int wrp = tid >> 5;
    const float4* aeC = (const float4*)(layer ? g_ae2c : g_ae1c);
    int beg = g_offs[w], end = g_offs[w + 1];
    float4 adv = *(const float4*)(g_ad + (size_t)w * 4);
    int h = lane >> 3;
    int f0 = lane * 8;
    float acc[8] = {0, 0, 0, 0, 0, 0, 0, 0};
    float den0 = 0, den1 = 0, den2 = 0, den3 = 0;
    float sa0 = 0, sa1 = 0, sa2 = 0, sa3 = 0;

    for (int base = beg; base < end; base += 32) {
        int i = base + lane;
        float p0 = 0, p1 = 0, p2 = 0, p3 = 0;
        int s = 0;
        if (i < end) {
            s = g_csrc[i];
            float4 ae = aeC[i];
            float4 as = *(const float4*)(g_as + (size_t)s * 4);
            sa0 += ae.x; sa1 += ae.y; sa2 += ae.z; sa3 += ae.w;
            p0 = __expf(lrelu(as.x + adv.x + ae.x));
            p1 = __expf(lrelu(as.y + adv.y + ae.y));
            p2 = __expf(lrelu(as.z + adv.z + ae.z));
            p3 = __expf(lrelu(as.w + adv.w + ae.w));
            den0 += p0; den1 += p1; den2 += p2; den3 += p3;
        }
        sp[wrp][lane] = make_float4(p0, p1, p2, p3);
        si[wrp][lane] = s;
        __syncwarp();
        int cnt = min(32, end - base);
        #pragma unroll 4
        for (int jj = 0; jj < cnt; jj++) {
            int ss = si[wrp][jj];
            float q = ((const float*)&sp[wrp][jj])[h];
            uint4 xv = *(const uint4*)(g_xsh + (size_t)ss * HC + f0);
            float2 x0 = __half22float2(*(__half2*)&xv.x);
            float2 x1 = __half22float2(*(__half2*)&xv.y);
            float2 x2 = __half22float2(*(__half2*)&xv.z);
            float2 x3 = __half22float2(*(__half2*)&xv.w);
            acc[0] = fmaf(q, x0.x, acc[0]); acc[1] = fmaf(q, x0.y, acc[1]);
            acc[2] = fmaf(q, x1.x, acc[2]); acc[3] = fmaf(q, x1.y, acc[3]);
            acc[4] = fmaf(q, x2.x, acc[4]); acc[5] = fmaf(q, x2.y, acc[5]);
            acc[6] = fmaf(q, x3.x, acc[6]); acc[7] = fmaf(q, x3.y, acc[7]);
        }
        __syncwarp();
    }
    #pragma unroll
    for (int o = 16; o; o >>= 1) {
        den0 += __shfl_xor_sync(0xffffffffu, den0, o);
        den1 += __shfl_xor_sync(0xffffffffu, den1, o);
        den2 += __shfl_xor_sync(0xffffffffu, den2, o);
        den3 += __shfl_xor_sync(0xffffffffu, den3, o);
        sa0 += __shfl_xor_sync(0xffffffffu, sa0, o);
        sa1 += __shfl_xor_sync(0xffffffffu, sa1, o);
        sa2 += __shfl_xor_sync(0xffffffffu, sa2, o);
        sa3 += __shfl_xor_sync(0xffffffffu, sa3, o);
    }
    int deg = end - beg;
    float invd = 1.0f / fmaxf((float)deg, 1.0f);
    float4 asn = *(const float4*)(g_as + (size_t)w * 4);
    float ps0 = __expf(lrelu(asn.x + adv.x + sa0 * invd));
    float ps1 = __expf(lrelu(asn.y + adv.y + sa1 * invd));
    float ps2 = __expf(lrelu(asn.z + adv.z + sa2 * invd));
    float ps3 = __expf(lrelu(asn.w + adv.w + sa3 * invd));
    den0 += ps0 + 1e-16f; den1 += ps1 + 1e-16f;
    den2 += ps2 + 1e-16f; den3 += ps3 + 1e-16f;
    {
        uint4 xv = *(const uint4*)(g_xsh + (size_t)w * HC + f0);
        float2 x0 = __half22float2(*(__half2*)&xv.x);
        float2 x1 = __half22float2(*(__half2*)&xv.y);
        float2 x2 = __half22float2(*(__half2*)&xv.z);
        float2 x3 = __half22float2(*(__half2*)&xv.w);
        float psh = (h == 0) ? ps0 : (h == 1) ? ps1 : (h == 2) ? ps2 : ps3;
        acc[0] = fmaf(psh, x0.x, acc[0]); acc[1] = fmaf(psh, x0.y, acc[1]);
        acc[2] = fmaf(psh, x1.x, acc[2]); acc[3] = fmaf(psh, x1.y, acc[3]);
        acc[4] = fmaf(psh, x2.x, acc[4]); acc[5] = fmaf(psh, x2.y, acc[5]);
        acc[6] = fmaf(psh, x3.x, acc[6]); acc[7] = fmaf(psh, x3.y, acc[7]);
    }
    float denh = (h == 0) ? den0 : (h == 1) ? den1 : (h == 2) ? den2 : den3;
    float r = 1.0f / denh;
    float4 b0 = *(const float4*)(bias + f0);
    float4 b1 = *(const float4*)(bias + f0 + 4);
    float v[8];
    v[0] = fmaf(acc[0], r, b0.x); v[1] = fmaf(acc[1], r, b0.y);
    v[2] = fmaf(acc[2], r, b0.z); v[3] = fmaf(acc[3], r, b0.w);
    v[4] = fmaf(acc[4], r, b1.x); v[5] = fmaf(acc[5], r, b1.y);
    v[6] = fmaf(acc[6], r, b1.z); v[7] = fmaf(acc[7], r, b1.w);
    {
        __half2 o0 = __floats2half2_rn(v[0], v[1]);
        __half2 o1 = __floats2half2_rn(v[2], v[3]);
        __half2 o2 = __floats2half2_rn(v[4], v[5]);
        __half2 o3 = __floats2half2_rn(v[6], v[7]);
        uint4 pack;
        pack.x = *(unsigned*)&o0; pack.y = *(unsigned*)&o1;
        pack.z = *(unsigned*)&o2; pack.w = *(unsigned*)&o3;
        *(uint4*)(g_hpreh + (size_t)w * HC + f0) = pack;
    }
    // fused BN stats: tree reduce across the block's 8 node-rows, then one
    // global fp32 atomic per feature per block (no smem atomics).
    *(float4*)(&s_part[wrp][f0])     = make_float4(v[0], v[1], v[2], v[3]);
    *(float4*)(&s_part[wrp][f0 + 4]) = make_float4(v[4], v[5], v[6], v[7]);
    __syncthreads();
    {
        float s = 0.f;
        #pragma unroll
        for (int rr = 0; rr < 8; rr++) s += s_part[rr][tid];
        atomicAdd(&g_stats[statsOff + tid], s);
    }
    __syncthreads();
    *(float4*)(&s_part[wrp][f0]) =
        make_float4(v[0] * v[0], v[1] * v[1], v[2] * v[2], v[3] * v[3]);
    *(float4*)(&s_part[wrp][f0 + 4]) =
        make_float4(v[4] * v[4], v[5] * v[5], v[6] * v[6], v[7] * v[7]);
    __syncthreads();
    {
        float s2 = 0.f;
        #pragma unroll
        for (int rr = 0; rr < 8; rr++) s2 += s_part[rr][tid];
        atomicAdd(&g_stats[statsOff + 256 + tid], s2);
    }
}

// ---------------- final: out[n] = relu(BN(hpre2)) . wout + bout ----------------
__global__ void k_final(const float* __restrict__ g, const float* __restrict__ be,
                        const float* __restrict__ wout, const float* __restrict__ bout,
                        float* __restrict__ out) {
    int w = (blockIdx.x * blockDim.x + threadIdx.x) >> 5;
    if (w >= NN) return;
    int lane = threadIdx.x & 31;
    const float invN = 1.0f / NN;
    float s = 0.f;
    #pragma unroll
    for (int j = 0; j < 8; j++) {
        int f = lane + 32 * j;
        float mu = g_stats[512 + f] * invN;
        float var = g_stats[768 + f] * invN - mu * mu;
        float sc = g[f] * rsqrtf(var + 1e-5f);
        float hv = __half2float(g_hpreh[(size_t)w * HC + f]);
        float v = fmaxf(sc * (hv - mu) + be[f], 0.f);
        s = fmaf(v, wout[f], s);
    }
    #pragma unroll
    for (int o = 16; o; o >>= 1) s += __shfl_xor_sync(0xffffffffu, s, o);
    if (lane == 0) out[w] = s + bout[0];
}

// ---------------- stream fork/join resources (created once, OUTSIDE capture) -----
struct ForkRes {
    cudaStream_t side;
    cudaEvent_t evFork, evJoin, evJoin2;
    ForkRes() {
        cudaStreamCreateWithFlags(&side, cudaStreamNonBlocking);
        cudaEventCreateWithFlags(&evFork, cudaEventDisableTiming);
        cudaEventCreateWithFlags(&evJoin, cudaEventDisableTiming);
        cudaEventCreateWithFlags(&evJoin2, cudaEventDisableTiming);
    }
};

// ---------------- launch ----------------
extern "C" void kernel_launch(void* const* d_in, const int* in_sizes, int n_in,
                              void* d_out, int out_size) {
    const float* x     = (const float*)d_in[0];
    const int*   esrc  = (const int*)d_in[1];
    const int*   edst  = (const int*)d_in[2];
    const float* eattr = (const float*)d_in[3];
    const float* W1    = (const float*)d_in[4];
    const float* atts1 = (const float*)d_in[5];
    const float* attd1 = (const float*)d_in[6];
    const float* We1   = (const float*)d_in[7];
    const float* atte1 = (const float*)d_in[8];
    const float* b1    = (const float*)d_in[9];
    const float* g1    = (const float*)d_in[10];
    const float* be1   = (const float*)d_in[11];
    const float* W2    = (const float*)d_in[12];
    const float* atts2 = (const float*)d_in[13];
    const float* attd2 = (const float*)d_in[14];
    const float* We2   = (const float*)d_in[15];
    const float* atte2 = (const float*)d_in[16];
    const float* b2    = (const float*)d_in[17];
    const float* g2    = (const float*)d_in[18];
    const float* be2   = (const float*)d_in[19];
    const float* Wout  = (const float*)d_in[20];
    const float* bout  = (const float*)d_in[21];
    float* out = (float*)d_out;

    static ForkRes fr;      // created on first (correctness) call, pre-capture

    const int EB = (EE + 255) / 256;
    const int NB = (NN + 255) / 256;
    const int WB = NN / 8;                 // warp-per-node kernels (256 thr)
    dim3 gg(2, (NN + 127) / 128);

    // main stream: setup (prepW + ve + zero), then fork
    k_setup<<<513, 256>>>(We1, atte1, We2, atte2, W1, W2);      // 1
    cudaEventRecord(fr.evFork, 0);
    cudaStreamWaitEvent(fr.side, fr.evFork, 0);

    // side stream: CSR build chain; main: GEMM1 concurrently
    k_deg<<<EB, 256, 0, fr.side>>>(edst);                       // 2
    k_scan1<<<NB, 256, 0, fr.side>>>();                         // 3
    k_gemm<<<gg, 256>>>(x, NN, 64, 0, 0, atts1, attd1,
                        nullptr, nullptr);                      // 4  <- profiled
    k_scan2<<<1, 256, 0, fr.side>>>(NB);                        // 5
    k_scan3<<<NB, 256, 0, fr.side>>>();                         // 6
    k_edge1<<<EB, 256, 0, fr.side>>>(eattr, esrc, edst);        // 7
    cudaEventRecord(fr.evJoin, fr.side);
    // edge2 stays on side stream: overlaps agg1/gemm2 on main
    k_edge2<<<EB, 256, 0, fr.side>>>(eattr);                    // 8
    cudaEventRecord(fr.evJoin2, fr.side);
    cudaStreamWaitEvent(0, fr.evJoin, 0);

    // layer 1 (needs gemm1 + CSR layer-1 data); BN stats fused into agg
    k_agg<<<WB, 256>>>(0, b1, 0);                               // 9

    // layer 2 (BN-prep + BN-ReLU of layer1 fused into GEMM, fp16 A)
    k_gemm<<<gg, 256>>>(nullptr, NN, 256, 1, 1, atts2, attd2,
                        g1, be1);                               // 10
    cudaStreamWaitEvent(0, fr.evJoin2, 0);                      // ae2c ready
    k_agg<<<WB, 256>>>(1, b2, 512);                             // 11

    // output head
    k_final<<<WB, 256>>>(g2, be2, Wout, bout, out);             // 12
}

// round 15
// speedup vs baseline: 1.6230x; 1.0342x over previous
#include <cuda_runtime.h>
#include <cuda_bf16.h>
#include <cuda_fp16.h>

#define NN 50000
#define EE 800000
#define HC 256

// ---------------- scratch (device globals; no allocation allowed) ----------------
__device__ __align__(16) __half g_xsh[NN * HC];   // xs of current layer, fp16
__device__ __align__(16) __half g_hpreh[NN * HC]; // aggregated pre-BN output, fp16
__device__ float g_as[NN * 4];
__device__ float g_ad[NN * 4];
__device__ float g_ae1c[EE * 4];    // a_e layer1, CSR order
__device__ float g_ae2c[EE * 4];    // a_e layer2, CSR order
__device__ int   g_epos[EE];        // edge -> CSR position (edge1 -> edge2)
__device__ int   g_deg[NN];
__device__ int   g_offs[NN + 1];
__device__ int   g_cursor[NN];
__device__ int   g_bsum[256];
__device__ int   g_bbase[257];
__device__ int   g_csrc[EE];
__device__ float g_ve1[64];         // [16,4]
__device__ float g_ve2[64];
__device__ float g_stats[1024];     // layer1: [0,512), layer2: [512,1024)
// W pre-transposed [n][k], single fp16 plane, per layer
__device__ __align__(16) unsigned short g_Wt[2][256 * 256];

__device__ __forceinline__ float lrelu(float x) { return fmaxf(x, 0.2f * x); }

// exact 2-term fp16 split of two fp32 values, packed as fp16x2 words
__device__ __forceinline__ void split_pk16(float x0, float x1, unsigned& h, unsigned& l) {
    __half h0 = __float2half_rn(x0), h1 = __float2half_rn(x1);
    float r0 = x0 - __half2float(h0), r1 = x1 - __half2float(h1);
    __half l0 = __float2half_rn(r0), l1 = __float2half_rn(r1);
    h = (unsigned)__half_as_ushort(h0) | ((unsigned)__half_as_ushort(h1) << 16);
    l = (unsigned)__half_as_ushort(l0) | ((unsigned)__half_as_ushort(l1) << 16);
}

#define MMA_FP16(C, A0, A1, A2, A3, B0, B1)                                      \
    asm volatile("mma.sync.aligned.m16n8k16.row.col.f32.f16.f16.f32 "            \
                 "{%0,%1,%2,%3}, {%4,%5,%6,%7}, {%8,%9}, {%0,%1,%2,%3};\n"       \
                 : "+f"((C)[0]), "+f"((C)[1]), "+f"((C)[2]), "+f"((C)[3])        \
                 : "r"(A0), "r"(A1), "r"(A2), "r"(A3), "r"(B0), "r"(B1))

// ---------------- zero: deg + stats (tiny, forks the side stream early) ----------
__global__ void k_zero() {
    int b = blockIdx.x, t = threadIdx.x;
    int zi = b * 256 + t;
    if (zi < NN) g_deg[zi] = 0;
    if (b == 196) {
        #pragma unroll
        for (int j = 0; j < 4; j++) g_stats[t + 256 * j] = 0.f;
    }
}

// ---------------- setup: prepW both layers (fp16) + ve ----------------
__global__ void k_setup(const float* __restrict__ We1, const float* __restrict__ at1,
                        const float* __restrict__ We2, const float* __restrict__ at2,
                        const float* __restrict__ W1, const float* __restrict__ W2) {
    int b = blockIdx.x;
    int t = threadIdx.x;
    if (b == 512) {
        if (t < 128) {
            int which = t >> 6;
            int u = t & 63;
            int j = u >> 2, h = u & 3;
            const float* We = which ? We2 : We1;
            const float* at = which ? at2 : at1;
            float s = 0.f;
            #pragma unroll 8
            for (int c = 0; c < 64; c++) s += We[j * HC + h * 64 + c] * at[h * 64 + c];
            if (which) g_ve2[u] = s; else g_ve1[u] = s;
        }
        return;
    }
    int layer = (b >= 256) ? 1 : 0;
    int n = layer ? (b - 256) : b;
    int K = layer ? 256 : 64;
    const float* W = layer ? W2 : W1;
    if (t >= K) return;
    float x = W[(size_t)t * 256 + n];
    g_Wt[layer][n * K + t] = __half_as_ushort(__float2half_rn(x));
}

// degree histogram only (dst reads, 3.2 MB)
__global__ void k_deg(const int* __restrict__ dst) {
    int e = blockIdx.x * blockDim.x + threadIdx.x;
    if (e < EE) atomicAdd(&g_deg[dst[e]], 1);
}

// ------------- 3-kernel exclusive scan of deg -> offs, cursor -------------
__global__ void k_scan1() {
    __shared__ int sh[256];
    int b = blockIdx.x, t = threadIdx.x;
    int i = b * 256 + t;
    sh[t] = (i < NN) ? g_deg[i] : 0;
    __syncthreads();
    for (int o = 128; o; o >>= 1) { if (t < o) sh[t] += sh[t + o]; __syncthreads(); }
    if (t == 0) g_bsum[b] = sh[0];
}

__global__ void k_scan2(int nb) {
    __shared__ int sh[256];
    int t = threadIdx.x;
    sh[t] = (t < nb) ? g_bsum[t] : 0;
    __syncthreads();
    for (int o = 1; o < 256; o <<= 1) {
        int v = (t >= o) ? sh[t - o] : 0;
        __syncthreads();
        sh[t] += v;
        __syncthreads();
    }
    g_bbase[t + 1] = sh[t];
    if (t == 0) { g_bbase[0] = 0; g_offs[NN] = EE; }
}

__global__ void k_scan3() {
    __shared__ int sh[256];
    int b = blockIdx.x, t = threadIdx.x;
    int i = b * 256 + t;
    int d = (i < NN) ? g_deg[i] : 0;
    sh[t] = d;
    __syncthreads();
    for (int o = 1; o < 256; o <<= 1) {
        int v = (t >= o) ? sh[t - o] : 0;
        __syncthreads();
        sh[t] += v;
        __syncthreads();
    }
    if (i < NN) {
        int off = g_bbase[b] + sh[t] - d;
        g_offs[i] = off;
        g_cursor[i] = off;
    }
}

// edge1 (join-critical): layer-1 a_e + CSR src + saved position
__global__ void k_edge1(const float* __restrict__ eattr, const int* __restrict__ src,
                        const int* __restrict__ dst) {
    int e = blockIdx.x * blockDim.x + threadIdx.x;
    if (e >= EE) return;
    const float4* p = (const float4*)(eattr + (size_t)e * 16);
    float4 a = p[0], b = p[1], c = p[2], d = p[3];
    float v[16] = {a.x,a.y,a.z,a.w, b.x,b.y,b.z,b.w, c.x,c.y,c.z,c.w, d.x,d.y,d.z,d.w};
    float o1[4] = {0, 0, 0, 0};
    #pragma unroll
    for (int j = 0; j < 16; j++)
        #pragma unroll
        for (int h = 0; h < 4; h++) o1[h] += v[j] * g_ve1[j * 4 + h];
    int pos = atomicAdd(&g_cursor[dst[e]], 1);
    g_csrc[pos] = src[e];
    g_epos[e] = pos;
    *(float4*)(g_ae1c + (size_t)pos * 4) = make_float4(o1[0], o1[1], o1[2], o1[3]);
}

// edge2 (deferred, overlaps agg1/gemm2): layer-2 a_e into CSR order
__global__ void k_edge2(const float* __restrict__ eattr) {
    int e = blockIdx.x * blockDim.x + threadIdx.x;
    if (e >= EE) return;
    const float4* p = (const float4*)(eattr + (size_t)e * 16);
    float4 a = p[0], b = p[1], c = p[2], d = p[3];
    float v[16] = {a.x,a.y,a.z,a.w, b.x,b.y,b.z,b.w, c.x,c.y,c.z,c.w, d.x,d.y,d.z,d.w};
    float o2[4] = {0, 0, 0, 0};
    #pragma unroll
    for (int j = 0; j < 16; j++)
        #pragma unroll
        for (int h = 0; h < 4; h++) o2[h] += v[j] * g_ve2[j * 4 + h];
    int pos = g_epos[e];
    *(float4*)(g_ae2c + (size_t)pos * 4) = make_float4(o2[0], o2[1], o2[2], o2[3]);
}

// ---------------- tensor-core GEMM: C[M,256] = A[M,K] @ W, fp16 2-term ----------
__global__ void __launch_bounds__(256, 2)
k_gemm(const float* __restrict__ Aext, int M, int K, int layer, int bnflag,
       const float* __restrict__ atts, const float* __restrict__ attd,
       const float* __restrict__ bng, const float* __restrict__ bnbe) {
    __shared__ unsigned sAh[2][1024], sAl[2][1024];   // 128 rows x 8 words
    __shared__ unsigned sB[2][1024];                  // 24 KB total
    __shared__ float s_bnsc[256], s_bnsh[256];
    int tid = threadIdx.x;
    int lane = tid & 31, wid = tid >> 5;
    int wm = (wid >> 2) * 64, wn = (wid & 3) * 32;
    int rowBlk = blockIdx.y * 128, colBlk = blockIdx.x * 128;

    if (bnflag) {
        const float invN = 1.0f / NN;
        float mu = g_stats[tid] * invN;
        float var = g_stats[256 + tid] * invN - mu * mu;
        float scv = bng[tid] * rsqrtf(var + 1e-5f);
        s_bnsc[tid] = scv;
        s_bnsh[tid] = bnbe[tid] - scv * mu;
        __syncthreads();
    }

    int ar = tid >> 1;
    int sel = tid & 1;
    bool aval = (rowBlk + ar) < M;
    const float* Ap = Aext ? (Aext + (size_t)(rowBlk + ar) * K + sel * 4) : nullptr;
    const __half* Aph = g_hpreh + (size_t)(rowBlk + ar) * K + sel * 4;
    int bn_ = tid & 127;
    int bsel = tid >> 7;
    const unsigned short* Bp = g_Wt[layer] + (size_t)(colBlk + bn_) * K;

    float c[4][4][4];
    #pragma unroll
    for (int mt = 0; mt < 4; mt++)
        #pragma unroll
        for (int nt = 0; nt < 4; nt++)
            #pragma unroll
            for (int q = 0; q < 4; q++) c[mt][nt][q] = 0.f;

    int nch = K >> 4;
    float4 fu, fv;
    uint4 bq0, bq1;

    auto loadChunk = [&](int ch) {
        if (Aext) {
            const float* Ap2 = Ap + ch * 16;
            fu = aval ? *(const float4*)(Ap2) : make_float4(0, 0, 0, 0);
            fv = aval ? *(const float4*)(Ap2 + 8) : make_float4(0, 0, 0, 0);
        } else {
            const __half* Ah2 = Aph + ch * 16;
            uint2 u0 = aval ? *(const uint2*)(Ah2) : make_uint2(0, 0);
            uint2 u1 = aval ? *(const uint2*)(Ah2 + 8) : make_uint2(0, 0);
            float2 p0 = __half22float2(*(__half2*)&u0.x);
            float2 p1 = __half22float2(*(__half2*)&u0.y);
            float2 p2 = __half22float2(*(__half2*)&u1.x);
            float2 p3 = __half22float2(*(__half2*)&u1.y);
            fu = make_float4(p0.x, p0.y, p1.x, p1.y);
            fv = make_float4(p2.x, p2.y, p3.x, p3.y);
        }
        if (bnflag && aval) {
            int kk = ch * 16 + sel * 4;
            float4 sc0 = *(const float4*)(s_bnsc + kk);
            float4 sh0 = *(const float4*)(s_bnsh + kk);
            float4 sc1 = *(const float4*)(s_bnsc + kk + 8);
            float4 sh1 = *(const float4*)(s_bnsh + kk + 8);
            fu.x = fmaxf(fmaf(sc0.x, fu.x, sh0.x), 0.f);
            fu.y = fmaxf(fmaf(sc0.y, fu.y, sh0.y), 0.f);
            fu.z = fmaxf(fmaf(sc0.z, fu.z, sh0.z), 0.f);
            fu.w = fmaxf(fmaf(sc0.w, fu.w, sh0.w), 0.f);
            fv.x = fmaxf(fmaf(sc1.x, fv.x, sh1.x), 0.f);
            fv.y = fmaxf(fmaf(sc1.y, fv.y, sh1.y), 0.f);
            fv.z = fmaxf(fmaf(sc1.z, fv.z, sh1.z), 0.f);
            fv.w = fmaxf(fmaf(sc1.w, fv.w, sh1.w), 0.f);
        }
        if (!bsel) {
            const uint4* Bc = (const uint4*)(Bp + ch * 16);
            bq0 = Bc[0];
            bq1 = Bc[1];
        }
    };
    auto stage = [&](int nb) {
        unsigned w0, w1, w2, w3, l0, l1, l2, l3;
        split_pk16(fu.x, fu.y, w0, l0);
        split_pk16(fv.x, fv.y, w1, l1);
        split_pk16(fu.z, fu.w, w2, l2);
        split_pk16(fv.z, fv.w, w3, l3);
        int s = ar & 3;
        int addr = ar * 8 + ((((2 * sel) ^ s) & ~1) << 1);
        if (s & 1) {
            *(uint4*)(&sAh[nb][addr]) = make_uint4(w2, w3, w0, w1);
            *(uint4*)(&sAl[nb][addr]) = make_uint4(l2, l3, l0, l1);
        } else {
            *(uint4*)(&sAh[nb][addr]) = make_uint4(w0, w1, w2, w3);
            *(uint4*)(&sAl[nb][addr]) = make_uint4(l0, l1, l2, l3);
        }
        if (!bsel) {
            int t = bn_ & 3;
            uint4 W0 = make_uint4(bq0.x, bq1.x, bq0.y, bq1.y);
            uint4 W1 = make_uint4(bq0.z, bq1.z, bq0.w, bq1.w);
            if (t & 1) {
                W0 = make_uint4(W0.z, W0.w, W0.x, W0.y);
                W1 = make_uint4(W1.z, W1.w, W1.x, W1.y);
            }
            int a0 = bn_ * 8 + (((0 ^ t) & ~1) << 1);
            int a1 = bn_ * 8 + (((2 ^ t) & ~1) << 1);
            *(uint4*)(&sB[nb][a0]) = W0;
            *(uint4*)(&sB[nb][a1]) = W1;
        }
    };

    loadChunk(0);
    stage(0);
    __syncthreads();

    for (int ch = 0; ch < nch; ch++) {
        int cur = ch & 1;
        if (ch + 1 < nch) loadChunk(ch + 1);
        uint2 bh[4];
        #pragma unroll
        for (int nt = 0; nt < 4; nt++) {
            int n = wn + nt * 8 + (lane >> 2);
            int off = n * 8 + ((((lane & 3) ^ (n & 3)) & 3) * 2);
            bh[nt] = *(const uint2*)(&sB[cur][off]);
        }
        #pragma unroll
        for (int mt = 0; mt < 4; mt++) {
            int r = wm + mt * 16 + (lane >> 2);
            int uoff = (((lane & 3) ^ (r & 3)) & 3) * 2;
            uint2 h0 = *(const uint2*)(&sAh[cur][r * 8 + uoff]);
            uint2 h1 = *(const uint2*)(&sAh[cur][(r + 8) * 8 + uoff]);
            uint2 q0 = *(const uint2*)(&sAl[cur][r * 8 + uoff]);
            uint2 q1 = *(const uint2*)(&sAl[cur][(r + 8) * 8 + uoff]);
            #pragma unroll
            for (int nt = 0; nt < 4; nt++) {
                MMA_FP16(c[mt][nt], h0.x, h1.x, h0.y, h1.y, bh[nt].x, bh[nt].y);
                MMA_FP16(c[mt][nt], q0.x, q1.x, q0.y, q1.y, bh[nt].x, bh[nt].y);
            }
        }
        if (ch + 1 < nch) stage(cur ^ 1);
        __syncthreads();
    }

    // epilogue: write C as fp16 (only consumer is the agg gather)
    #pragma unroll
    for (int mt = 0; mt < 4; mt++) {
        int r0 = rowBlk + wm + mt * 16 + (lane >> 2);
        #pragma unroll
        for (int nt = 0; nt < 4; nt++) {
            int col = colBlk + wn + nt * 8 + (lane & 3) * 2;
            if (r0 < M)
                *(__half2*)(g_xsh + (size_t)r0 * 256 + col) =
                    __floats2half2_rn(c[mt][nt][0], c[mt][nt][1]);
            if (r0 + 8 < M)
                *(__half2*)(g_xsh + (size_t)(r0 + 8) * 256 + col) =
                    __floats2half2_rn(c[mt][nt][2], c[mt][nt][3]);
        }
    }
    // fused attdot
    float2* sred = reinterpret_cast<float2*>(&sAh[0][0]);   // [4][128] = 4KB
    float sv[4][2], dv[4][2];
    #pragma unroll
    for (int nt = 0; nt < 4; nt++)
        #pragma unroll
        for (int q = 0; q < 2; q++) {
            int col = colBlk + wn + nt * 8 + (lane & 3) * 2 + q;
            sv[nt][q] = atts[col];
            dv[nt][q] = attd[col];
        }
    #pragma unroll
    for (int mt = 0; mt < 4; mt++) {
        #pragma unroll
        for (int half = 0; half < 2; half++) {
            float ss = 0.f, dd = 0.f;
            #pragma unroll
            for (int nt = 0; nt < 4; nt++) {
                #pragma unroll
                for (int q = 0; q < 2; q++) {
                    ss = fmaf(c[mt][nt][half * 2 + q], sv[nt][q], ss);
                    dd = fmaf(c[mt][nt][half * 2 + q], dv[nt][q], dd);
                }
            }
            ss += __shfl_xor_sync(0xffffffffu, ss, 1);
            ss += __shfl_xor_sync(0xffffffffu, ss, 2);
            dd += __shfl_xor_sync(0xffffffffu, dd, 1);
            dd += __shfl_xor_sync(0xffffffffu, dd, 2);
            if ((lane & 3) == 0)
                sred[(wid & 3) * 128 + wm + mt * 16 + half * 8 + (lane >> 2)] =
                    make_float2(ss, dd);
        }
    }
    __syncthreads();
    {
        int row = tid >> 1, hl = tid & 1;
        int r = rowBlk + row;
        if (r < M) {
            float2 aa = sred[2 * hl * 128 + row], bb = sred[(2 * hl + 1) * 128 + row];
            int hidx = (colBlk >> 6) + hl;
            g_as[r * 4 + hidx] = aa.x + bb.x;
            g_ad[r * 4 + hidx] = aa.y + bb.y;
        }
    }
}

// ---------------- GAT aggregation + fused BN stats (tree reduce).
// Warp per dst node; fp16 gather (2-way unrolled for MLP); fp32 accum. -----------
__global__ void __launch_bounds__(256) k_agg(int layer, const float* __restrict__ bias,
                                             int statsOff) {
    __shared__ float4 sp[8][32];
    __shared__ int    si[8][32];
    __shared__ float  s_part[8][256];   // 8 KB, reused for sum then sumsq
    int tid = threadIdx.x;
    int w = (blockIdx.x * blockDim.x + tid) >> 5;
    int lane = tid & 31;
    int wrp = tid >> 5;
    const float4* aeC = (const float4*)(layer ? g_ae2c : g_ae1c);
    int beg = g_offs[w], end = g_offs[w + 1];
    float4 adv = *(const float4*)(g_ad + (size_t)w * 4);
    int h = lane >> 3;
    int f0 = lane * 8;
    float acc[8] = {0, 0, 0, 0, 0, 0, 0, 0};
    float den0 = 0, den1 = 0, den2 = 0, den3 = 0;
    float sa0 = 0, sa1 = 0, sa2 = 0, sa3 = 0;

    for (int base = beg; base < end; base += 32) {
        int i = base + lane;
        float p0 = 0, p1 = 0, p2 = 0, p3 = 0;
        int s = 0;
        if (i < end) {
            s = g_csrc[i];
            float4 ae = aeC[i];
            float4 as = *(const float4*)(g_as + (size_t)s * 4);
            sa0 += ae.x; sa1 += ae.y; sa2 += ae.z; sa3 += ae.w;
            p0 = __expf(lrelu(as.x + adv.x + ae.x));
            p1 = __expf(lrelu(as.y + adv.y + ae.y));
            p2 = __expf(lrelu(as.z + adv.z + ae.z));
            p3 = __expf(lrelu(as.w + adv.w + ae.w));
            den0 += p0; den1 += p1; den2 += p2; den3 += p3;
        }
        sp[wrp][lane] = make_float4(p0, p1, p2, p3);
        si[wrp][lane] = s;
        __syncwarp();
        int cnt = min(32, end - base);
        int jj = 0;
        for (; jj + 2 <= cnt; jj += 2) {   // 2-way unroll: both gathers in flight
            int ss0 = si[wrp][jj], ss1 = si[wrp][jj + 1];
            float q0 = ((const float*)&sp[wrp][jj])[h];
            float q1 = ((const float*)&sp[wrp][jj + 1])[h];
            uint4 xa_ = *(const uint4*)(g_xsh + (size_t)ss0 * HC + f0);
            uint4 xb_ = *(const uint4*)(g_xsh + (size_t)ss1 * HC + f0);
            float2 a0 = __half22float2(*(__half2*)&xa_.x);
            float2 a1 = __half22float2(*(__half2*)&xa_.y);
            float2 a2 = __half22float2(*(__half2*)&xa_.z);
            float2 a3 = __half22float2(*(__half2*)&xa_.w);
            acc[0] = fmaf(q0, a0.x, acc[0]); acc[1] = fmaf(q0, a0.y, acc[1]);
            acc[2] = fmaf(q0, a1.x, acc[2]); acc[3] = fmaf(q0, a1.y, acc[3]);
            acc[4] = fmaf(q0, a2.x, acc[4]); acc[5] = fmaf(q0, a2.y, acc[5]);
            acc[6] = fmaf(q0, a3.x, acc[6]); acc[7] = fmaf(q0, a3.y, acc[7]);
            float2 b0_ = __half22float2(*(__half2*)&xb_.x);
            float2 b1_ = __half22float2(*(__half2*)&xb_.y);
            float2 b2_ = __half22float2(*(__half2*)&xb_.z);
            float2 b3_ = __half22float2(*(__half2*)&xb_.w);
            acc[0] = fmaf(q1, b0_.x, acc[0]); acc[1] = fmaf(q1, b0_.y, acc[1]);
            acc[2] = fmaf(q1, b1_.x, acc[2]); acc[3] = fmaf(q1, b1_.y, acc[3]);
            acc[4] = fmaf(q1, b2_.x, acc[4]); acc[5] = fmaf(q1, b2_.y, acc[5]);
            acc[6] = fmaf(q1, b3_.x, acc[6]); acc[7] = fmaf(q1, b3_.y, acc[7]);
        }
        if (jj < cnt) {
            int ss = si[wrp][jj];
            float q = ((const float*)&sp[wrp][jj])[h];
            uint4 xv = *(const uint4*)(g_xsh + (size_t)ss * HC + f0);
            float2 x0 = __half22float2(*(__half2*)&xv.x);
            float2 x1 = __half22float2(*(__half2*)&xv.y);
            float2 x2 = __half22float2(*(__half2*)&xv.z);
            float2 x3 = __half22float2(*(__half2*)&xv.w);
            acc[0] = fmaf(q, x0.x, acc[0]); acc[1] = fmaf(q, x0.y, acc[1]);
            acc[2] = fmaf(q, x1.x, acc[2]); acc[3] = fmaf(q, x1.y, acc[3]);
            acc[4] = fmaf(q, x2.x, acc[4]); acc[5] = fmaf(q, x2.y, acc[5]);
            acc[6] = fmaf(q, x3.x, acc[6]); acc[7] = fmaf(q, x3.y, acc[7]);
        }
        __syncwarp();
    }
    #pragma unroll
    for (int o = 16; o; o >>= 1) {
        den0 += __shfl_xor_sync(0xffffffffu, den0, o);
        den1 += __shfl_xor_sync(0xffffffffu, den1, o);
        den2 += __shfl_xor_sync(0xffffffffu, den2, o);
        den3 += __shfl_xor_sync(0xffffffffu, den3, o);
        sa0 += __shfl_xor_sync(0xffffffffu, sa0, o);
        sa1 += __shfl_xor_sync(0xffffffffu, sa1, o);
        sa2 += __shfl_xor_sync(0xffffffffu, sa2, o);
        sa3 += __shfl_xor_sync(0xffffffffu, sa3, o);
    }
    int deg = end - beg;
    float invd = 1.0f / fmaxf((float)deg, 1.0f);
    float4 asn = *(const float4*)(g_as + (size_t)w * 4);
    float ps0 = __expf(lrelu(asn.x + adv.x + sa0 * invd));
    float ps1 = __expf(lrelu(asn.y + adv.y + sa1 * invd));
    float ps2 = __expf(lrelu(asn.z + adv.z + sa2 * invd));
    float ps3 = __expf(lrelu(asn.w + adv.w + sa3 * invd));
    den0 += ps0 + 1e-16f; den1 += ps1 + 1e-16f;
    den2 += ps2 + 1e-16f; den3 += ps3 + 1e-16f;
    {
        uint4 xv = *(const uint4*)(g_xsh + (size_t)w * HC + f0);
        float2 x0 = __half22float2(*(__half2*)&xv.x);
        float2 x1 = __half22float2(*(__half2*)&xv.y);
        float2 x2 = __half22float2(*(__half2*)&xv.z);
        float2 x3 = __half22float2(*(__half2*)&xv.w);
        float psh = (h == 0) ? ps0 : (h == 1) ? ps1 : (h == 2) ? ps2 : ps3;
        acc[0] = fmaf(psh, x0.x, acc[0]); acc[1] = fmaf(psh, x0.y, acc[1]);
        acc[2] = fmaf(psh, x1.x, acc[2]); acc[3] = fmaf(psh, x1.y, acc[3]);
        acc[4] = fmaf(psh, x2.x, acc[4]); acc[5] = fmaf(psh, x2.y, acc[5]);
        acc[6] = fmaf(psh, x3.x, acc[6]); acc[7] = fmaf(psh, x3.y, acc[7]);
    }
    float denh = (h == 0) ? den0 : (h == 1) ? den1 : (h == 2) ? den2 : den3;
    float r = 1.0f / denh;
    float4 b0 = *(const float4*)(bias + f0);
    float4 b1 = *(const float4*)(bias + f0 + 4);
    float v[8];
    v[0] = fmaf(acc[0], r, b0.x); v[1] = fmaf(acc[1], r, b0.y);
    v[2] = fmaf(acc[2], r, b0.z); v[3] = fmaf(acc[3], r, b0.w);
    v[4] = fmaf(acc[4], r, b1.x); v[5] = fmaf(acc[5], r, b1.y);
    v[6] = fmaf(acc[6], r, b1.z); v[7] = fmaf(acc[7], r, b1.w);
    {
        __half2 o0 = __floats2half2_rn(v[0], v[1]);
        __half2 o1 = __floats2half2_rn(v[2], v[3]);
        __half2 o2 = __floats2half2_rn(v[4], v[5]);
        __half2 o3 = __floats2half2_rn(v[6], v[7]);
        uint4 pack;
        pack.x = *(unsigned*)&o0; pack.y = *(unsigned*)&o1;
        pack.z = *(unsigned*)&o2; pack.w = *(unsigned*)&o3;
        *(uint4*)(g_hpreh + (size_t)w * HC + f0) = pack;
    }
    // fused BN stats: tree reduce across the block's 8 node-rows, then one
    // global fp32 atomic per feature per block (no smem atomics).
    *(float4*)(&s_part[wrp][f0])     = make_float4(v[0], v[1], v[2], v[3]);
    *(float4*)(&s_part[wrp][f0 + 4]) = make_float4(v[4], v[5], v[6], v[7]);
    __syncthreads();
    {
        float s = 0.f;
        #pragma unroll
        for (int rr = 0; rr < 8; rr++) s += s_part[rr][tid];
        atomicAdd(&g_stats[statsOff + tid], s);
    }
    __syncthreads();
    *(float4*)(&s_part[wrp][f0]) =
        make_float4(v[0] * v[0], v[1] * v[1], v[2] * v[2], v[3] * v[3]);
    *(float4*)(&s_part[wrp][f0 + 4]) =
        make_float4(v[4] * v[4], v[5] * v[5], v[6] * v[6], v[7] * v[7]);
    __syncthreads();
    {
        float s2 = 0.f;
        #pragma unroll
        for (int rr = 0; rr < 8; rr++) s2 += s_part[rr][tid];
        atomicAdd(&g_stats[statsOff + 256 + tid], s2);
    }
}

// ---------------- final: out[n] = relu(BN(hpre2)) . wout + bout ----------------
__global__ void k_final(const float* __restrict__ g, const float* __restrict__ be,
                        const float* __restrict__ wout, const float* __restrict__ bout,
                        float* __restrict__ out) {
    int w = (blockIdx.x * blockDim.x + threadIdx.x) >> 5;
    if (w >= NN) return;
    int lane = threadIdx.x & 31;
    const float invN = 1.0f / NN;
    float s = 0.f;
    #pragma unroll
    for (int j = 0; j < 8; j++) {
        int f = lane + 32 * j;
        float mu = g_stats[512 + f] * invN;
        float var = g_stats[768 + f] * invN - mu * mu;
        float sc = g[f] * rsqrtf(var + 1e-5f);
        float hv = __half2float(g_hpreh[(size_t)w * HC + f]);
        float v = fmaxf(sc * (hv - mu) + be[f], 0.f);
        s = fmaf(v, wout[f], s);
    }
    #pragma unroll
    for (int o = 16; o; o >>= 1) s += __shfl_xor_sync(0xffffffffu, s, o);
    if (lane == 0) out[w] = s + bout[0];
}

// ---------------- stream fork/join resources (created once, OUTSIDE capture) -----
struct ForkRes {
    cudaStream_t side;
    cudaEvent_t evFork, evSetup, evJoin, evJoin2;
    ForkRes() {
        cudaStreamCreateWithFlags(&side, cudaStreamNonBlocking);
        cudaEventCreateWithFlags(&evFork, cudaEventDisableTiming);
        cudaEventCreateWithFlags(&evSetup, cudaEventDisableTiming);
        cudaEventCreateWithFlags(&evJoin, cudaEventDisableTiming);
        cudaEventCreateWithFlags(&evJoin2, cudaEventDisableTiming);
    }
};

// ---------------- launch ----------------
extern "C" void kernel_launch(void* const* d_in, const int* in_sizes, int n_in,
                              void* d_out, int out_size) {
    const float* x     = (const float*)d_in[0];
    const int*   esrc  = (const int*)d_in[1];
    const int*   edst  = (const int*)d_in[2];
    const float* eattr = (const float*)d_in[3];
    const float* W1    = (const float*)d_in[4];
    const float* atts1 = (const float*)d_in[5];
    const float* attd1 = (const float*)d_in[6];
    const float* We1   = (const float*)d_in[7];
    const float* atte1 = (const float*)d_in[8];
    const float* b1    = (const float*)d_in[9];
    const float* g1    = (const float*)d_in[10];
    const float* be1   = (const float*)d_in[11];
    const float* W2    = (const float*)d_in[12];
    const float* atts2 = (const float*)d_in[13];
    const float* attd2 = (const float*)d_in[14];
    const float* We2   = (const float*)d_in[15];
    const float* atte2 = (const float*)d_in[16];
    const float* b2    = (const float*)d_in[17];
    const float* g2    = (const float*)d_in[18];
    const float* be2   = (const float*)d_in[19];
    const float* Wout  = (const float*)d_in[20];
    const float* bout  = (const float*)d_in[21];
    float* out = (float*)d_out;

    static ForkRes fr;      // created on first (correctness) call, pre-capture

    const int EB = (EE + 255) / 256;
    const int NB = (NN + 255) / 256;
    const int WB = NN / 8;                 // warp-per-node kernels (256 thr)
    dim3 gg(2, (NN + 127) / 128);

    // main: tiny zero, fork immediately (side chain starts ~6us earlier)
    k_zero<<<197, 256>>>();                                     // 1
    cudaEventRecord(fr.evFork, 0);
    cudaStreamWaitEvent(fr.side, fr.evFork, 0);

    // side: deg + scans (no setup dependency); main: setup then gemm1
    k_deg<<<EB, 256, 0, fr.side>>>(edst);                       // 2
    k_setup<<<513, 256>>>(We1, atte1, We2, atte2, W1, W2);      // 3
    cudaEventRecord(fr.evSetup, 0);
    k_gemm<<<gg, 256>>>(x, NN, 64, 0, 0, atts1, attd1,
                        nullptr, nullptr);                      // 4  <- profiled
    k_scan1<<<NB, 256, 0, fr.side>>>();                         // 5
    k_scan2<<<1, 256, 0, fr.side>>>(NB);                        // 6
    k_scan3<<<NB, 256, 0, fr.side>>>();                         // 7
    cudaStreamWaitEvent(fr.side, fr.evSetup, 0);                // ve1 for edge1
    k_edge1<<<EB, 256, 0, fr.side>>>(eattr, esrc, edst);        // 8
    cudaEventRecord(fr.evJoin, fr.side);
    k_edge2<<<EB, 256, 0, fr.side>>>(eattr);                    // 9
    cudaEventRecord(fr.evJoin2, fr.side);
    cudaStreamWaitEvent(0, fr.evJoin, 0);

    // layer 1 (needs gemm1 + CSR layer-1 data); BN stats fused into agg
    k_agg<<<WB, 256>>>(0, b1, 0);                               // 10

    // layer 2 (BN-prep + BN-ReLU of layer1 fused into GEMM, fp16 A)
    k_gemm<<<gg, 256>>>(nullptr, NN, 256, 1, 1, atts2, attd2,
                        g1, be1);                               // 11
    cudaStreamWaitEvent(0, fr.evJoin2, 0);                      // ae2c ready
    k_agg<<<WB, 256>>>(1, b2, 512);                             // 12

    // output head
    k_final<<<WB, 256>>>(g2, be2, Wout, bout, out);             // 13
}